// round 7
// baseline (speedup 1.0000x reference)
#include <cuda_runtime.h>
#include <cstdint>
#include <math.h>

#define B_  2
#define L_  2048
#define D_  1024
#define H_  16
#define HD_ 64
#define SCALE_ 0.125f  /* 64^-0.5 */

#define NQKV ((size_t)B_ * H_ * L_ * HD_)   // 4,194,304
#define NX   ((size_t)B_ * L_ * D_)         // 4,194,304
#define NWQ  ((size_t)D_ * 3 * D_)          // 3,145,728
#define NWO  ((size_t)D_ * D_)              // 1,048,576

// Scratch (allocation-free rule: __device__ globals) — hi/lo tf32 planes
__device__ float g_xhi[NX],  g_xlo[NX];
__device__ float g_wqh[NWQ], g_wql[NWQ];
__device__ float g_woh[NWO], g_wol[NWO];
__device__ float g_qhi[NQKV], g_qlo[NQKV];
__device__ float g_khi[NQKV], g_klo[NQKV];
__device__ float g_vhi[NQKV], g_vlo[NQKV];
__device__ float g_ahi[NX],  g_alo[NX];

// ===========================================================================
// PTX helpers
// ===========================================================================
__device__ __forceinline__ uint32_t smem_u32(const void* p) {
    uint32_t a;
    asm("{ .reg .u64 t; cvta.to.shared.u64 t, %1; cvt.u32.u64 %0, t; }"
        : "=r"(a) : "l"(p));
    return a;
}
__device__ __forceinline__ void cp_async16(uint32_t dst, const void* src) {
    asm volatile("cp.async.cg.shared.global [%0], [%1], 16;"
                 :: "r"(dst), "l"(src) : "memory");
}
__device__ __forceinline__ void cp_commit() {
    asm volatile("cp.async.commit_group;" ::: "memory");
}
template<int N>
__device__ __forceinline__ void cp_wait() {
    asm volatile("cp.async.wait_group %0;" :: "n"(N) : "memory");
}
__device__ __forceinline__ void tf32_split(float x, uint32_t& hi, uint32_t& lo) {
    asm("cvt.rna.tf32.f32 %0, %1;" : "=r"(hi) : "f"(x));
    const float r = x - __uint_as_float(hi);
    asm("cvt.rna.tf32.f32 %0, %1;" : "=r"(lo) : "f"(r));
}
#define MMA_TF32(c, a, b)                                                      \
    asm volatile(                                                              \
        "mma.sync.aligned.m16n8k8.row.col.f32.tf32.tf32.f32 "                  \
        "{%0,%1,%2,%3}, {%4,%5,%6,%7}, {%8,%9}, {%0,%1,%2,%3};"                \
        : "+f"((c)[0]), "+f"((c)[1]), "+f"((c)[2]), "+f"((c)[3])               \
        : "r"((a)[0]), "r"((a)[1]), "r"((a)[2]), "r"((a)[3]),                  \
          "r"((b)[0]), "r"((b)[1]))

// ===========================================================================
// Elementwise tf32 hi/lo split prep kernel (float4 vectorized)
// ===========================================================================
__global__ __launch_bounds__(256)
void split_kernel(const float4* __restrict__ src, float4* __restrict__ hi,
                  float4* __restrict__ lo, int n4)
{
    const int i = blockIdx.x * blockDim.x + threadIdx.x;
    if (i >= n4) return;
    const float4 v = src[i];
    uint32_t h0, l0, h1, l1, h2, l2, h3, l3;
    tf32_split(v.x, h0, l0); tf32_split(v.y, h1, l1);
    tf32_split(v.z, h2, l2); tf32_split(v.w, h3, l3);
    float4 hv = { __uint_as_float(h0), __uint_as_float(h1),
                  __uint_as_float(h2), __uint_as_float(h3) };
    float4 lv = { __uint_as_float(l0), __uint_as_float(l1),
                  __uint_as_float(l2), __uint_as_float(l3) };
    hi[i] = hv;
    lo[i] = lv;
}

// ===========================================================================
// tf32x3 GEMM on pre-split planes: C = A @ W + bias
// CTA tile 128x128, K slab 32, double-buffered 4-plane cp.async.
// 512 threads / 16 warps in 4(m) x 4(n); warp tile 32x32; acc 2x4x4.
// Inner loop: LDS + MMA only.
// ===========================================================================
#define AST 36
#define BST 136
#define G_AF (128 * AST)                       // 4608
#define G_BF (32 * BST)                        // 4352
#define G_BUFSZ (2 * G_AF + 2 * G_BF)          // 17920 floats per buffer
#define GEMM_SMEM (2 * G_BUFSZ * 4)            // 143360 B

template<int NCOLS, int QKV>
__global__ __launch_bounds__(512)
void gemm_mma(const float* __restrict__ Ahi, const float* __restrict__ Alo,
              const float* __restrict__ Whi, const float* __restrict__ Wlo,
              const float* __restrict__ bias,
              float* __restrict__ o0, float* __restrict__ o1,
              float* __restrict__ o2, float* __restrict__ o3,
              float* __restrict__ o4, float* __restrict__ o5,
              float* __restrict__ o6, float* __restrict__ o7)
{
    extern __shared__ float smf[];
    const uint32_t sb = smem_u32(smf);

    const int tid  = threadIdx.x;
    const int wid  = tid >> 5;
    const int lane = tid & 31;
    const int g = lane >> 2;
    const int t = lane & 3;
    const int wm0 = (wid >> 2) * 32;   // warp m origin (0,32,64,96)
    const int wn0 = (wid & 3) * 32;    // warp n origin (0,32,64,96)
    const int m0 = blockIdx.y * 128;
    const int n0 = blockIdx.x * 128;

    float acc[2][4][4];
#pragma unroll
    for (int mt = 0; mt < 2; mt++)
#pragma unroll
        for (int nt = 0; nt < 4; nt++)
#pragma unroll
            for (int r = 0; r < 4; r++) acc[mt][nt][r] = 0.f;

    auto load_stage = [&](int s, int b) {
        const int k0 = s * 32;
        const uint32_t aH = sb + (uint32_t)(b * G_BUFSZ) * 4;
        const uint32_t aL = aH + G_AF * 4;
        const uint32_t bH = aL + G_AF * 4;
        const uint32_t bL = bH + G_BF * 4;
        const size_t abase = (size_t)m0 * D_ + k0;
#pragma unroll
        for (int i = 0; i < 2; i++) {
            const int idx = tid + i * 512;      // 1024 float4: 128r x 8c4
            const int r = idx >> 3, c4 = idx & 7;
            const size_t go = abase + (size_t)r * D_ + c4 * 4;
            const uint32_t so = (uint32_t)(r * AST + c4 * 4) * 4;
            cp_async16(aH + so, Ahi + go);
            cp_async16(aL + so, Alo + go);
        }
        const size_t wbase = (size_t)k0 * NCOLS + n0;
#pragma unroll
        for (int i = 0; i < 2; i++) {
            const int idx = tid + i * 512;      // 1024 float4: 32k x 32n4
            const int k = idx >> 5, n4 = idx & 31;
            const size_t go = wbase + (size_t)k * NCOLS + n4 * 4;
            const uint32_t so = (uint32_t)(k * BST + n4 * 4) * 4;
            cp_async16(bH + so, Whi + go);
            cp_async16(bL + so, Wlo + go);
        }
        cp_commit();
    };

    auto compute_stage = [&](int b) {
        const float* AH = smf + b * G_BUFSZ;
        const float* AL = AH + G_AF;
        const float* BH = AL + G_AF;
        const float* BL = BH + G_BF;
#pragma unroll
        for (int k8 = 0; k8 < 4; k8++) {
            const int kb = k8 * 8;
            uint32_t ah[2][4], al[2][4], bh[4][2], bl[4][2];
#pragma unroll
            for (int mt = 0; mt < 2; mt++) {
                const int ro = (wm0 + mt * 16 + g) * AST + kb;
                ah[mt][0] = __float_as_uint(AH[ro + t]);
                ah[mt][1] = __float_as_uint(AH[ro + 8 * AST + t]);
                ah[mt][2] = __float_as_uint(AH[ro + t + 4]);
                ah[mt][3] = __float_as_uint(AH[ro + 8 * AST + t + 4]);
                al[mt][0] = __float_as_uint(AL[ro + t]);
                al[mt][1] = __float_as_uint(AL[ro + 8 * AST + t]);
                al[mt][2] = __float_as_uint(AL[ro + t + 4]);
                al[mt][3] = __float_as_uint(AL[ro + 8 * AST + t + 4]);
            }
#pragma unroll
            for (int nt = 0; nt < 4; nt++) {
                const int nn = wn0 + nt * 8 + g;
                bh[nt][0] = __float_as_uint(BH[(kb + t) * BST + nn]);
                bh[nt][1] = __float_as_uint(BH[(kb + t + 4) * BST + nn]);
                bl[nt][0] = __float_as_uint(BL[(kb + t) * BST + nn]);
                bl[nt][1] = __float_as_uint(BL[(kb + t + 4) * BST + nn]);
            }
#pragma unroll
            for (int mt = 0; mt < 2; mt++)
#pragma unroll
                for (int nt = 0; nt < 4; nt++) {
                    MMA_TF32(acc[mt][nt], al[mt], bh[nt]);
                    MMA_TF32(acc[mt][nt], ah[mt], bl[nt]);
                    MMA_TF32(acc[mt][nt], ah[mt], bh[nt]);
                }
        }
    };

    load_stage(0, 0);
    constexpr int NS = D_ / 32;
    for (int s = 0; s < NS; s++) {
        const int b = s & 1;
        if (s + 1 < NS) {
            load_stage(s + 1, b ^ 1);
            cp_wait<1>();
        } else {
            cp_wait<0>();
        }
        __syncthreads();
        compute_stage(b);
        __syncthreads();
    }

    // epilogue
#pragma unroll
    for (int mt = 0; mt < 2; mt++) {
#pragma unroll
        for (int half = 0; half < 2; half++) {
            const int m = m0 + wm0 + mt * 16 + g + half * 8;
            int bb = 0, l = 0;
            if (QKV) { bb = m >> 11; l = m & (L_ - 1); }
#pragma unroll
            for (int nt = 0; nt < 4; nt++) {
                const int n = n0 + wn0 + nt * 8 + t * 2;
                float2 v;
                v.x = acc[mt][nt][half * 2 + 0] + bias[n];
                v.y = acc[mt][nt][half * 2 + 1] + bias[n + 1];
                if (QKV) {
                    const int sidx = n0 >> 10;  // block-uniform q/k/v select
                    const int h = (n >> 6) & (H_ - 1), dd = n & (HD_ - 1);
                    const size_t off =
                        (((size_t)(bb * H_ + h)) * L_ + l) * HD_ + dd;
                    uint32_t hx, lx, hy, ly;
                    tf32_split(v.x, hx, lx);
                    tf32_split(v.y, hy, ly);
                    float2 vh = { __uint_as_float(hx), __uint_as_float(hy) };
                    float2 vl = { __uint_as_float(lx), __uint_as_float(ly) };
                    if (sidx == 0) {
                        *reinterpret_cast<float2*>(o0 + off) = vh;  // qhi
                        *reinterpret_cast<float2*>(o1 + off) = vl;  // qlo
                    } else if (sidx == 1) {
                        *reinterpret_cast<float2*>(o6 + off) = v;   // k raw
                        *reinterpret_cast<float2*>(o2 + off) = vh;  // khi
                        *reinterpret_cast<float2*>(o3 + off) = vl;  // klo
                    } else {
                        *reinterpret_cast<float2*>(o7 + off) = v;   // v raw
                        *reinterpret_cast<float2*>(o4 + off) = vh;  // vhi
                        *reinterpret_cast<float2*>(o5 + off) = vl;  // vlo
                    }
                } else {
                    *reinterpret_cast<float2*>(o0 + (size_t)m * NCOLS + n) = v;
                }
            }
        }
    }
}

// ===========================================================================
// Flash attention (causal), tf32x3 mma on pre-split planes (validated R6).
// ===========================================================================
#define AQST 68
#define AKST 68
#define AVST 72
#define A_OFF_QLO  8704                     // 128*68
#define A_BUF0     17408
#define A_BUFSZ    17920
#define ATTN_FLOATS (A_BUF0 + 2 * A_BUFSZ)  // 53248
#define ATTN_SMEM (ATTN_FLOATS * 4)         // 212992 B

__global__ __launch_bounds__(256)
void attn_mma(const float* __restrict__ qhi_g, const float* __restrict__ qlo_g,
              const float* __restrict__ khi_g, const float* __restrict__ klo_g,
              const float* __restrict__ vhi_g, const float* __restrict__ vlo_g,
              float* __restrict__ ahi_g, float* __restrict__ alo_g)
{
    extern __shared__ float sm[];
    const uint32_t sbase = smem_u32(sm);

    const int tidx = (int)gridDim.x - 1 - (int)blockIdx.x;  // heavy tiles first
    const int bh   = blockIdx.y;
    const int row0 = tidx * 128;
    const size_t base = (size_t)bh * L_ * HD_;
    const float* qph = qhi_g + base;
    const float* qpl = qlo_g + base;
    const float* kph = khi_g + base;
    const float* kpl = klo_g + base;
    const float* vph = vhi_g + base;
    const float* vpl = vlo_g + base;

    const int tid = threadIdx.x;
    const int wid = tid >> 5;
    const int lane = tid & 31;
    const int g = lane >> 2;
    const int t = lane & 3;
    const int wrow = wid * 16;

    float* Qhi = sm;
    float* Qlo = sm + A_OFF_QLO;
#pragma unroll
    for (int i = 0; i < 8; i++) {
        const int idx = tid + i * 256;
        const int r = idx >> 4, c = (idx & 15) * 4;
        const size_t go = (size_t)(row0 + r) * HD_ + c;
        *reinterpret_cast<float4*>(&Qhi[r * AQST + c]) =
            *reinterpret_cast<const float4*>(qph + go);
        *reinterpret_cast<float4*>(&Qlo[r * AQST + c]) =
            *reinterpret_cast<const float4*>(qpl + go);
    }

    float accO[8][4];
    float m_i[2] = { -1e30f, -1e30f };
    float l_i[2] = { 0.f, 0.f };
#pragma unroll
    for (int nt = 0; nt < 8; nt++)
#pragma unroll
        for (int e = 0; e < 4; e++) accO[nt][e] = 0.f;

    auto load_kv = [&](int c0, int b) {
        const uint32_t kH = sbase + (uint32_t)(A_BUF0 + b * A_BUFSZ) * 4;
        const uint32_t kL = kH + 4352 * 4;
        const uint32_t vH = kH + 8704 * 4;
        const uint32_t vL = kH + 13312 * 4;
#pragma unroll
        for (int i = 0; i < 4; i++) {
            const int idx = tid + i * 256;
            const int r = idx >> 4, c = (idx & 15) * 4;
            const size_t go = (size_t)(c0 + r) * HD_ + c;
            cp_async16(kH + (uint32_t)(r * AKST + c) * 4, kph + go);
            cp_async16(kL + (uint32_t)(r * AKST + c) * 4, kpl + go);
            cp_async16(vH + (uint32_t)(r * AVST + c) * 4, vph + go);
            cp_async16(vL + (uint32_t)(r * AVST + c) * 4, vpl + go);
        }
        cp_commit();
    };
    load_kv(0, 0);

    const int jmax = 2 * tidx + 1;
    for (int j0 = 0; j0 <= jmax; j0++) {
        const int c0 = j0 * 64;
        const int b = j0 & 1;

        cp_wait<0>();
        __syncthreads();

        if (j0 < jmax) load_kv(c0 + 64, b ^ 1);

        const float* Khi = sm + A_BUF0 + b * A_BUFSZ;
        const float* Klo = Khi + 4352;
        const float* Vhi = Khi + 8704;
        const float* Vlo = Khi + 13312;
        float* Ps = const_cast<float*>(Khi);

        float s[8][4];
#pragma unroll
        for (int nt = 0; nt < 8; nt++)
#pragma unroll
            for (int e = 0; e < 4; e++) s[nt][e] = 0.f;

#pragma unroll
        for (int k8 = 0; k8 < 8; k8++) {
            const int kb = k8 * 8;
            uint32_t ah[4], al[4];
            const int qo = (wrow + g) * AQST + kb;
            ah[0] = __float_as_uint(Qhi[qo + t]);
            ah[1] = __float_as_uint(Qhi[qo + 8 * AQST + t]);
            ah[2] = __float_as_uint(Qhi[qo + t + 4]);
            ah[3] = __float_as_uint(Qhi[qo + 8 * AQST + t + 4]);
            al[0] = __float_as_uint(Qlo[qo + t]);
            al[1] = __float_as_uint(Qlo[qo + 8 * AQST + t]);
            al[2] = __float_as_uint(Qlo[qo + t + 4]);
            al[3] = __float_as_uint(Qlo[qo + 8 * AQST + t + 4]);
#pragma unroll
            for (int nt = 0; nt < 8; nt++) {
                const int nn = nt * 8 + g;
                uint32_t bh2[2], bl2[2];
                bh2[0] = __float_as_uint(Khi[nn * AKST + kb + t]);
                bh2[1] = __float_as_uint(Khi[nn * AKST + kb + t + 4]);
                bl2[0] = __float_as_uint(Klo[nn * AKST + kb + t]);
                bl2[1] = __float_as_uint(Klo[nn * AKST + kb + t + 4]);
                MMA_TF32(s[nt], al, bh2);
                MMA_TF32(s[nt], ah, bl2);
                MMA_TF32(s[nt], ah, bh2);
            }
        }

        const bool dm = (c0 + 63 > row0);
        const int r0 = row0 + wrow + g;
        const int r1 = r0 + 8;
#pragma unroll
        for (int nt = 0; nt < 8; nt++) {
#pragma unroll
            for (int e = 0; e < 4; e++) {
                const int col = c0 + nt * 8 + 2 * t + (e & 1);
                const int row = (e < 2) ? r0 : r1;
                s[nt][e] *= SCALE_;
                if (dm && col > row) s[nt][e] = -1e30f;
            }
        }

        float mx0 = -1e30f, mx1 = -1e30f;
#pragma unroll
        for (int nt = 0; nt < 8; nt++) {
            mx0 = fmaxf(mx0, fmaxf(s[nt][0], s[nt][1]));
            mx1 = fmaxf(mx1, fmaxf(s[nt][2], s[nt][3]));
        }
#pragma unroll
        for (int off = 1; off <= 2; off <<= 1) {
            mx0 = fmaxf(mx0, __shfl_xor_sync(0xffffffffu, mx0, off));
            mx1 = fmaxf(mx1, __shfl_xor_sync(0xffffffffu, mx1, off));
        }
        const float mn0 = fmaxf(m_i[0], mx0);
        const float mn1 = fmaxf(m_i[1], mx1);
        const float corr0 = __expf(m_i[0] - mn0);
        const float corr1 = __expf(m_i[1] - mn1);
        m_i[0] = mn0; m_i[1] = mn1;

        float ls0 = 0.f, ls1 = 0.f;
#pragma unroll
        for (int nt = 0; nt < 8; nt++) {
            s[nt][0] = __expf(s[nt][0] - mn0);
            s[nt][1] = __expf(s[nt][1] - mn0);
            s[nt][2] = __expf(s[nt][2] - mn1);
            s[nt][3] = __expf(s[nt][3] - mn1);
            ls0 += s[nt][0] + s[nt][1];
            ls1 += s[nt][2] + s[nt][3];
        }
#pragma unroll
        for (int off = 1; off <= 2; off <<= 1) {
            ls0 += __shfl_xor_sync(0xffffffffu, ls0, off);
            ls1 += __shfl_xor_sync(0xffffffffu, ls1, off);
        }
        l_i[0] = l_i[0] * corr0 + ls0;
        l_i[1] = l_i[1] * corr1 + ls1;
#pragma unroll
        for (int nt = 0; nt < 8; nt++) {
            accO[nt][0] *= corr0; accO[nt][1] *= corr0;
            accO[nt][2] *= corr1; accO[nt][3] *= corr1;
        }

        __syncthreads();   // all warps done reading K[b] before P overwrites it

#pragma unroll
        for (int nt = 0; nt < 8; nt++) {
            Ps[(wrow + g) * AQST + nt * 8 + 2 * t]         = s[nt][0];
            Ps[(wrow + g) * AQST + nt * 8 + 2 * t + 1]     = s[nt][1];
            Ps[(wrow + g + 8) * AQST + nt * 8 + 2 * t]     = s[nt][2];
            Ps[(wrow + g + 8) * AQST + nt * 8 + 2 * t + 1] = s[nt][3];
        }
        __syncwarp();

#pragma unroll
        for (int k8 = 0; k8 < 8; k8++) {
            const int kb = k8 * 8;
            uint32_t ph[4], pl[4];
            tf32_split(Ps[(wrow + g) * AQST + kb + t],         ph[0], pl[0]);
            tf32_split(Ps[(wrow + g + 8) * AQST + kb + t],     ph[1], pl[1]);
            tf32_split(Ps[(wrow + g) * AQST + kb + t + 4],     ph[2], pl[2]);
            tf32_split(Ps[(wrow + g + 8) * AQST + kb + t + 4], ph[3], pl[3]);
#pragma unroll
            for (int nt = 0; nt < 8; nt++) {
                const int nn = nt * 8 + g;
                uint32_t vh[2], vl[2];
                vh[0] = __float_as_uint(Vhi[(kb + t) * AVST + nn]);
                vh[1] = __float_as_uint(Vhi[(kb + t + 4) * AVST + nn]);
                vl[0] = __float_as_uint(Vlo[(kb + t) * AVST + nn]);
                vl[1] = __float_as_uint(Vlo[(kb + t + 4) * AVST + nn]);
                MMA_TF32(accO[nt], pl, vh);
                MMA_TF32(accO[nt], ph, vl);
                MMA_TF32(accO[nt], ph, vh);
            }
        }
    }

    const int bb = bh >> 4;
    const int h  = bh & (H_ - 1);
    const float inv0 = 1.0f / l_i[0];
    const float inv1 = 1.0f / l_i[1];
    const int r0 = row0 + wrow + g;
#pragma unroll
    for (int nt = 0; nt < 8; nt++) {
        const int col = h * HD_ + nt * 8 + 2 * t;
        const size_t o0 = ((size_t)(bb * L_ + r0)) * D_ + col;
        const size_t o1 = ((size_t)(bb * L_ + r0 + 8)) * D_ + col;
        uint32_t hx, lx, hy, ly;
        tf32_split(accO[nt][0] * inv0, hx, lx);
        tf32_split(accO[nt][1] * inv0, hy, ly);
        *reinterpret_cast<float2*>(ahi_g + o0) =
            { __uint_as_float(hx), __uint_as_float(hy) };
        *reinterpret_cast<float2*>(alo_g + o0) =
            { __uint_as_float(lx), __uint_as_float(ly) };
        tf32_split(accO[nt][2] * inv1, hx, lx);
        tf32_split(accO[nt][3] * inv1, hy, ly);
        *reinterpret_cast<float2*>(ahi_g + o1) =
            { __uint_as_float(hx), __uint_as_float(hy) };
        *reinterpret_cast<float2*>(alo_g + o1) =
            { __uint_as_float(lx), __uint_as_float(ly) };
    }
}

// ---------------------------------------------------------------------------
extern "C" void kernel_launch(void* const* d_in, const int* in_sizes, int n_in,
                              void* d_out, int out_size)
{
    const float* x     = (const float*)d_in[0];
    const float* w_qkv = (const float*)d_in[1];
    const float* b_qkv = (const float*)d_in[2];
    const float* w_out = (const float*)d_in[3];
    const float* b_out = (const float*)d_in[4];

    float* out  = (float*)d_out;                                   // (B,L,D)
    float* kout = out  + (size_t)B_ * L_ * D_;                     // (B,H,L,HD)
    float* vout = kout + (size_t)B_ * H_ * L_ * HD_;               // (B,H,L,HD)

    float *xhi, *xlo, *wqh, *wql, *woh, *wol;
    float *qhi, *qlo, *khi, *klo, *vhi, *vlo, *ahi, *alo;
    cudaGetSymbolAddress((void**)&xhi, g_xhi);
    cudaGetSymbolAddress((void**)&xlo, g_xlo);
    cudaGetSymbolAddress((void**)&wqh, g_wqh);
    cudaGetSymbolAddress((void**)&wql, g_wql);
    cudaGetSymbolAddress((void**)&woh, g_woh);
    cudaGetSymbolAddress((void**)&wol, g_wol);
    cudaGetSymbolAddress((void**)&qhi, g_qhi);
    cudaGetSymbolAddress((void**)&qlo, g_qlo);
    cudaGetSymbolAddress((void**)&khi, g_khi);
    cudaGetSymbolAddress((void**)&klo, g_klo);
    cudaGetSymbolAddress((void**)&vhi, g_vhi);
    cudaGetSymbolAddress((void**)&vlo, g_vlo);
    cudaGetSymbolAddress((void**)&ahi, g_ahi);
    cudaGetSymbolAddress((void**)&alo, g_alo);

    cudaFuncSetAttribute(gemm_mma<3 * D_, 1>,
                         cudaFuncAttributeMaxDynamicSharedMemorySize, GEMM_SMEM);
    cudaFuncSetAttribute(gemm_mma<D_, 0>,
                         cudaFuncAttributeMaxDynamicSharedMemorySize, GEMM_SMEM);
    cudaFuncSetAttribute(attn_mma,
                         cudaFuncAttributeMaxDynamicSharedMemorySize, ATTN_SMEM);

    // 0) Split inputs into tf32 hi/lo planes
    split_kernel<<<(int)(NX / 4 + 255) / 256, 256>>>(
        (const float4*)x, (float4*)xhi, (float4*)xlo, (int)(NX / 4));
    split_kernel<<<(int)(NWQ / 4 + 255) / 256, 256>>>(
        (const float4*)w_qkv, (float4*)wqh, (float4*)wql, (int)(NWQ / 4));
    split_kernel<<<(int)(NWO / 4 + 255) / 256, 256>>>(
        (const float4*)w_out, (float4*)woh, (float4*)wol, (int)(NWO / 4));

    // 1) QKV projection -> q/k/v hi-lo planes + raw k/v into d_out
    gemm_mma<3 * D_, 1><<<dim3((3 * D_) / 128, (B_ * L_) / 128), 512, GEMM_SMEM>>>(
        xhi, xlo, wqh, wql, b_qkv,
        qhi, qlo, khi, klo, vhi, vlo, kout, vout);

    // 2) Causal flash attention -> attn-out hi/lo planes
    attn_mma<<<dim3(L_ / 128, B_ * H_), 256, ATTN_SMEM>>>(
        qhi, qlo, khi, klo, vhi, vlo, ahi, alo);

    // 3) Output projection -> d_out
    gemm_mma<D_, 0><<<dim3(D_ / 128, (B_ * L_) / 128), 512, GEMM_SMEM>>>(
        ahi, alo, woh, wol, b_out,
        out, nullptr, nullptr, nullptr, nullptr, nullptr, nullptr, nullptr);
}

// round 8
// speedup vs baseline: 1.0313x; 1.0313x over previous
#include <cuda_runtime.h>
#include <cstdint>
#include <math.h>

#define B_  2
#define L_  2048
#define D_  1024
#define H_  16
#define HD_ 64
#define SCALE_ 0.125f  /* 64^-0.5 */

#define NQKV ((size_t)B_ * H_ * L_ * HD_)
#define NX   ((size_t)B_ * L_ * D_)
#define NWQ  ((size_t)D_ * 3 * D_)
#define NWO  ((size_t)D_ * D_)

// Scratch (allocation-free rule: __device__ globals) — hi/lo tf32 planes
__device__ float g_xhi[NX],  g_xlo[NX];
__device__ float g_wqh[NWQ], g_wql[NWQ];
__device__ float g_woh[NWO], g_wol[NWO];
__device__ float g_qhi[NQKV], g_qlo[NQKV];
__device__ float g_khi[NQKV], g_klo[NQKV];
__device__ float g_vhi[NQKV], g_vlo[NQKV];
__device__ float g_ahi[NX],  g_alo[NX];

// ===========================================================================
// PTX helpers
// ===========================================================================
__device__ __forceinline__ uint32_t smem_u32(const void* p) {
    uint32_t a;
    asm("{ .reg .u64 t; cvta.to.shared.u64 t, %1; cvt.u32.u64 %0, t; }"
        : "=r"(a) : "l"(p));
    return a;
}
__device__ __forceinline__ void cp_async16(uint32_t dst, const void* src) {
    asm volatile("cp.async.cg.shared.global [%0], [%1], 16;"
                 :: "r"(dst), "l"(src) : "memory");
}
__device__ __forceinline__ void cp_commit() {
    asm volatile("cp.async.commit_group;" ::: "memory");
}
template<int N>
__device__ __forceinline__ void cp_wait() {
    asm volatile("cp.async.wait_group %0;" :: "n"(N) : "memory");
}
__device__ __forceinline__ void tf32_split(float x, uint32_t& hi, uint32_t& lo) {
    asm("cvt.rna.tf32.f32 %0, %1;" : "=r"(hi) : "f"(x));
    const float r = x - __uint_as_float(hi);
    asm("cvt.rna.tf32.f32 %0, %1;" : "=r"(lo) : "f"(r));
}
// NON-volatile: pure register op; lets ptxas schedule around it.
#define MMA_TF32(c, a, b)                                                      \
    asm("mma.sync.aligned.m16n8k8.row.col.f32.tf32.tf32.f32 "                  \
        "{%0,%1,%2,%3}, {%4,%5,%6,%7}, {%8,%9}, {%0,%1,%2,%3};"                \
        : "+f"((c)[0]), "+f"((c)[1]), "+f"((c)[2]), "+f"((c)[3])               \
        : "r"((a)[0]), "r"((a)[1]), "r"((a)[2]), "r"((a)[3]),                  \
          "r"((b)[0]), "r"((b)[1]))

// ===========================================================================
// Elementwise tf32 hi/lo split prep kernel
// ===========================================================================
__global__ __launch_bounds__(256)
void split_kernel(const float4* __restrict__ src, float4* __restrict__ hi,
                  float4* __restrict__ lo, int n4)
{
    const int i = blockIdx.x * blockDim.x + threadIdx.x;
    if (i >= n4) return;
    const float4 v = src[i];
    uint32_t h0, l0, h1, l1, h2, l2, h3, l3;
    tf32_split(v.x, h0, l0); tf32_split(v.y, h1, l1);
    tf32_split(v.z, h2, l2); tf32_split(v.w, h3, l3);
    float4 hv = { __uint_as_float(h0), __uint_as_float(h1),
                  __uint_as_float(h2), __uint_as_float(h3) };
    float4 lv = { __uint_as_float(l0), __uint_as_float(l1),
                  __uint_as_float(l2), __uint_as_float(l3) };
    hi[i] = hv;
    lo[i] = lv;
}

// ===========================================================================
// tf32x3 GEMM on pre-split planes (R6 shape: 256 thr, 8 warps 2x4, warp 64x32)
// MMA issue: 3 interleaved passes over 16 tiles (chain-breaking).
// ===========================================================================
#define AST 36
#define BST 136
#define G_AF (128 * AST)
#define G_BF (32 * BST)
#define G_BUFSZ (2 * G_AF + 2 * G_BF)
#define GEMM_SMEM (2 * G_BUFSZ * 4)

template<int NCOLS, int QKV>
__global__ __launch_bounds__(256)
void gemm_mma(const float* __restrict__ Ahi, const float* __restrict__ Alo,
              const float* __restrict__ Whi, const float* __restrict__ Wlo,
              const float* __restrict__ bias,
              float* __restrict__ o0, float* __restrict__ o1,
              float* __restrict__ o2, float* __restrict__ o3,
              float* __restrict__ o4, float* __restrict__ o5,
              float* __restrict__ o6, float* __restrict__ o7)
{
    extern __shared__ float smf[];
    const uint32_t sb = smem_u32(smf);

    const int tid  = threadIdx.x;
    const int wid  = tid >> 5;
    const int lane = tid & 31;
    const int g = lane >> 2;
    const int t = lane & 3;
    const int wm0 = (wid >> 2) * 64;
    const int wn0 = (wid & 3) * 32;
    const int m0 = blockIdx.y * 128;
    const int n0 = blockIdx.x * 128;

    float acc[4][4][4];
#pragma unroll
    for (int mt = 0; mt < 4; mt++)
#pragma unroll
        for (int nt = 0; nt < 4; nt++)
#pragma unroll
            for (int r = 0; r < 4; r++) acc[mt][nt][r] = 0.f;

    auto load_stage = [&](int s, int b) {
        const int k0 = s * 32;
        const uint32_t aH = sb + (uint32_t)(b * G_BUFSZ) * 4;
        const uint32_t aL = aH + G_AF * 4;
        const uint32_t bH = aL + G_AF * 4;
        const uint32_t bL = bH + G_BF * 4;
        const size_t abase = (size_t)m0 * D_ + k0;
#pragma unroll
        for (int i = 0; i < 4; i++) {
            const int idx = tid + i * 256;
            const int r = idx >> 3, c4 = idx & 7;
            const size_t go = abase + (size_t)r * D_ + c4 * 4;
            const uint32_t so = (uint32_t)(r * AST + c4 * 4) * 4;
            cp_async16(aH + so, Ahi + go);
            cp_async16(aL + so, Alo + go);
        }
        const size_t wbase = (size_t)k0 * NCOLS + n0;
#pragma unroll
        for (int i = 0; i < 4; i++) {
            const int idx = tid + i * 256;
            const int k = idx >> 5, n4 = idx & 31;
            const size_t go = wbase + (size_t)k * NCOLS + n4 * 4;
            const uint32_t so = (uint32_t)(k * BST + n4 * 4) * 4;
            cp_async16(bH + so, Whi + go);
            cp_async16(bL + so, Wlo + go);
        }
        cp_commit();
    };

    auto compute_stage = [&](int b) {
        const float* AH = smf + b * G_BUFSZ;
        const float* AL = AH + G_AF;
        const float* BH = AL + G_AF;
        const float* BL = BH + G_BF;
#pragma unroll
        for (int k8 = 0; k8 < 4; k8++) {
            const int kb = k8 * 8;
            uint32_t ah[4][4], al[4][4], bh[4][2], bl[4][2];
#pragma unroll
            for (int mt = 0; mt < 4; mt++) {
                const int ro = (wm0 + mt * 16 + g) * AST + kb;
                ah[mt][0] = __float_as_uint(AH[ro + t]);
                ah[mt][1] = __float_as_uint(AH[ro + 8 * AST + t]);
                ah[mt][2] = __float_as_uint(AH[ro + t + 4]);
                ah[mt][3] = __float_as_uint(AH[ro + 8 * AST + t + 4]);
                al[mt][0] = __float_as_uint(AL[ro + t]);
                al[mt][1] = __float_as_uint(AL[ro + 8 * AST + t]);
                al[mt][2] = __float_as_uint(AL[ro + t + 4]);
                al[mt][3] = __float_as_uint(AL[ro + 8 * AST + t + 4]);
            }
#pragma unroll
            for (int nt = 0; nt < 4; nt++) {
                const int nn = wn0 + nt * 8 + g;
                bh[nt][0] = __float_as_uint(BH[(kb + t) * BST + nn]);
                bh[nt][1] = __float_as_uint(BH[(kb + t + 4) * BST + nn]);
                bl[nt][0] = __float_as_uint(BL[(kb + t) * BST + nn]);
                bl[nt][1] = __float_as_uint(BL[(kb + t + 4) * BST + nn]);
            }
            // 3 interleaved passes: 15 independent MMAs between chain links
#pragma unroll
            for (int mt = 0; mt < 4; mt++)
#pragma unroll
                for (int nt = 0; nt < 4; nt++)
                    MMA_TF32(acc[mt][nt], al[mt], bh[nt]);
#pragma unroll
            for (int mt = 0; mt < 4; mt++)
#pragma unroll
                for (int nt = 0; nt < 4; nt++)
                    MMA_TF32(acc[mt][nt], ah[mt], bl[nt]);
#pragma unroll
            for (int mt = 0; mt < 4; mt++)
#pragma unroll
                for (int nt = 0; nt < 4; nt++)
                    MMA_TF32(acc[mt][nt], ah[mt], bh[nt]);
        }
    };

    load_stage(0, 0);
    constexpr int NS = D_ / 32;
    for (int s = 0; s < NS; s++) {
        const int b = s & 1;
        if (s + 1 < NS) {
            load_stage(s + 1, b ^ 1);
            cp_wait<1>();
        } else {
            cp_wait<0>();
        }
        __syncthreads();
        compute_stage(b);
        __syncthreads();
    }

    // epilogue
#pragma unroll
    for (int mt = 0; mt < 4; mt++) {
#pragma unroll
        for (int half = 0; half < 2; half++) {
            const int m = m0 + wm0 + mt * 16 + g + half * 8;
            int bb = 0, l = 0;
            if (QKV) { bb = m >> 11; l = m & (L_ - 1); }
#pragma unroll
            for (int nt = 0; nt < 4; nt++) {
                const int n = n0 + wn0 + nt * 8 + t * 2;
                float2 v;
                v.x = acc[mt][nt][half * 2 + 0] + bias[n];
                v.y = acc[mt][nt][half * 2 + 1] + bias[n + 1];
                if (QKV) {
                    const int sidx = n0 >> 10;
                    const int h = (n >> 6) & (H_ - 1), dd = n & (HD_ - 1);
                    const size_t off =
                        (((size_t)(bb * H_ + h)) * L_ + l) * HD_ + dd;
                    uint32_t hx, lx, hy, ly;
                    tf32_split(v.x, hx, lx);
                    tf32_split(v.y, hy, ly);
                    float2 vh = { __uint_as_float(hx), __uint_as_float(hy) };
                    float2 vl = { __uint_as_float(lx), __uint_as_float(ly) };
                    if (sidx == 0) {
                        *reinterpret_cast<float2*>(o0 + off) = vh;
                        *reinterpret_cast<float2*>(o1 + off) = vl;
                    } else if (sidx == 1) {
                        *reinterpret_cast<float2*>(o6 + off) = v;
                        *reinterpret_cast<float2*>(o2 + off) = vh;
                        *reinterpret_cast<float2*>(o3 + off) = vl;
                    } else {
                        *reinterpret_cast<float2*>(o7 + off) = v;
                        *reinterpret_cast<float2*>(o4 + off) = vh;
                        *reinterpret_cast<float2*>(o5 + off) = vl;
                    }
                } else {
                    *reinterpret_cast<float2*>(o0 + (size_t)m * NCOLS + n) = v;
                }
            }
        }
    }
}

// ===========================================================================
// Flash attention (causal), tf32x3 mma, interleaved MMA passes.
// ===========================================================================
#define AQST 68
#define AKST 68
#define AVST 72
#define A_OFF_QLO  8704
#define A_BUF0     17408
#define A_BUFSZ    17920
#define ATTN_FLOATS (A_BUF0 + 2 * A_BUFSZ)
#define ATTN_SMEM (ATTN_FLOATS * 4)

__global__ __launch_bounds__(256)
void attn_mma(const float* __restrict__ qhi_g, const float* __restrict__ qlo_g,
              const float* __restrict__ khi_g, const float* __restrict__ klo_g,
              const float* __restrict__ vhi_g, const float* __restrict__ vlo_g,
              float* __restrict__ ahi_g, float* __restrict__ alo_g)
{
    extern __shared__ float sm[];
    const uint32_t sbase = smem_u32(sm);

    const int tidx = (int)gridDim.x - 1 - (int)blockIdx.x;
    const int bh   = blockIdx.y;
    const int row0 = tidx * 128;
    const size_t base = (size_t)bh * L_ * HD_;
    const float* qph = qhi_g + base;
    const float* qpl = qlo_g + base;
    const float* kph = khi_g + base;
    const float* kpl = klo_g + base;
    const float* vph = vhi_g + base;
    const float* vpl = vlo_g + base;

    const int tid = threadIdx.x;
    const int wid = tid >> 5;
    const int lane = tid & 31;
    const int g = lane >> 2;
    const int t = lane & 3;
    const int wrow = wid * 16;

    float* Qhi = sm;
    float* Qlo = sm + A_OFF_QLO;
#pragma unroll
    for (int i = 0; i < 8; i++) {
        const int idx = tid + i * 256;
        const int r = idx >> 4, c = (idx & 15) * 4;
        const size_t go = (size_t)(row0 + r) * HD_ + c;
        *reinterpret_cast<float4*>(&Qhi[r * AQST + c]) =
            *reinterpret_cast<const float4*>(qph + go);
        *reinterpret_cast<float4*>(&Qlo[r * AQST + c]) =
            *reinterpret_cast<const float4*>(qpl + go);
    }

    float accO[8][4];
    float m_i[2] = { -1e30f, -1e30f };
    float l_i[2] = { 0.f, 0.f };
#pragma unroll
    for (int nt = 0; nt < 8; nt++)
#pragma unroll
        for (int e = 0; e < 4; e++) accO[nt][e] = 0.f;

    auto load_kv = [&](int c0, int b) {
        const uint32_t kH = sbase + (uint32_t)(A_BUF0 + b * A_BUFSZ) * 4;
        const uint32_t kL = kH + 4352 * 4;
        const uint32_t vH = kH + 8704 * 4;
        const uint32_t vL = kH + 13312 * 4;
#pragma unroll
        for (int i = 0; i < 4; i++) {
            const int idx = tid + i * 256;
            const int r = idx >> 4, c = (idx & 15) * 4;
            const size_t go = (size_t)(c0 + r) * HD_ + c;
            cp_async16(kH + (uint32_t)(r * AKST + c) * 4, kph + go);
            cp_async16(kL + (uint32_t)(r * AKST + c) * 4, kpl + go);
            cp_async16(vH + (uint32_t)(r * AVST + c) * 4, vph + go);
            cp_async16(vL + (uint32_t)(r * AVST + c) * 4, vpl + go);
        }
        cp_commit();
    };
    load_kv(0, 0);

    const int jmax = 2 * tidx + 1;
    for (int j0 = 0; j0 <= jmax; j0++) {
        const int c0 = j0 * 64;
        const int b = j0 & 1;

        cp_wait<0>();
        __syncthreads();

        if (j0 < jmax) load_kv(c0 + 64, b ^ 1);

        const float* Khi = sm + A_BUF0 + b * A_BUFSZ;
        const float* Klo = Khi + 4352;
        const float* Vhi = Khi + 8704;
        const float* Vlo = Khi + 13312;
        float* Ps = const_cast<float*>(Khi);

        float s[8][4];
#pragma unroll
        for (int nt = 0; nt < 8; nt++)
#pragma unroll
            for (int e = 0; e < 4; e++) s[nt][e] = 0.f;

#pragma unroll
        for (int k8 = 0; k8 < 8; k8++) {
            const int kb = k8 * 8;
            uint32_t ah[4], al[4], bh2[8][2], bl2[8][2];
            const int qo = (wrow + g) * AQST + kb;
            ah[0] = __float_as_uint(Qhi[qo + t]);
            ah[1] = __float_as_uint(Qhi[qo + 8 * AQST + t]);
            ah[2] = __float_as_uint(Qhi[qo + t + 4]);
            ah[3] = __float_as_uint(Qhi[qo + 8 * AQST + t + 4]);
            al[0] = __float_as_uint(Qlo[qo + t]);
            al[1] = __float_as_uint(Qlo[qo + 8 * AQST + t]);
            al[2] = __float_as_uint(Qlo[qo + t + 4]);
            al[3] = __float_as_uint(Qlo[qo + 8 * AQST + t + 4]);
#pragma unroll
            for (int nt = 0; nt < 8; nt++) {
                const int nn = nt * 8 + g;
                bh2[nt][0] = __float_as_uint(Khi[nn * AKST + kb + t]);
                bh2[nt][1] = __float_as_uint(Khi[nn * AKST + kb + t + 4]);
                bl2[nt][0] = __float_as_uint(Klo[nn * AKST + kb + t]);
                bl2[nt][1] = __float_as_uint(Klo[nn * AKST + kb + t + 4]);
            }
            // 3 interleaved passes over 8 tiles
#pragma unroll
            for (int nt = 0; nt < 8; nt++) MMA_TF32(s[nt], al, bh2[nt]);
#pragma unroll
            for (int nt = 0; nt < 8; nt++) MMA_TF32(s[nt], ah, bl2[nt]);
#pragma unroll
            for (int nt = 0; nt < 8; nt++) MMA_TF32(s[nt], ah, bh2[nt]);
        }

        const bool dm = (c0 + 63 > row0);
        const int r0 = row0 + wrow + g;
        const int r1 = r0 + 8;
#pragma unroll
        for (int nt = 0; nt < 8; nt++) {
#pragma unroll
            for (int e = 0; e < 4; e++) {
                const int col = c0 + nt * 8 + 2 * t + (e & 1);
                const int row = (e < 2) ? r0 : r1;
                s[nt][e] *= SCALE_;
                if (dm && col > row) s[nt][e] = -1e30f;
            }
        }

        float mx0 = -1e30f, mx1 = -1e30f;
#pragma unroll
        for (int nt = 0; nt < 8; nt++) {
            mx0 = fmaxf(mx0, fmaxf(s[nt][0], s[nt][1]));
            mx1 = fmaxf(mx1, fmaxf(s[nt][2], s[nt][3]));
        }
#pragma unroll
        for (int off = 1; off <= 2; off <<= 1) {
            mx0 = fmaxf(mx0, __shfl_xor_sync(0xffffffffu, mx0, off));
            mx1 = fmaxf(mx1, __shfl_xor_sync(0xffffffffu, mx1, off));
        }
        const float mn0 = fmaxf(m_i[0], mx0);
        const float mn1 = fmaxf(m_i[1], mx1);
        const float corr0 = __expf(m_i[0] - mn0);
        const float corr1 = __expf(m_i[1] - mn1);
        m_i[0] = mn0; m_i[1] = mn1;

        float ls0 = 0.f, ls1 = 0.f;
#pragma unroll
        for (int nt = 0; nt < 8; nt++) {
            s[nt][0] = __expf(s[nt][0] - mn0);
            s[nt][1] = __expf(s[nt][1] - mn0);
            s[nt][2] = __expf(s[nt][2] - mn1);
            s[nt][3] = __expf(s[nt][3] - mn1);
            ls0 += s[nt][0] + s[nt][1];
            ls1 += s[nt][2] + s[nt][3];
        }
#pragma unroll
        for (int off = 1; off <= 2; off <<= 1) {
            ls0 += __shfl_xor_sync(0xffffffffu, ls0, off);
            ls1 += __shfl_xor_sync(0xffffffffu, ls1, off);
        }
        l_i[0] = l_i[0] * corr0 + ls0;
        l_i[1] = l_i[1] * corr1 + ls1;
#pragma unroll
        for (int nt = 0; nt < 8; nt++) {
            accO[nt][0] *= corr0; accO[nt][1] *= corr0;
            accO[nt][2] *= corr1; accO[nt][3] *= corr1;
        }

        __syncthreads();   // all warps done reading K[b] before P overwrites it

#pragma unroll
        for (int nt = 0; nt < 8; nt++) {
            Ps[(wrow + g) * AQST + nt * 8 + 2 * t]         = s[nt][0];
            Ps[(wrow + g) * AQST + nt * 8 + 2 * t + 1]     = s[nt][1];
            Ps[(wrow + g + 8) * AQST + nt * 8 + 2 * t]     = s[nt][2];
            Ps[(wrow + g + 8) * AQST + nt * 8 + 2 * t + 1] = s[nt][3];
        }
        __syncwarp();

#pragma unroll
        for (int k8 = 0; k8 < 8; k8++) {
            const int kb = k8 * 8;
            uint32_t ph[4], pl[4], vh[8][2], vl[8][2];
            tf32_split(Ps[(wrow + g) * AQST + kb + t],         ph[0], pl[0]);
            tf32_split(Ps[(wrow + g + 8) * AQST + kb + t],     ph[1], pl[1]);
            tf32_split(Ps[(wrow + g) * AQST + kb + t + 4],     ph[2], pl[2]);
            tf32_split(Ps[(wrow + g + 8) * AQST + kb + t + 4], ph[3], pl[3]);
#pragma unroll
            for (int nt = 0; nt < 8; nt++) {
                const int nn = nt * 8 + g;
                vh[nt][0] = __float_as_uint(Vhi[(kb + t) * AVST + nn]);
                vh[nt][1] = __float_as_uint(Vhi[(kb + t + 4) * AVST + nn]);
                vl[nt][0] = __float_as_uint(Vlo[(kb + t) * AVST + nn]);
                vl[nt][1] = __float_as_uint(Vlo[(kb + t + 4) * AVST + nn]);
            }
#pragma unroll
            for (int nt = 0; nt < 8; nt++) MMA_TF32(accO[nt], pl, vh[nt]);
#pragma unroll
            for (int nt = 0; nt < 8; nt++) MMA_TF32(accO[nt], ph, vl[nt]);
#pragma unroll
            for (int nt = 0; nt < 8; nt++) MMA_TF32(accO[nt], ph, vh[nt]);
        }
    }

    const int bb = bh >> 4;
    const int h  = bh & (H_ - 1);
    const float inv0 = 1.0f / l_i[0];
    const float inv1 = 1.0f / l_i[1];
    const int r0 = row0 + wrow + g;
#pragma unroll
    for (int nt = 0; nt < 8; nt++) {
        const int col = h * HD_ + nt * 8 + 2 * t;
        const size_t o0 = ((size_t)(bb * L_ + r0)) * D_ + col;
        const size_t o1 = ((size_t)(bb * L_ + r0 + 8)) * D_ + col;
        uint32_t hx, lx, hy, ly;
        tf32_split(accO[nt][0] * inv0, hx, lx);
        tf32_split(accO[nt][1] * inv0, hy, ly);
        *reinterpret_cast<float2*>(ahi_g + o0) =
            { __uint_as_float(hx), __uint_as_float(hy) };
        *reinterpret_cast<float2*>(alo_g + o0) =
            { __uint_as_float(lx), __uint_as_float(ly) };
        tf32_split(accO[nt][2] * inv1, hx, lx);
        tf32_split(accO[nt][3] * inv1, hy, ly);
        *reinterpret_cast<float2*>(ahi_g + o1) =
            { __uint_as_float(hx), __uint_as_float(hy) };
        *reinterpret_cast<float2*>(alo_g + o1) =
            { __uint_as_float(lx), __uint_as_float(ly) };
    }
}

// ---------------------------------------------------------------------------
extern "C" void kernel_launch(void* const* d_in, const int* in_sizes, int n_in,
                              void* d_out, int out_size)
{
    const float* x     = (const float*)d_in[0];
    const float* w_qkv = (const float*)d_in[1];
    const float* b_qkv = (const float*)d_in[2];
    const float* w_out = (const float*)d_in[3];
    const float* b_out = (const float*)d_in[4];

    float* out  = (float*)d_out;
    float* kout = out  + (size_t)B_ * L_ * D_;
    float* vout = kout + (size_t)B_ * H_ * L_ * HD_;

    float *xhi, *xlo, *wqh, *wql, *woh, *wol;
    float *qhi, *qlo, *khi, *klo, *vhi, *vlo, *ahi, *alo;
    cudaGetSymbolAddress((void**)&xhi, g_xhi);
    cudaGetSymbolAddress((void**)&xlo, g_xlo);
    cudaGetSymbolAddress((void**)&wqh, g_wqh);
    cudaGetSymbolAddress((void**)&wql, g_wql);
    cudaGetSymbolAddress((void**)&woh, g_woh);
    cudaGetSymbolAddress((void**)&wol, g_wol);
    cudaGetSymbolAddress((void**)&qhi, g_qhi);
    cudaGetSymbolAddress((void**)&qlo, g_qlo);
    cudaGetSymbolAddress((void**)&khi, g_khi);
    cudaGetSymbolAddress((void**)&klo, g_klo);
    cudaGetSymbolAddress((void**)&vhi, g_vhi);
    cudaGetSymbolAddress((void**)&vlo, g_vlo);
    cudaGetSymbolAddress((void**)&ahi, g_ahi);
    cudaGetSymbolAddress((void**)&alo, g_alo);

    cudaFuncSetAttribute(gemm_mma<3 * D_, 1>,
                         cudaFuncAttributeMaxDynamicSharedMemorySize, GEMM_SMEM);
    cudaFuncSetAttribute(gemm_mma<D_, 0>,
                         cudaFuncAttributeMaxDynamicSharedMemorySize, GEMM_SMEM);
    cudaFuncSetAttribute(attn_mma,
                         cudaFuncAttributeMaxDynamicSharedMemorySize, ATTN_SMEM);

    // 0) Split inputs into tf32 hi/lo planes
    split_kernel<<<(int)(NX / 4 + 255) / 256, 256>>>(
        (const float4*)x, (float4*)xhi, (float4*)xlo, (int)(NX / 4));
    split_kernel<<<(int)(NWQ / 4 + 255) / 256, 256>>>(
        (const float4*)w_qkv, (float4*)wqh, (float4*)wql, (int)(NWQ / 4));
    split_kernel<<<(int)(NWO / 4 + 255) / 256, 256>>>(
        (const float4*)w_out, (float4*)woh, (float4*)wol, (int)(NWO / 4));

    // 1) QKV projection -> q/k/v hi-lo planes + raw k/v into d_out
    gemm_mma<3 * D_, 1><<<dim3((3 * D_) / 128, (B_ * L_) / 128), 256, GEMM_SMEM>>>(
        xhi, xlo, wqh, wql, b_qkv,
        qhi, qlo, khi, klo, vhi, vlo, kout, vout);

    // 2) Causal flash attention -> attn-out hi/lo planes
    attn_mma<<<dim3(L_ / 128, B_ * H_), 256, ATTN_SMEM>>>(
        qhi, qlo, khi, klo, vhi, vlo, ahi, alo);

    // 3) Output projection -> d_out
    gemm_mma<D_, 0><<<dim3(D_ / 128, (B_ * L_) / 128), 256, GEMM_SMEM>>>(
        ahi, alo, woh, wol, b_out,
        out, nullptr, nullptr, nullptr, nullptr, nullptr, nullptr, nullptr);
}

// round 10
// speedup vs baseline: 1.8511x; 1.7949x over previous
#include <cuda_runtime.h>
#include <cstdint>
#include <math.h>

#define B_  2
#define L_  2048
#define D_  1024
#define H_  16
#define HD_ 64
#define SCALE_ 0.125f

#define NQKV ((size_t)B_ * H_ * L_ * HD_)   // 4,194,304
#define NX   ((size_t)B_ * L_ * D_)
#define NWQ  ((size_t)D_ * 3 * D_)
#define NWO  ((size_t)D_ * D_)
#define PKW  (D_ / 2)                        // 512 packed words per K=1024 row

// Packed bf16x2 hi/lo planes (allocation-free scratch)
__device__ uint32_t g_xh[NX / 2],   g_xl[NX / 2];     // x   [4096][512]
__device__ uint32_t g_wqh[NWQ / 2], g_wql[NWQ / 2];   // Wqkv^T [3072][512]
__device__ uint32_t g_woh[NWO / 2], g_wol[NWO / 2];   // Wout^T [1024][512]
__device__ uint32_t g_qh[NQKV / 2], g_ql[NQKV / 2];   // q  [bh][L][32]
__device__ uint32_t g_kh[NQKV / 2], g_kl[NQKV / 2];   // k  [bh][L][32]
__device__ uint32_t g_vth[NQKV / 2], g_vtl[NQKV / 2]; // v^T [bh][64][1024]
__device__ uint32_t g_ah[NX / 2],   g_al[NX / 2];     // attn out [4096][512]

// ===========================================================================
// Helpers
// ===========================================================================
__device__ __forceinline__ void cp_async16(uint32_t dst, const void* src) {
    asm volatile("cp.async.cg.shared.global [%0], [%1], 16;"
                 :: "r"(dst), "l"(src) : "memory");
}
__device__ __forceinline__ void cp_commit() {
    asm volatile("cp.async.commit_group;" ::: "memory");
}
template<int N>
__device__ __forceinline__ void cp_wait() {
    asm volatile("cp.async.wait_group %0;" :: "n"(N) : "memory");
}
__device__ __forceinline__ uint32_t smem_u32(const void* p) {
    uint32_t a;
    asm("{ .reg .u64 t; cvta.to.shared.u64 t, %1; cvt.u32.u64 %0, t; }"
        : "=r"(a) : "l"(p));
    return a;
}
// pack (lo element, hi element) -> bf16x2 word (low half = first element)
__device__ __forceinline__ uint32_t pack_bf16(float e0, float e1) {
    uint32_t d;
    asm("cvt.rn.bf16x2.f32 %0, %1, %2;" : "=r"(d) : "f"(e1), "f"(e0));
    return d;
}
// split pair into hi-plane word + lo-plane word
__device__ __forceinline__ void bf16x2_split(float x0, float x1,
                                             uint32_t& hw, uint32_t& lw) {
    hw = pack_bf16(x0, x1);
    const float h0 = __uint_as_float(hw << 16);
    const float h1 = __uint_as_float(hw & 0xffff0000u);
    lw = pack_bf16(x0 - h0, x1 - h1);
}
// D(16x8,f32) += A(16x16,bf16) @ B(16x8,bf16)
#define MMA_BF16(c, a, b)                                                      \
    asm("mma.sync.aligned.m16n8k16.row.col.f32.bf16.bf16.f32 "                 \
        "{%0,%1,%2,%3}, {%4,%5,%6,%7}, {%8,%9}, {%0,%1,%2,%3};"                \
        : "+f"((c)[0]), "+f"((c)[1]), "+f"((c)[2]), "+f"((c)[3])               \
        : "r"((a)[0]), "r"((a)[1]), "r"((a)[2]), "r"((a)[3]),                  \
          "r"((b)[0]), "r"((b)[1]))

// ===========================================================================
// Prep kernels
// ===========================================================================
__global__ __launch_bounds__(256)
void pack_rows(const float4* __restrict__ src, uint32_t* __restrict__ dhi,
               uint32_t* __restrict__ dlo, int n4)
{
    const int i = blockIdx.x * blockDim.x + threadIdx.x;
    if (i >= n4) return;
    const float4 v = src[i];
    uint32_t h0, l0, h1, l1;
    bf16x2_split(v.x, v.y, h0, l0);
    bf16x2_split(v.z, v.w, h1, l1);
    dhi[2 * i] = h0; dhi[2 * i + 1] = h1;
    dlo[2 * i] = l0; dlo[2 * i + 1] = l1;
}

// W [K][N] fp32 -> Wp hi/lo [N][K/2] bf16x2 (k-pairs), tile transpose
__global__ __launch_bounds__(256)
void transpose_pack(const float* __restrict__ src, uint32_t* __restrict__ dhi,
                    uint32_t* __restrict__ dlo, int K, int N)
{
    __shared__ float tsm[64][65];
    const int tid = threadIdx.x;
    const int n0 = blockIdx.x * 64;
    const int k0 = blockIdx.y * 64;
#pragma unroll
    for (int i = 0; i < 4; i++) {
        const int idx = tid + i * 256;
        const int kk = idx >> 4, n4 = (idx & 15) * 4;
        const float4 v = *reinterpret_cast<const float4*>(
            src + (size_t)(k0 + kk) * N + n0 + n4);
        tsm[kk][n4] = v.x; tsm[kk][n4 + 1] = v.y;
        tsm[kk][n4 + 2] = v.z; tsm[kk][n4 + 3] = v.w;
    }
    __syncthreads();
    const int kw = K / 2;
#pragma unroll
    for (int i = 0; i < 8; i++) {
        const int idx = tid + i * 256;
        const int nn = idx >> 5, k2 = idx & 31;
        uint32_t hw, lw;
        bf16x2_split(tsm[2 * k2][nn], tsm[2 * k2 + 1][nn], hw, lw);
        const size_t off = (size_t)(n0 + nn) * kw + k0 / 2 + k2;
        dhi[off] = hw;
        dlo[off] = lw;
    }
}

// V raw [bh][L][64] fp32 -> Vt hi/lo [bh][64][L/2] bf16x2 (l-pairs)
__global__ __launch_bounds__(256)
void vtrans(const float* __restrict__ vraw, uint32_t* __restrict__ dhi,
            uint32_t* __restrict__ dlo)
{
    __shared__ float tsm[64][65];
    const int tid = threadIdx.x;
    const int l0 = blockIdx.x * 64;
    const int bh = blockIdx.y;
#pragma unroll
    for (int i = 0; i < 4; i++) {
        const int idx = tid + i * 256;
        const int ll = idx >> 4, h4 = (idx & 15) * 4;
        const float4 v = *reinterpret_cast<const float4*>(
            vraw + ((size_t)bh * L_ + l0 + ll) * HD_ + h4);
        tsm[ll][h4] = v.x; tsm[ll][h4 + 1] = v.y;
        tsm[ll][h4 + 2] = v.z; tsm[ll][h4 + 3] = v.w;
    }
    __syncthreads();
#pragma unroll
    for (int i = 0; i < 8; i++) {
        const int idx = tid + i * 256;
        const int hd = idx >> 5, l2 = idx & 31;
        uint32_t hw, lw;
        bf16x2_split(tsm[2 * l2][hd], tsm[2 * l2 + 1][hd], hw, lw);
        const size_t off = (size_t)bh * HD_ * (L_ / 2) + (size_t)hd * (L_ / 2)
                         + l0 / 2 + l2;
        dhi[off] = hw;
        dlo[off] = lw;
    }
}

// ===========================================================================
// bf16x3 GEMM: C(M x NCOLS) = A @ W + bias. CTA 128x128, K-slab 32 (16 words),
// double-buffered, 256 thr / 8 warps (2m x 4n), warp 64x32. 2 CTAs/SM.
// ===========================================================================
#define GST 20                                   // smem row stride (words)
#define G_TF (128 * GST)                         // 2560 words per plane
#define G_BUFW (4 * G_TF)                        // Ahi,Alo,Bhi,Blo
#define GEMM_SMEM (2 * G_BUFW * 4)               // 81920 B

template<int NCOLS, int QKV>
__global__ __launch_bounds__(256, 2)
void gemm_bf16(const uint32_t* __restrict__ Ahi, const uint32_t* __restrict__ Alo,
               const uint32_t* __restrict__ Whi, const uint32_t* __restrict__ Wlo,
               const float* __restrict__ bias,
               float* __restrict__ outF,
               uint32_t* __restrict__ qh, uint32_t* __restrict__ ql,
               uint32_t* __restrict__ kh, uint32_t* __restrict__ kl,
               float* __restrict__ kraw, float* __restrict__ vraw)
{
    extern __shared__ uint32_t smu[];
    const uint32_t sb = smem_u32(smu);

    const int tid  = threadIdx.x;
    const int wid  = tid >> 5;
    const int lane = tid & 31;
    const int g = lane >> 2;
    const int t = lane & 3;
    const int wm0 = (wid >> 2) * 64;
    const int wn0 = (wid & 3) * 32;
    const int m0 = blockIdx.y * 128;
    const int n0 = blockIdx.x * 128;

    float acc[4][4][4];
#pragma unroll
    for (int mt = 0; mt < 4; mt++)
#pragma unroll
        for (int nt = 0; nt < 4; nt++)
#pragma unroll
            for (int r = 0; r < 4; r++) acc[mt][nt][r] = 0.f;

    auto load_stage = [&](int s, int b) {
        const int kw0 = s * 16;                   // word offset in K
        const uint32_t aH = sb + (uint32_t)(b * G_BUFW) * 4;
        const uint32_t aL = aH + G_TF * 4;
        const uint32_t bH = aL + G_TF * 4;
        const uint32_t bL = bH + G_TF * 4;
#pragma unroll
        for (int i = 0; i < 2; i++) {             // A: 512 chunks/plane
            const int idx = tid + i * 256;
            const int r = idx >> 2, c4 = (idx & 3) * 4;
            const size_t go = (size_t)(m0 + r) * PKW + kw0 + c4;
            const uint32_t so = (uint32_t)(r * GST + c4) * 4;
            cp_async16(aH + so, Ahi + go);
            cp_async16(aL + so, Alo + go);
        }
#pragma unroll
        for (int i = 0; i < 2; i++) {             // B: 512 chunks/plane
            const int idx = tid + i * 256;
            const int r = idx >> 2, c4 = (idx & 3) * 4;
            const size_t go = (size_t)(n0 + r) * PKW + kw0 + c4;
            const uint32_t so = (uint32_t)(r * GST + c4) * 4;
            cp_async16(bH + so, Whi + go);
            cp_async16(bL + so, Wlo + go);
        }
        cp_commit();
    };

    auto compute_stage = [&](int b) {
        const uint32_t* AH = smu + b * G_BUFW;
        const uint32_t* AL = AH + G_TF;
        const uint32_t* BH = AL + G_TF;
        const uint32_t* BL = BH + G_TF;
#pragma unroll
        for (int k16 = 0; k16 < 2; k16++) {
            const int kb2 = k16 * 8;
            uint32_t ah[4][4], al[4][4], bh[4][2], bl[4][2];
#pragma unroll
            for (int mt = 0; mt < 4; mt++) {
                const int ro = (wm0 + mt * 16 + g) * GST + kb2;
                ah[mt][0] = AH[ro + t];
                ah[mt][1] = AH[ro + 8 * GST + t];
                ah[mt][2] = AH[ro + t + 4];
                ah[mt][3] = AH[ro + 8 * GST + t + 4];
                al[mt][0] = AL[ro + t];
                al[mt][1] = AL[ro + 8 * GST + t];
                al[mt][2] = AL[ro + t + 4];
                al[mt][3] = AL[ro + 8 * GST + t + 4];
            }
#pragma unroll
            for (int nt = 0; nt < 4; nt++) {
                const int no = (wn0 + nt * 8 + g) * GST + kb2;
                bh[nt][0] = BH[no + t]; bh[nt][1] = BH[no + t + 4];
                bl[nt][0] = BL[no + t]; bl[nt][1] = BL[no + t + 4];
            }
#pragma unroll
            for (int mt = 0; mt < 4; mt++)
#pragma unroll
                for (int nt = 0; nt < 4; nt++)
                    MMA_BF16(acc[mt][nt], al[mt], bh[nt]);
#pragma unroll
            for (int mt = 0; mt < 4; mt++)
#pragma unroll
                for (int nt = 0; nt < 4; nt++)
                    MMA_BF16(acc[mt][nt], ah[mt], bl[nt]);
#pragma unroll
            for (int mt = 0; mt < 4; mt++)
#pragma unroll
                for (int nt = 0; nt < 4; nt++)
                    MMA_BF16(acc[mt][nt], ah[mt], bh[nt]);
        }
    };

    load_stage(0, 0);
    constexpr int NS = D_ / 32;
    for (int s = 0; s < NS; s++) {
        const int b = s & 1;
        if (s + 1 < NS) {
            load_stage(s + 1, b ^ 1);
            cp_wait<1>();
        } else {
            cp_wait<0>();
        }
        __syncthreads();
        compute_stage(b);
        __syncthreads();
    }

    // epilogue
#pragma unroll
    for (int mt = 0; mt < 4; mt++) {
#pragma unroll
        for (int half = 0; half < 2; half++) {
            const int m = m0 + wm0 + mt * 16 + g + half * 8;
            int bb = 0, l = 0;
            if (QKV) { bb = m >> 11; l = m & (L_ - 1); }
#pragma unroll
            for (int nt = 0; nt < 4; nt++) {
                const int n = n0 + wn0 + nt * 8 + t * 2;
                float2 v;
                v.x = acc[mt][nt][half * 2 + 0] + bias[n];
                v.y = acc[mt][nt][half * 2 + 1] + bias[n + 1];
                if (QKV) {
                    const int sidx = n0 >> 10;
                    const int h = (n >> 6) & (H_ - 1), dd = n & (HD_ - 1);
                    const size_t row = (size_t)(bb * H_ + h) * L_ + l;
                    const size_t woff = row * 32 + (dd >> 1);
                    if (sidx == 0) {
                        uint32_t hw, lw;
                        bf16x2_split(v.x, v.y, hw, lw);
                        qh[woff] = hw; ql[woff] = lw;
                    } else if (sidx == 1) {
                        uint32_t hw, lw;
                        bf16x2_split(v.x, v.y, hw, lw);
                        kh[woff] = hw; kl[woff] = lw;
                        *reinterpret_cast<float2*>(kraw + row * HD_ + dd) = v;
                    } else {
                        *reinterpret_cast<float2*>(vraw + row * HD_ + dd) = v;
                    }
                } else {
                    *reinterpret_cast<float2*>(outF + (size_t)m * NCOLS + n) = v;
                }
            }
        }
    }
}

// ===========================================================================
// Flash attention (causal), bf16x3 m16n8k16. 256 thr / 8 warps, warp = 16 q
// rows. Key tiles 64, double-buffered K/V planes; P packed from registers.
// ===========================================================================
#define ATST 36
#define AQ_WORDS (128 * ATST)                    // 4608 per plane
#define ABUF0 (2 * AQ_WORDS)                     // 9216
#define AKV_TILE (64 * ATST)                     // 2304 words
#define ABUFW (4 * AKV_TILE)                     // Khi,Klo,Vhi,Vlo = 9216
#define ATTN_WORDS (ABUF0 + 2 * ABUFW)           // 27648
#define ATTN_SMEM (ATTN_WORDS * 4)               // 110592 B

__global__ __launch_bounds__(256)
void attn_bf16(const uint32_t* __restrict__ qh_g, const uint32_t* __restrict__ ql_g,
               const uint32_t* __restrict__ kh_g, const uint32_t* __restrict__ kl_g,
               const uint32_t* __restrict__ vth_g, const uint32_t* __restrict__ vtl_g,
               uint32_t* __restrict__ ah_g, uint32_t* __restrict__ al_g)
{
    extern __shared__ uint32_t smu[];
    const uint32_t sb = smem_u32(smu);

    const int tidx = (int)gridDim.x - 1 - (int)blockIdx.x;  // heavy first
    const int bh   = blockIdx.y;
    const int row0 = tidx * 128;
    const uint32_t* qhp = qh_g + (size_t)bh * L_ * 32;
    const uint32_t* qlp = ql_g + (size_t)bh * L_ * 32;
    const uint32_t* khp = kh_g + (size_t)bh * L_ * 32;
    const uint32_t* klp = kl_g + (size_t)bh * L_ * 32;
    const uint32_t* vhp = vth_g + (size_t)bh * HD_ * (L_ / 2);
    const uint32_t* vlp = vtl_g + (size_t)bh * HD_ * (L_ / 2);

    const int tid = threadIdx.x;
    const int wid = tid >> 5;
    const int lane = tid & 31;
    const int g = lane >> 2;
    const int t = lane & 3;
    const int wrow = wid * 16;

    auto load_kv = [&](int c0, int b) {
        const uint32_t kH = sb + (uint32_t)(ABUF0 + b * ABUFW) * 4;
        const uint32_t kL = kH + AKV_TILE * 4;
        const uint32_t vH = kL + AKV_TILE * 4;
        const uint32_t vL = vH + AKV_TILE * 4;
#pragma unroll
        for (int i = 0; i < 2; i++) {            // K: 512 chunks/plane
            const int idx = tid + i * 256;
            const int r = idx >> 3, c4 = (idx & 7) * 4;
            const uint32_t so = (uint32_t)(r * ATST + c4) * 4;
            cp_async16(kH + so, khp + (size_t)(c0 + r) * 32 + c4);
            cp_async16(kL + so, klp + (size_t)(c0 + r) * 32 + c4);
        }
#pragma unroll
        for (int i = 0; i < 2; i++) {            // Vt: rows = hd
            const int idx = tid + i * 256;
            const int r = idx >> 3, c4 = (idx & 7) * 4;
            const uint32_t so = (uint32_t)(r * ATST + c4) * 4;
            cp_async16(vH + so, vhp + (size_t)r * (L_ / 2) + c0 / 2 + c4);
            cp_async16(vL + so, vlp + (size_t)r * (L_ / 2) + c0 / 2 + c4);
        }
        cp_commit();
    };
    load_kv(0, 0);

    // Q tile (plain loads, overlap with cp.async)
    uint32_t* Qh = smu;
    uint32_t* Ql = smu + AQ_WORDS;
#pragma unroll
    for (int i = 0; i < 2; i++) {
        const int idx = tid + i * 256;           // 512 rows x 4 chunk cols
        const int r = idx >> 2, c4 = (idx & 3) * 8;
        *reinterpret_cast<uint4*>(&Qh[r * ATST + c4]) =
            *reinterpret_cast<const uint4*>(qhp + (size_t)(row0 + r) * 32 + c4);
        *reinterpret_cast<uint4*>(&Qh[r * ATST + c4 + 4]) =
            *reinterpret_cast<const uint4*>(qhp + (size_t)(row0 + r) * 32 + c4 + 4);
        *reinterpret_cast<uint4*>(&Ql[r * ATST + c4]) =
            *reinterpret_cast<const uint4*>(qlp + (size_t)(row0 + r) * 32 + c4);
        *reinterpret_cast<uint4*>(&Ql[r * ATST + c4 + 4]) =
            *reinterpret_cast<const uint4*>(qlp + (size_t)(row0 + r) * 32 + c4 + 4);
    }

    float accO[8][4];
    float m_i[2] = { -1e30f, -1e30f };
    float l_i[2] = { 0.f, 0.f };
#pragma unroll
    for (int nt = 0; nt < 8; nt++)
#pragma unroll
        for (int e = 0; e < 4; e++) accO[nt][e] = 0.f;

    const int jmax = 2 * tidx + 1;
    for (int j0 = 0; j0 <= jmax; j0++) {
        const int c0 = j0 * 64;
        const int b = j0 & 1;

        cp_wait<0>();
        __syncthreads();                          // tile b ready, prior tile done

        if (j0 < jmax) load_kv(c0 + 64, b ^ 1);

        const uint32_t* KH = smu + ABUF0 + b * ABUFW;
        const uint32_t* KL = KH + AKV_TILE;
        const uint32_t* VH = KL + AKV_TILE;
        const uint32_t* VL = VH + AKV_TILE;

        // ---- S = Q @ K^T, bf16x3, 4 k16 steps ----
        float s[8][4];
#pragma unroll
        for (int nt = 0; nt < 8; nt++)
#pragma unroll
            for (int e = 0; e < 4; e++) s[nt][e] = 0.f;

#pragma unroll
        for (int k16 = 0; k16 < 4; k16++) {
            const int kb2 = k16 * 8;
            uint32_t ah[4], al[4], bh2[8][2], bl2[8][2];
            const int qo = (wrow + g) * ATST + kb2;
            ah[0] = Qh[qo + t];            al[0] = Ql[qo + t];
            ah[1] = Qh[qo + 8 * ATST + t]; al[1] = Ql[qo + 8 * ATST + t];
            ah[2] = Qh[qo + t + 4];        al[2] = Ql[qo + t + 4];
            ah[3] = Qh[qo + 8 * ATST + t + 4];
            al[3] = Ql[qo + 8 * ATST + t + 4];
#pragma unroll
            for (int nt = 0; nt < 8; nt++) {
                const int ko = (nt * 8 + g) * ATST + kb2;
                bh2[nt][0] = KH[ko + t]; bh2[nt][1] = KH[ko + t + 4];
                bl2[nt][0] = KL[ko + t]; bl2[nt][1] = KL[ko + t + 4];
            }
#pragma unroll
            for (int nt = 0; nt < 8; nt++) MMA_BF16(s[nt], al, bh2[nt]);
#pragma unroll
            for (int nt = 0; nt < 8; nt++) MMA_BF16(s[nt], ah, bl2[nt]);
#pragma unroll
            for (int nt = 0; nt < 8; nt++) MMA_BF16(s[nt], ah, bh2[nt]);
        }

        // ---- scale + causal mask ----
        const bool dm = (c0 + 63 > row0);
        const int r0 = row0 + wrow + g;
        const int r1 = r0 + 8;
#pragma unroll
        for (int nt = 0; nt < 8; nt++) {
#pragma unroll
            for (int e = 0; e < 4; e++) {
                const int col = c0 + nt * 8 + 2 * t + (e & 1);
                const int row = (e < 2) ? r0 : r1;
                s[nt][e] *= SCALE_;
                if (dm && col > row) s[nt][e] = -1e30f;
            }
        }

        // ---- online softmax ----
        float mx0 = -1e30f, mx1 = -1e30f;
#pragma unroll
        for (int nt = 0; nt < 8; nt++) {
            mx0 = fmaxf(mx0, fmaxf(s[nt][0], s[nt][1]));
            mx1 = fmaxf(mx1, fmaxf(s[nt][2], s[nt][3]));
        }
#pragma unroll
        for (int off = 1; off <= 2; off <<= 1) {
            mx0 = fmaxf(mx0, __shfl_xor_sync(0xffffffffu, mx0, off));
            mx1 = fmaxf(mx1, __shfl_xor_sync(0xffffffffu, mx1, off));
        }
        const float mn0 = fmaxf(m_i[0], mx0);
        const float mn1 = fmaxf(m_i[1], mx1);
        const float corr0 = __expf(m_i[0] - mn0);
        const float corr1 = __expf(m_i[1] - mn1);
        m_i[0] = mn0; m_i[1] = mn1;

        float ls0 = 0.f, ls1 = 0.f;
#pragma unroll
        for (int nt = 0; nt < 8; nt++) {
            s[nt][0] = __expf(s[nt][0] - mn0);
            s[nt][1] = __expf(s[nt][1] - mn0);
            s[nt][2] = __expf(s[nt][2] - mn1);
            s[nt][3] = __expf(s[nt][3] - mn1);
            ls0 += s[nt][0] + s[nt][1];
            ls1 += s[nt][2] + s[nt][3];
        }
#pragma unroll
        for (int off = 1; off <= 2; off <<= 1) {
            ls0 += __shfl_xor_sync(0xffffffffu, ls0, off);
            ls1 += __shfl_xor_sync(0xffffffffu, ls1, off);
        }
        l_i[0] = l_i[0] * corr0 + ls0;
        l_i[1] = l_i[1] * corr1 + ls1;
#pragma unroll
        for (int nt = 0; nt < 8; nt++) {
            accO[nt][0] *= corr0; accO[nt][1] *= corr0;
            accO[nt][2] *= corr1; accO[nt][3] *= corr1;
        }

        // ---- pack P from registers (no SMEM staging) ----
        uint32_t phw[8][2], plw[8][2];
#pragma unroll
        for (int nt = 0; nt < 8; nt++) {
            bf16x2_split(s[nt][0], s[nt][1], phw[nt][0], plw[nt][0]);
            bf16x2_split(s[nt][2], s[nt][3], phw[nt][1], plw[nt][1]);
        }

        // ---- O += P @ V, bf16x3, 4 k16 steps over 64 keys ----
#pragma unroll
        for (int ks = 0; ks < 4; ks++) {
            const int kb2 = ks * 8;
            uint32_t pah[4] = { phw[2 * ks][0], phw[2 * ks][1],
                                phw[2 * ks + 1][0], phw[2 * ks + 1][1] };
            uint32_t pal[4] = { plw[2 * ks][0], plw[2 * ks][1],
                                plw[2 * ks + 1][0], plw[2 * ks + 1][1] };
            uint32_t vh[8][2], vl[8][2];
#pragma unroll
            for (int nt = 0; nt < 8; nt++) {
                const int vo = (nt * 8 + g) * ATST + kb2;
                vh[nt][0] = VH[vo + t]; vh[nt][1] = VH[vo + t + 4];
                vl[nt][0] = VL[vo + t]; vl[nt][1] = VL[vo + t + 4];
            }
#pragma unroll
            for (int nt = 0; nt < 8; nt++) MMA_BF16(accO[nt], pal, vh[nt]);
#pragma unroll
            for (int nt = 0; nt < 8; nt++) MMA_BF16(accO[nt], pah, vl[nt]);
#pragma unroll
            for (int nt = 0; nt < 8; nt++) MMA_BF16(accO[nt], pah, vh[nt]);
        }
    }

    // ---- finalize: /l, pack hi/lo words into attn-out planes ----
    const int bb = bh >> 4;
    const int h  = bh & (H_ - 1);
    const float inv0 = 1.0f / l_i[0];
    const float inv1 = 1.0f / l_i[1];
    const int r0 = row0 + wrow + g;
#pragma unroll
    for (int nt = 0; nt < 8; nt++) {
        const int widx = h * 32 + nt * 4 + t;
        uint32_t hw, lw;
        bf16x2_split(accO[nt][0] * inv0, accO[nt][1] * inv0, hw, lw);
        ah_g[((size_t)(bb * L_ + r0)) * 512 + widx] = hw;
        al_g[((size_t)(bb * L_ + r0)) * 512 + widx] = lw;
        bf16x2_split(accO[nt][2] * inv1, accO[nt][3] * inv1, hw, lw);
        ah_g[((size_t)(bb * L_ + r0 + 8)) * 512 + widx] = hw;
        al_g[((size_t)(bb * L_ + r0 + 8)) * 512 + widx] = lw;
    }
}

// ---------------------------------------------------------------------------
extern "C" void kernel_launch(void* const* d_in, const int* in_sizes, int n_in,
                              void* d_out, int out_size)
{
    const float* x     = (const float*)d_in[0];
    const float* w_qkv = (const float*)d_in[1];
    const float* b_qkv = (const float*)d_in[2];
    const float* w_out = (const float*)d_in[3];
    const float* b_out = (const float*)d_in[4];

    float* out  = (float*)d_out;
    float* kout = out  + (size_t)B_ * L_ * D_;
    float* vout = kout + NQKV;

    uint32_t *xh, *xl, *wqh, *wql, *woh, *wol;
    uint32_t *qh, *ql, *kh, *kl, *vth, *vtl, *ah, *al;
    cudaGetSymbolAddress((void**)&xh, g_xh);
    cudaGetSymbolAddress((void**)&xl, g_xl);
    cudaGetSymbolAddress((void**)&wqh, g_wqh);
    cudaGetSymbolAddress((void**)&wql, g_wql);
    cudaGetSymbolAddress((void**)&woh, g_woh);
    cudaGetSymbolAddress((void**)&wol, g_wol);
    cudaGetSymbolAddress((void**)&qh, g_qh);
    cudaGetSymbolAddress((void**)&ql, g_ql);
    cudaGetSymbolAddress((void**)&kh, g_kh);
    cudaGetSymbolAddress((void**)&kl, g_kl);
    cudaGetSymbolAddress((void**)&vth, g_vth);
    cudaGetSymbolAddress((void**)&vtl, g_vtl);
    cudaGetSymbolAddress((void**)&ah, g_ah);
    cudaGetSymbolAddress((void**)&al, g_al);

    cudaFuncSetAttribute(gemm_bf16<3 * D_, 1>,
                         cudaFuncAttributeMaxDynamicSharedMemorySize, GEMM_SMEM);
    cudaFuncSetAttribute(gemm_bf16<D_, 0>,
                         cudaFuncAttributeMaxDynamicSharedMemorySize, GEMM_SMEM);
    cudaFuncSetAttribute(attn_bf16,
                         cudaFuncAttributeMaxDynamicSharedMemorySize, ATTN_SMEM);

    // 0) Prep: pack x rows; transpose-pack weights
    pack_rows<<<(int)(NX / 4 + 255) / 256, 256>>>(
        (const float4*)x, xh, xl, (int)(NX / 4));
    transpose_pack<<<dim3(3 * D_ / 64, D_ / 64), 256>>>(w_qkv, wqh, wql, D_, 3 * D_);
    transpose_pack<<<dim3(D_ / 64, D_ / 64), 256>>>(w_out, woh, wol, D_, D_);

    // 1) QKV projection
    gemm_bf16<3 * D_, 1><<<dim3(24, 32), 256, GEMM_SMEM>>>(
        xh, xl, wqh, wql, b_qkv, nullptr, qh, ql, kh, kl, kout, vout);

    // 1b) Transpose-pack V from raw
    vtrans<<<dim3(L_ / 64, B_ * H_), 256>>>(vout, vth, vtl);

    // 2) Causal flash attention
    attn_bf16<<<dim3(L_ / 128, B_ * H_), 256, ATTN_SMEM>>>(
        qh, ql, kh, kl, vth, vtl, ah, al);

    // 3) Output projection
    gemm_bf16<D_, 0><<<dim3(8, 32), 256, GEMM_SMEM>>>(
        ah, al, woh, wol, b_out, out,
        nullptr, nullptr, nullptr, nullptr, nullptr, nullptr);
}

// round 12
// speedup vs baseline: 1.9796x; 1.0694x over previous
#include <cuda_runtime.h>
#include <cstdint>
#include <math.h>

#define B_  2
#define L_  2048
#define D_  1024
#define H_  16
#define HD_ 64
#define SCALE_ 0.125f

#define NQKV ((size_t)B_ * H_ * L_ * HD_)
#define NX   ((size_t)B_ * L_ * D_)
#define NWQ  ((size_t)D_ * 3 * D_)
#define NWO  ((size_t)D_ * D_)
#define PKW  (D_ / 2)

// Packed bf16x2 hi/lo planes (allocation-free scratch)
__device__ uint32_t g_xh[NX / 2],   g_xl[NX / 2];
__device__ uint32_t g_wqh[NWQ / 2], g_wql[NWQ / 2];
__device__ uint32_t g_woh[NWO / 2], g_wol[NWO / 2];
__device__ uint32_t g_qh[NQKV / 2], g_ql[NQKV / 2];
__device__ uint32_t g_kh[NQKV / 2], g_kl[NQKV / 2];
__device__ uint32_t g_vth[NQKV / 2], g_vtl[NQKV / 2];  // v^T [bh][64][L/2]
__device__ uint32_t g_ah[NX / 2],   g_al[NX / 2];

// ===========================================================================
// Helpers
// ===========================================================================
__device__ __forceinline__ void cp_async16(uint32_t dst, const void* src) {
    asm volatile("cp.async.cg.shared.global [%0], [%1], 16;"
                 :: "r"(dst), "l"(src) : "memory");
}
__device__ __forceinline__ void cp_commit() {
    asm volatile("cp.async.commit_group;" ::: "memory");
}
template<int N>
__device__ __forceinline__ void cp_wait() {
    asm volatile("cp.async.wait_group %0;" :: "n"(N) : "memory");
}
__device__ __forceinline__ uint32_t smem_u32(const void* p) {
    uint32_t a;
    asm("{ .reg .u64 t; cvta.to.shared.u64 t, %1; cvt.u32.u64 %0, t; }"
        : "=r"(a) : "l"(p));
    return a;
}
__device__ __forceinline__ uint32_t pack_bf16(float e0, float e1) {
    uint32_t d;
    asm("cvt.rn.bf16x2.f32 %0, %1, %2;" : "=r"(d) : "f"(e1), "f"(e0));
    return d;
}
__device__ __forceinline__ void bf16x2_split(float x0, float x1,
                                             uint32_t& hw, uint32_t& lw) {
    hw = pack_bf16(x0, x1);
    const float h0 = __uint_as_float(hw << 16);
    const float h1 = __uint_as_float(hw & 0xffff0000u);
    lw = pack_bf16(x0 - h0, x1 - h1);
}
#define MMA_BF16(c, a, b)                                                      \
    asm("mma.sync.aligned.m16n8k16.row.col.f32.bf16.bf16.f32 "                 \
        "{%0,%1,%2,%3}, {%4,%5,%6,%7}, {%8,%9}, {%0,%1,%2,%3};"                \
        : "+f"((c)[0]), "+f"((c)[1]), "+f"((c)[2]), "+f"((c)[3])               \
        : "r"((a)[0]), "r"((a)[1]), "r"((a)[2]), "r"((a)[3]),                  \
          "r"((b)[0]), "r"((b)[1]))
#define LDSM_X4(r0, r1, r2, r3, addr)                                          \
    asm volatile("ldmatrix.sync.aligned.m8n8.x4.shared.b16 {%0,%1,%2,%3}, [%4];" \
        : "=r"(r0), "=r"(r1), "=r"(r2), "=r"(r3) : "r"(addr))

// ===========================================================================
// Prep kernels
// ===========================================================================
__global__ __launch_bounds__(256)
void pack_rows(const float4* __restrict__ src, uint32_t* __restrict__ dhi,
               uint32_t* __restrict__ dlo, int n4)
{
    const int i = blockIdx.x * blockDim.x + threadIdx.x;
    if (i >= n4) return;
    const float4 v = src[i];
    uint32_t h0, l0, h1, l1;
    bf16x2_split(v.x, v.y, h0, l0);
    bf16x2_split(v.z, v.w, h1, l1);
    dhi[2 * i] = h0; dhi[2 * i + 1] = h1;
    dlo[2 * i] = l0; dlo[2 * i + 1] = l1;
}

__global__ __launch_bounds__(256)
void transpose_pack(const float* __restrict__ src, uint32_t* __restrict__ dhi,
                    uint32_t* __restrict__ dlo, int K, int N)
{
    __shared__ float tsm[64][65];
    const int tid = threadIdx.x;
    const int n0 = blockIdx.x * 64;
    const int k0 = blockIdx.y * 64;
#pragma unroll
    for (int i = 0; i < 4; i++) {
        const int idx = tid + i * 256;
        const int kk = idx >> 4, n4 = (idx & 15) * 4;
        const float4 v = *reinterpret_cast<const float4*>(
            src + (size_t)(k0 + kk) * N + n0 + n4);
        tsm[kk][n4] = v.x; tsm[kk][n4 + 1] = v.y;
        tsm[kk][n4 + 2] = v.z; tsm[kk][n4 + 3] = v.w;
    }
    __syncthreads();
    const int kw = K / 2;
#pragma unroll
    for (int i = 0; i < 8; i++) {
        const int idx = tid + i * 256;
        const int nn = idx >> 5, k2 = idx & 31;
        uint32_t hw, lw;
        bf16x2_split(tsm[2 * k2][nn], tsm[2 * k2 + 1][nn], hw, lw);
        const size_t off = (size_t)(n0 + nn) * kw + k0 / 2 + k2;
        dhi[off] = hw;
        dlo[off] = lw;
    }
}

// ===========================================================================
// bf16x3 GEMM (CTA 128x128, K-slab 32, 256 thr / 8 warps 2x4, 2 CTAs/SM).
// Fragment loads via ldmatrix.x4. QKV epilogue also emits V^T planes (fused).
// ===========================================================================
#define GST 20
#define G_TF (128 * GST)
#define G_BUFW (4 * G_TF)
#define GEMM_SMEM (2 * G_BUFW * 4)               // 81920 B

template<int NCOLS, int QKV>
__global__ __launch_bounds__(256, 2)
void gemm_bf16(const uint32_t* __restrict__ Ahi, const uint32_t* __restrict__ Alo,
               const uint32_t* __restrict__ Whi, const uint32_t* __restrict__ Wlo,
               const float* __restrict__ bias,
               float* __restrict__ outF,
               uint32_t* __restrict__ qh, uint32_t* __restrict__ ql,
               uint32_t* __restrict__ kh, uint32_t* __restrict__ kl,
               uint32_t* __restrict__ vth, uint32_t* __restrict__ vtl,
               float* __restrict__ kraw, float* __restrict__ vraw)
{
    extern __shared__ uint32_t smu[];
    const uint32_t sb = smem_u32(smu);

    const int tid  = threadIdx.x;
    const int wid  = tid >> 5;
    const int lane = tid & 31;
    const int g = lane >> 2;
    const int t = lane & 3;
    const int wm0 = (wid >> 2) * 64;
    const int wn0 = (wid & 3) * 32;
    const int m0 = blockIdx.y * 128;
    const int n0 = blockIdx.x * 128;

    // per-lane ldmatrix byte offsets
    const uint32_t laneA = (uint32_t)(((lane & 15) * GST + (lane >> 4) * 4) * 4);
    const uint32_t laneB = (uint32_t)((((lane & 7) + (lane >> 4) * 8) * GST
                                      + ((lane >> 3) & 1) * 4) * 4);

    float acc[4][4][4];
#pragma unroll
    for (int mt = 0; mt < 4; mt++)
#pragma unroll
        for (int nt = 0; nt < 4; nt++)
#pragma unroll
            for (int r = 0; r < 4; r++) acc[mt][nt][r] = 0.f;

    auto load_stage = [&](int s, int b) {
        const int kw0 = s * 16;
        const uint32_t aH = sb + (uint32_t)(b * G_BUFW) * 4;
        const uint32_t aL = aH + G_TF * 4;
        const uint32_t bH = aL + G_TF * 4;
        const uint32_t bL = bH + G_TF * 4;
#pragma unroll
        for (int i = 0; i < 2; i++) {
            const int idx = tid + i * 256;
            const int r = idx >> 2, c4 = (idx & 3) * 4;
            const size_t go = (size_t)(m0 + r) * PKW + kw0 + c4;
            const uint32_t so = (uint32_t)(r * GST + c4) * 4;
            cp_async16(aH + so, Ahi + go);
            cp_async16(aL + so, Alo + go);
        }
#pragma unroll
        for (int i = 0; i < 2; i++) {
            const int idx = tid + i * 256;
            const int r = idx >> 2, c4 = (idx & 3) * 4;
            const size_t go = (size_t)(n0 + r) * PKW + kw0 + c4;
            const uint32_t so = (uint32_t)(r * GST + c4) * 4;
            cp_async16(bH + so, Whi + go);
            cp_async16(bL + so, Wlo + go);
        }
        cp_commit();
    };

    auto compute_stage = [&](int b) {
        const uint32_t aH = sb + (uint32_t)(b * G_BUFW) * 4;
        const uint32_t aL = aH + G_TF * 4;
        const uint32_t bHa = aL + G_TF * 4;
        const uint32_t bLa = bHa + G_TF * 4;
#pragma unroll
        for (int k16 = 0; k16 < 2; k16++) {
            const uint32_t kboff = (uint32_t)(k16 * 32);   // 8 words
            uint32_t ah[4][4], al[4][4], bh[4][2], bl[4][2];
#pragma unroll
            for (int mt = 0; mt < 4; mt++) {
                const uint32_t base = (uint32_t)((wm0 + mt * 16) * GST * 4) + kboff + laneA;
                LDSM_X4(ah[mt][0], ah[mt][1], ah[mt][2], ah[mt][3], aH + base);
                LDSM_X4(al[mt][0], al[mt][1], al[mt][2], al[mt][3], aL + base);
            }
#pragma unroll
            for (int nt2 = 0; nt2 < 2; nt2++) {
                const uint32_t base = (uint32_t)((wn0 + nt2 * 16) * GST * 4) + kboff + laneB;
                LDSM_X4(bh[2 * nt2][0], bh[2 * nt2][1],
                        bh[2 * nt2 + 1][0], bh[2 * nt2 + 1][1], bHa + base);
                LDSM_X4(bl[2 * nt2][0], bl[2 * nt2][1],
                        bl[2 * nt2 + 1][0], bl[2 * nt2 + 1][1], bLa + base);
            }
#pragma unroll
            for (int mt = 0; mt < 4; mt++)
#pragma unroll
                for (int nt = 0; nt < 4; nt++)
                    MMA_BF16(acc[mt][nt], al[mt], bh[nt]);
#pragma unroll
            for (int mt = 0; mt < 4; mt++)
#pragma unroll
                for (int nt = 0; nt < 4; nt++)
                    MMA_BF16(acc[mt][nt], ah[mt], bl[nt]);
#pragma unroll
            for (int mt = 0; mt < 4; mt++)
#pragma unroll
                for (int nt = 0; nt < 4; nt++)
                    MMA_BF16(acc[mt][nt], ah[mt], bh[nt]);
        }
    };

    load_stage(0, 0);
    constexpr int NS = D_ / 32;
    for (int s = 0; s < NS; s++) {
        const int b = s & 1;
        if (s + 1 < NS) {
            load_stage(s + 1, b ^ 1);
            cp_wait<1>();
        } else {
            cp_wait<0>();
        }
        __syncthreads();
        compute_stage(b);
        __syncthreads();
    }

    // epilogue
#pragma unroll
    for (int mt = 0; mt < 4; mt++) {
#pragma unroll
        for (int half = 0; half < 2; half++) {
            const int m = m0 + wm0 + mt * 16 + g + half * 8;
            int bb = 0, l = 0;
            if (QKV) { bb = m >> 11; l = m & (L_ - 1); }
#pragma unroll
            for (int nt = 0; nt < 4; nt++) {
                const int n = n0 + wn0 + nt * 8 + t * 2;
                float2 v;
                v.x = acc[mt][nt][half * 2 + 0] + bias[n];
                v.y = acc[mt][nt][half * 2 + 1] + bias[n + 1];
                if (QKV) {
                    const int sidx = n0 >> 10;   // block-uniform q/k/v select
                    const int h = (n >> 6) & (H_ - 1), dd = n & (HD_ - 1);
                    const size_t row = (size_t)(bb * H_ + h) * L_ + l;
                    const size_t woff = row * 32 + (dd >> 1);
                    if (sidx == 0) {
                        uint32_t hw, lw;
                        bf16x2_split(v.x, v.y, hw, lw);
                        qh[woff] = hw; ql[woff] = lw;
                    } else if (sidx == 1) {
                        uint32_t hw, lw;
                        bf16x2_split(v.x, v.y, hw, lw);
                        kh[woff] = hw; kl[woff] = lw;
                        *reinterpret_cast<float2*>(kraw + row * HD_ + dd) = v;
                    } else {
                        // raw V out + fused V^T hi/lo pack via row-pair shfl
                        *reinterpret_cast<float2*>(vraw + row * HD_ + dd) = v;
                        const float vxn = __shfl_down_sync(0xffffffffu, v.x, 4);
                        const float vyn = __shfl_down_sync(0xffffffffu, v.y, 4);
                        if ((g & 1) == 0) {
                            const size_t vb = (size_t)(bb * H_ + h) * HD_ * (L_ / 2);
                            const size_t l2 = (size_t)(l >> 1);
                            uint32_t hw, lw;
                            bf16x2_split(v.x, vxn, hw, lw);
                            vth[vb + (size_t)dd * (L_ / 2) + l2] = hw;
                            vtl[vb + (size_t)dd * (L_ / 2) + l2] = lw;
                            bf16x2_split(v.y, vyn, hw, lw);
                            vth[vb + (size_t)(dd + 1) * (L_ / 2) + l2] = hw;
                            vtl[vb + (size_t)(dd + 1) * (L_ / 2) + l2] = lw;
                        }
                    }
                } else {
                    *reinterpret_cast<float2*>(outF + (size_t)m * NCOLS + n) = v;
                }
            }
        }
    }
}

// ===========================================================================
// Flash attention (causal), bf16x3 m16n8k16 with ldmatrix fragment loads.
// ===========================================================================
#define ATST 36
#define AQ_WORDS (128 * ATST)
#define ABUF0 (2 * AQ_WORDS)
#define AKV_TILE (64 * ATST)
#define ABUFW (4 * AKV_TILE)
#define ATTN_WORDS (ABUF0 + 2 * ABUFW)
#define ATTN_SMEM (ATTN_WORDS * 4)               // 110592 B

__global__ __launch_bounds__(256)
void attn_bf16(const uint32_t* __restrict__ qh_g, const uint32_t* __restrict__ ql_g,
               const uint32_t* __restrict__ kh_g, const uint32_t* __restrict__ kl_g,
               const uint32_t* __restrict__ vth_g, const uint32_t* __restrict__ vtl_g,
               uint32_t* __restrict__ ah_g, uint32_t* __restrict__ al_g)
{
    extern __shared__ uint32_t smu[];
    const uint32_t sb = smem_u32(smu);

    const int tidx = (int)gridDim.x - 1 - (int)blockIdx.x;
    const int bh   = blockIdx.y;
    const int row0 = tidx * 128;
    const uint32_t* qhp = qh_g + (size_t)bh * L_ * 32;
    const uint32_t* qlp = ql_g + (size_t)bh * L_ * 32;
    const uint32_t* khp = kh_g + (size_t)bh * L_ * 32;
    const uint32_t* klp = kl_g + (size_t)bh * L_ * 32;
    const uint32_t* vhp = vth_g + (size_t)bh * HD_ * (L_ / 2);
    const uint32_t* vlp = vtl_g + (size_t)bh * HD_ * (L_ / 2);

    const int tid = threadIdx.x;
    const int wid = tid >> 5;
    const int lane = tid & 31;
    const int g = lane >> 2;
    const int t = lane & 3;
    const int wrow = wid * 16;

    const uint32_t laneA = (uint32_t)(((lane & 15) * ATST + (lane >> 4) * 4) * 4);
    const uint32_t laneB = (uint32_t)((((lane & 7) + (lane >> 4) * 8) * ATST
                                      + ((lane >> 3) & 1) * 4) * 4);

    auto load_kv = [&](int c0, int b) {
        const uint32_t kH = sb + (uint32_t)(ABUF0 + b * ABUFW) * 4;
        const uint32_t kL = kH + AKV_TILE * 4;
        const uint32_t vH = kL + AKV_TILE * 4;
        const uint32_t vL = vH + AKV_TILE * 4;
#pragma unroll
        for (int i = 0; i < 2; i++) {
            const int idx = tid + i * 256;
            const int r = idx >> 3, c4 = (idx & 7) * 4;
            const uint32_t so = (uint32_t)(r * ATST + c4) * 4;
            cp_async16(kH + so, khp + (size_t)(c0 + r) * 32 + c4);
            cp_async16(kL + so, klp + (size_t)(c0 + r) * 32 + c4);
        }
#pragma unroll
        for (int i = 0; i < 2; i++) {
            const int idx = tid + i * 256;
            const int r = idx >> 3, c4 = (idx & 7) * 4;
            const uint32_t so = (uint32_t)(r * ATST + c4) * 4;
            cp_async16(vH + so, vhp + (size_t)r * (L_ / 2) + c0 / 2 + c4);
            cp_async16(vL + so, vlp + (size_t)r * (L_ / 2) + c0 / 2 + c4);
        }
        cp_commit();
    };
    load_kv(0, 0);

    uint32_t* Qh = smu;
    uint32_t* Ql = smu + AQ_WORDS;
#pragma unroll
    for (int i = 0; i < 2; i++) {
        const int idx = tid + i * 256;
        const int r = idx >> 2, c4 = (idx & 3) * 8;
        *reinterpret_cast<uint4*>(&Qh[r * ATST + c4]) =
            *reinterpret_cast<const uint4*>(qhp + (size_t)(row0 + r) * 32 + c4);
        *reinterpret_cast<uint4*>(&Qh[r * ATST + c4 + 4]) =
            *reinterpret_cast<const uint4*>(qhp + (size_t)(row0 + r) * 32 + c4 + 4);
        *reinterpret_cast<uint4*>(&Ql[r * ATST + c4]) =
            *reinterpret_cast<const uint4*>(qlp + (size_t)(row0 + r) * 32 + c4);
        *reinterpret_cast<uint4*>(&Ql[r * ATST + c4 + 4]) =
            *reinterpret_cast<const uint4*>(qlp + (size_t)(row0 + r) * 32 + c4 + 4);
    }
    const uint32_t QhA = sb;
    const uint32_t QlA = sb + AQ_WORDS * 4;

    float accO[8][4];
    float m_i[2] = { -1e30f, -1e30f };
    float l_i[2] = { 0.f, 0.f };
#pragma unroll
    for (int nt = 0; nt < 8; nt++)
#pragma unroll
        for (int e = 0; e < 4; e++) accO[nt][e] = 0.f;

    const int jmax = 2 * tidx + 1;
    for (int j0 = 0; j0 <= jmax; j0++) {
        const int c0 = j0 * 64;
        const int b = j0 & 1;

        cp_wait<0>();
        __syncthreads();

        if (j0 < jmax) load_kv(c0 + 64, b ^ 1);

        const uint32_t KH = sb + (uint32_t)(ABUF0 + b * ABUFW) * 4;
        const uint32_t KL = KH + AKV_TILE * 4;
        const uint32_t VH = KL + AKV_TILE * 4;
        const uint32_t VL = VH + AKV_TILE * 4;

        // ---- S = Q @ K^T ----
        float s[8][4];
#pragma unroll
        for (int nt = 0; nt < 8; nt++)
#pragma unroll
            for (int e = 0; e < 4; e++) s[nt][e] = 0.f;

#pragma unroll
        for (int k16 = 0; k16 < 4; k16++) {
            const uint32_t kboff = (uint32_t)(k16 * 32);
            uint32_t ah[4], al[4], bh2[8][2], bl2[8][2];
            const uint32_t qbase = (uint32_t)(wrow * ATST * 4) + kboff + laneA;
            LDSM_X4(ah[0], ah[1], ah[2], ah[3], QhA + qbase);
            LDSM_X4(al[0], al[1], al[2], al[3], QlA + qbase);
#pragma unroll
            for (int nt2 = 0; nt2 < 4; nt2++) {
                const uint32_t base = (uint32_t)(nt2 * 16 * ATST * 4) + kboff + laneB;
                LDSM_X4(bh2[2 * nt2][0], bh2[2 * nt2][1],
                        bh2[2 * nt2 + 1][0], bh2[2 * nt2 + 1][1], KH + base);
                LDSM_X4(bl2[2 * nt2][0], bl2[2 * nt2][1],
                        bl2[2 * nt2 + 1][0], bl2[2 * nt2 + 1][1], KL + base);
            }
#pragma unroll
            for (int nt = 0; nt < 8; nt++) MMA_BF16(s[nt], al, bh2[nt]);
#pragma unroll
            for (int nt = 0; nt < 8; nt++) MMA_BF16(s[nt], ah, bl2[nt]);
#pragma unroll
            for (int nt = 0; nt < 8; nt++) MMA_BF16(s[nt], ah, bh2[nt]);
        }

        // ---- scale + causal mask ----
        const bool dm = (c0 + 63 > row0);
        const int r0 = row0 + wrow + g;
        const int r1 = r0 + 8;
#pragma unroll
        for (int nt = 0; nt < 8; nt++) {
#pragma unroll
            for (int e = 0; e < 4; e++) {
                const int col = c0 + nt * 8 + 2 * t + (e & 1);
                const int row = (e < 2) ? r0 : r1;
                s[nt][e] *= SCALE_;
                if (dm && col > row) s[nt][e] = -1e30f;
            }
        }

        // ---- online softmax ----
        float mx0 = -1e30f, mx1 = -1e30f;
#pragma unroll
        for (int nt = 0; nt < 8; nt++) {
            mx0 = fmaxf(mx0, fmaxf(s[nt][0], s[nt][1]));
            mx1 = fmaxf(mx1, fmaxf(s[nt][2], s[nt][3]));
        }
#pragma unroll
        for (int off = 1; off <= 2; off <<= 1) {
            mx0 = fmaxf(mx0, __shfl_xor_sync(0xffffffffu, mx0, off));
            mx1 = fmaxf(mx1, __shfl_xor_sync(0xffffffffu, mx1, off));
        }
        const float mn0 = fmaxf(m_i[0], mx0);
        const float mn1 = fmaxf(m_i[1], mx1);
        const float corr0 = __expf(m_i[0] - mn0);
        const float corr1 = __expf(m_i[1] - mn1);
        m_i[0] = mn0; m_i[1] = mn1;

        float ls0 = 0.f, ls1 = 0.f;
#pragma unroll
        for (int nt = 0; nt < 8; nt++) {
            s[nt][0] = __expf(s[nt][0] - mn0);
            s[nt][1] = __expf(s[nt][1] - mn0);
            s[nt][2] = __expf(s[nt][2] - mn1);
            s[nt][3] = __expf(s[nt][3] - mn1);
            ls0 += s[nt][0] + s[nt][1];
            ls1 += s[nt][2] + s[nt][3];
        }
#pragma unroll
        for (int off = 1; off <= 2; off <<= 1) {
            ls0 += __shfl_xor_sync(0xffffffffu, ls0, off);
            ls1 += __shfl_xor_sync(0xffffffffu, ls1, off);
        }
        l_i[0] = l_i[0] * corr0 + ls0;
        l_i[1] = l_i[1] * corr1 + ls1;
#pragma unroll
        for (int nt = 0; nt < 8; nt++) {
            accO[nt][0] *= corr0; accO[nt][1] *= corr0;
            accO[nt][2] *= corr1; accO[nt][3] *= corr1;
        }

        // ---- pack P from registers ----
        uint32_t phw[8][2], plw[8][2];
#pragma unroll
        for (int nt = 0; nt < 8; nt++) {
            bf16x2_split(s[nt][0], s[nt][1], phw[nt][0], plw[nt][0]);
            bf16x2_split(s[nt][2], s[nt][3], phw[nt][1], plw[nt][1]);
        }

        // ---- O += P @ V ----
#pragma unroll
        for (int ks = 0; ks < 4; ks++) {
            const uint32_t kboff = (uint32_t)(ks * 32);
            uint32_t pah[4] = { phw[2 * ks][0], phw[2 * ks][1],
                                phw[2 * ks + 1][0], phw[2 * ks + 1][1] };
            uint32_t pal[4] = { plw[2 * ks][0], plw[2 * ks][1],
                                plw[2 * ks + 1][0], plw[2 * ks + 1][1] };
            uint32_t vh[8][2], vl[8][2];
#pragma unroll
            for (int nt2 = 0; nt2 < 4; nt2++) {
                const uint32_t base = (uint32_t)(nt2 * 16 * ATST * 4) + kboff + laneB;
                LDSM_X4(vh[2 * nt2][0], vh[2 * nt2][1],
                        vh[2 * nt2 + 1][0], vh[2 * nt2 + 1][1], VH + base);
                LDSM_X4(vl[2 * nt2][0], vl[2 * nt2][1],
                        vl[2 * nt2 + 1][0], vl[2 * nt2 + 1][1], VL + base);
            }
#pragma unroll
            for (int nt = 0; nt < 8; nt++) MMA_BF16(accO[nt], pal, vh[nt]);
#pragma unroll
            for (int nt = 0; nt < 8; nt++) MMA_BF16(accO[nt], pah, vl[nt]);
#pragma unroll
            for (int nt = 0; nt < 8; nt++) MMA_BF16(accO[nt], pah, vh[nt]);
        }
    }

    // ---- finalize ----
    const int bb = bh >> 4;
    const int h  = bh & (H_ - 1);
    const float inv0 = 1.0f / l_i[0];
    const float inv1 = 1.0f / l_i[1];
    const int r0 = row0 + wrow + g;
#pragma unroll
    for (int nt = 0; nt < 8; nt++) {
        const int widx = h * 32 + nt * 4 + t;
        uint32_t hw, lw;
        bf16x2_split(accO[nt][0] * inv0, accO[nt][1] * inv0, hw, lw);
        ah_g[((size_t)(bb * L_ + r0)) * 512 + widx] = hw;
        al_g[((size_t)(bb * L_ + r0)) * 512 + widx] = lw;
        bf16x2_split(accO[nt][2] * inv1, accO[nt][3] * inv1, hw, lw);
        ah_g[((size_t)(bb * L_ + r0 + 8)) * 512 + widx] = hw;
        al_g[((size_t)(bb * L_ + r0 + 8)) * 512 + widx] = lw;
    }
}

// ---------------------------------------------------------------------------
extern "C" void kernel_launch(void* const* d_in, const int* in_sizes, int n_in,
                              void* d_out, int out_size)
{
    const float* x     = (const float*)d_in[0];
    const float* w_qkv = (const float*)d_in[1];
    const float* b_qkv = (const float*)d_in[2];
    const float* w_out = (const float*)d_in[3];
    const float* b_out = (const float*)d_in[4];

    float* out  = (float*)d_out;
    float* kout = out  + (size_t)B_ * L_ * D_;
    float* vout = kout + NQKV;

    uint32_t *xh, *xl, *wqh, *wql, *woh, *wol;
    uint32_t *qh, *ql, *kh, *kl, *vth, *vtl, *ah, *al;
    cudaGetSymbolAddress((void**)&xh, g_xh);
    cudaGetSymbolAddress((void**)&xl, g_xl);
    cudaGetSymbolAddress((void**)&wqh, g_wqh);
    cudaGetSymbolAddress((void**)&wql, g_wql);
    cudaGetSymbolAddress((void**)&woh, g_woh);
    cudaGetSymbolAddress((void**)&wol, g_wol);
    cudaGetSymbolAddress((void**)&qh, g_qh);
    cudaGetSymbolAddress((void**)&ql, g_ql);
    cudaGetSymbolAddress((void**)&kh, g_kh);
    cudaGetSymbolAddress((void**)&kl, g_kl);
    cudaGetSymbolAddress((void**)&vth, g_vth);
    cudaGetSymbolAddress((void**)&vtl, g_vtl);
    cudaGetSymbolAddress((void**)&ah, g_ah);
    cudaGetSymbolAddress((void**)&al, g_al);

    cudaFuncSetAttribute(gemm_bf16<3 * D_, 1>,
                         cudaFuncAttributeMaxDynamicSharedMemorySize, GEMM_SMEM);
    cudaFuncSetAttribute(gemm_bf16<D_, 0>,
                         cudaFuncAttributeMaxDynamicSharedMemorySize, GEMM_SMEM);
    cudaFuncSetAttribute(attn_bf16,
                         cudaFuncAttributeMaxDynamicSharedMemorySize, ATTN_SMEM);

    // 0) Prep
    pack_rows<<<(int)(NX / 4 + 255) / 256, 256>>>(
        (const float4*)x, xh, xl, (int)(NX / 4));
    transpose_pack<<<dim3(3 * D_ / 64, D_ / 64), 256>>>(w_qkv, wqh, wql, D_, 3 * D_);
    transpose_pack<<<dim3(D_ / 64, D_ / 64), 256>>>(w_out, woh, wol, D_, D_);

    // 1) QKV projection (V^T pack fused into epilogue)
    gemm_bf16<3 * D_, 1><<<dim3(24, 32), 256, GEMM_SMEM>>>(
        xh, xl, wqh, wql, b_qkv, nullptr, qh, ql, kh, kl, vth, vtl, kout, vout);

    // 2) Causal flash attention
    attn_bf16<<<dim3(L_ / 128, B_ * H_), 256, ATTN_SMEM>>>(
        qh, ql, kh, kl, vth, vtl, ah, al);

    // 3) Output projection (14 args: 8 trailing output ptrs unused)
    gemm_bf16<D_, 0><<<dim3(8, 32), 256, GEMM_SMEM>>>(
        ah, al, woh, wol, b_out, out,
        nullptr, nullptr, nullptr, nullptr, nullptr, nullptr, nullptr, nullptr);
}

// round 13
// speedup vs baseline: 1.9866x; 1.0036x over previous
#include <cuda_runtime.h>
#include <cstdint>
#include <math.h>

#define B_  2
#define L_  2048
#define D_  1024
#define H_  16
#define HD_ 64
#define SCALE_ 0.125f

#define NQKV ((size_t)B_ * H_ * L_ * HD_)
#define NX   ((size_t)B_ * L_ * D_)
#define NWQ  ((size_t)D_ * 3 * D_)
#define NWO  ((size_t)D_ * D_)
#define PKW  (D_ / 2)

// Packed bf16x2 hi/lo planes (allocation-free scratch)
__device__ uint32_t g_xh[NX / 2],   g_xl[NX / 2];
__device__ uint32_t g_wqh[NWQ / 2], g_wql[NWQ / 2];
__device__ uint32_t g_woh[NWO / 2], g_wol[NWO / 2];
__device__ uint32_t g_qh[NQKV / 2], g_ql[NQKV / 2];
__device__ uint32_t g_kh[NQKV / 2], g_kl[NQKV / 2];
__device__ uint32_t g_vth[NQKV / 2], g_vtl[NQKV / 2];  // v^T [bh][64][L/2]
__device__ uint32_t g_ah[NX / 2],   g_al[NX / 2];

// ===========================================================================
// Helpers
// ===========================================================================
__device__ __forceinline__ void cp_async16(uint32_t dst, const void* src) {
    asm volatile("cp.async.cg.shared.global [%0], [%1], 16;"
                 :: "r"(dst), "l"(src) : "memory");
}
__device__ __forceinline__ void cp_commit() {
    asm volatile("cp.async.commit_group;" ::: "memory");
}
template<int N>
__device__ __forceinline__ void cp_wait() {
    asm volatile("cp.async.wait_group %0;" :: "n"(N) : "memory");
}
__device__ __forceinline__ uint32_t smem_u32(const void* p) {
    uint32_t a;
    asm("{ .reg .u64 t; cvta.to.shared.u64 t, %1; cvt.u32.u64 %0, t; }"
        : "=r"(a) : "l"(p));
    return a;
}
__device__ __forceinline__ uint32_t pack_bf16(float e0, float e1) {
    uint32_t d;
    asm("cvt.rn.bf16x2.f32 %0, %1, %2;" : "=r"(d) : "f"(e1), "f"(e0));
    return d;
}
__device__ __forceinline__ void bf16x2_split(float x0, float x1,
                                             uint32_t& hw, uint32_t& lw) {
    hw = pack_bf16(x0, x1);
    const float h0 = __uint_as_float(hw << 16);
    const float h1 = __uint_as_float(hw & 0xffff0000u);
    lw = pack_bf16(x0 - h0, x1 - h1);
}
#define MMA_BF16(c, a, b)                                                      \
    asm("mma.sync.aligned.m16n8k16.row.col.f32.bf16.bf16.f32 "                 \
        "{%0,%1,%2,%3}, {%4,%5,%6,%7}, {%8,%9}, {%0,%1,%2,%3};"                \
        : "+f"((c)[0]), "+f"((c)[1]), "+f"((c)[2]), "+f"((c)[3])               \
        : "r"((a)[0]), "r"((a)[1]), "r"((a)[2]), "r"((a)[3]),                  \
          "r"((b)[0]), "r"((b)[1]))
#define LDSM_X4(r0, r1, r2, r3, addr)                                          \
    asm volatile("ldmatrix.sync.aligned.m8n8.x4.shared.b16 {%0,%1,%2,%3}, [%4];" \
        : "=r"(r0), "=r"(r1), "=r"(r2), "=r"(r3) : "r"(addr))

// ===========================================================================
// Combined prep kernel: one launch does x-pack + both weight transposes.
//   blocks [0, XB)            : pack x rows
//   blocks [XB, XB+WQB)       : transpose-pack w_qkv (48 x 16 tiles)
//   blocks [XB+WQB, +WOB)     : transpose-pack w_out (16 x 16 tiles)
// ===========================================================================
#define XB  ((int)(NX / 4 / 256))     // 4096
#define WQB ((3 * D_ / 64) * (D_ / 64))  // 768
#define WOB ((D_ / 64) * (D_ / 64))      // 256

__device__ __forceinline__ void transpose_tile(
    const float* __restrict__ src, uint32_t* __restrict__ dhi,
    uint32_t* __restrict__ dlo, int K, int N, int n0, int k0, int tid,
    float (*tsm)[65])
{
#pragma unroll
    for (int i = 0; i < 4; i++) {
        const int idx = tid + i * 256;
        const int kk = idx >> 4, n4 = (idx & 15) * 4;
        const float4 v = *reinterpret_cast<const float4*>(
            src + (size_t)(k0 + kk) * N + n0 + n4);
        tsm[kk][n4] = v.x; tsm[kk][n4 + 1] = v.y;
        tsm[kk][n4 + 2] = v.z; tsm[kk][n4 + 3] = v.w;
    }
    __syncthreads();
    const int kw = K / 2;
#pragma unroll
    for (int i = 0; i < 8; i++) {
        const int idx = tid + i * 256;
        const int nn = idx >> 5, k2 = idx & 31;
        uint32_t hw, lw;
        bf16x2_split(tsm[2 * k2][nn], tsm[2 * k2 + 1][nn], hw, lw);
        const size_t off = (size_t)(n0 + nn) * kw + k0 / 2 + k2;
        dhi[off] = hw;
        dlo[off] = lw;
    }
}

__global__ __launch_bounds__(256)
void prep_all(const float* __restrict__ x,
              const float* __restrict__ w_qkv,
              const float* __restrict__ w_out,
              uint32_t* __restrict__ xh, uint32_t* __restrict__ xl,
              uint32_t* __restrict__ wqh, uint32_t* __restrict__ wql,
              uint32_t* __restrict__ woh, uint32_t* __restrict__ wol)
{
    __shared__ float tsm[64][65];
    const int bid = blockIdx.x;
    const int tid = threadIdx.x;
    if (bid < XB) {
        const int i = bid * 256 + tid;
        const float4 v = reinterpret_cast<const float4*>(x)[i];
        uint32_t h0, l0, h1, l1;
        bf16x2_split(v.x, v.y, h0, l0);
        bf16x2_split(v.z, v.w, h1, l1);
        xh[2 * i] = h0; xh[2 * i + 1] = h1;
        xl[2 * i] = l0; xl[2 * i + 1] = l1;
    } else if (bid < XB + WQB) {
        const int b = bid - XB;
        const int n0 = (b % (3 * D_ / 64)) * 64;
        const int k0 = (b / (3 * D_ / 64)) * 64;
        transpose_tile(w_qkv, wqh, wql, D_, 3 * D_, n0, k0, tid, tsm);
    } else {
        const int b = bid - XB - WQB;
        const int n0 = (b % (D_ / 64)) * 64;
        const int k0 = (b / (D_ / 64)) * 64;
        transpose_tile(w_out, woh, wol, D_, D_, n0, k0, tid, tsm);
    }
}

// ===========================================================================
// bf16x3 GEMM (CTA 128x128, K-slab 32, 256 thr / 8 warps 2x4, 2 CTAs/SM).
// Fragment loads via ldmatrix.x4. QKV epilogue also emits V^T planes (fused).
// ===========================================================================
#define GST 20
#define G_TF (128 * GST)
#define G_BUFW (4 * G_TF)
#define GEMM_SMEM (2 * G_BUFW * 4)               // 81920 B

template<int NCOLS, int QKV>
__global__ __launch_bounds__(256, 2)
void gemm_bf16(const uint32_t* __restrict__ Ahi, const uint32_t* __restrict__ Alo,
               const uint32_t* __restrict__ Whi, const uint32_t* __restrict__ Wlo,
               const float* __restrict__ bias,
               float* __restrict__ outF,
               uint32_t* __restrict__ qh, uint32_t* __restrict__ ql,
               uint32_t* __restrict__ kh, uint32_t* __restrict__ kl,
               uint32_t* __restrict__ vth, uint32_t* __restrict__ vtl,
               float* __restrict__ kraw, float* __restrict__ vraw)
{
    extern __shared__ uint32_t smu[];
    const uint32_t sb = smem_u32(smu);

    const int tid  = threadIdx.x;
    const int wid  = tid >> 5;
    const int lane = tid & 31;
    const int g = lane >> 2;
    const int t = lane & 3;
    const int wm0 = (wid >> 2) * 64;
    const int wn0 = (wid & 3) * 32;
    const int m0 = blockIdx.y * 128;
    const int n0 = blockIdx.x * 128;

    const uint32_t laneA = (uint32_t)(((lane & 15) * GST + (lane >> 4) * 4) * 4);
    const uint32_t laneB = (uint32_t)((((lane & 7) + (lane >> 4) * 8) * GST
                                      + ((lane >> 3) & 1) * 4) * 4);

    float acc[4][4][4];
#pragma unroll
    for (int mt = 0; mt < 4; mt++)
#pragma unroll
        for (int nt = 0; nt < 4; nt++)
#pragma unroll
            for (int r = 0; r < 4; r++) acc[mt][nt][r] = 0.f;

    auto load_stage = [&](int s, int b) {
        const int kw0 = s * 16;
        const uint32_t aH = sb + (uint32_t)(b * G_BUFW) * 4;
        const uint32_t aL = aH + G_TF * 4;
        const uint32_t bH = aL + G_TF * 4;
        const uint32_t bL = bH + G_TF * 4;
#pragma unroll
        for (int i = 0; i < 2; i++) {
            const int idx = tid + i * 256;
            const int r = idx >> 2, c4 = (idx & 3) * 4;
            const size_t go = (size_t)(m0 + r) * PKW + kw0 + c4;
            const uint32_t so = (uint32_t)(r * GST + c4) * 4;
            cp_async16(aH + so, Ahi + go);
            cp_async16(aL + so, Alo + go);
        }
#pragma unroll
        for (int i = 0; i < 2; i++) {
            const int idx = tid + i * 256;
            const int r = idx >> 2, c4 = (idx & 3) * 4;
            const size_t go = (size_t)(n0 + r) * PKW + kw0 + c4;
            const uint32_t so = (uint32_t)(r * GST + c4) * 4;
            cp_async16(bH + so, Whi + go);
            cp_async16(bL + so, Wlo + go);
        }
        cp_commit();
    };

    auto compute_stage = [&](int b) {
        const uint32_t aH = sb + (uint32_t)(b * G_BUFW) * 4;
        const uint32_t aL = aH + G_TF * 4;
        const uint32_t bHa = aL + G_TF * 4;
        const uint32_t bLa = bHa + G_TF * 4;
#pragma unroll
        for (int k16 = 0; k16 < 2; k16++) {
            const uint32_t kboff = (uint32_t)(k16 * 32);
            uint32_t ah[4][4], al[4][4], bh[4][2], bl[4][2];
#pragma unroll
            for (int mt = 0; mt < 4; mt++) {
                const uint32_t base = (uint32_t)((wm0 + mt * 16) * GST * 4) + kboff + laneA;
                LDSM_X4(ah[mt][0], ah[mt][1], ah[mt][2], ah[mt][3], aH + base);
                LDSM_X4(al[mt][0], al[mt][1], al[mt][2], al[mt][3], aL + base);
            }
#pragma unroll
            for (int nt2 = 0; nt2 < 2; nt2++) {
                const uint32_t base = (uint32_t)((wn0 + nt2 * 16) * GST * 4) + kboff + laneB;
                LDSM_X4(bh[2 * nt2][0], bh[2 * nt2][1],
                        bh[2 * nt2 + 1][0], bh[2 * nt2 + 1][1], bHa + base);
                LDSM_X4(bl[2 * nt2][0], bl[2 * nt2][1],
                        bl[2 * nt2 + 1][0], bl[2 * nt2 + 1][1], bLa + base);
            }
#pragma unroll
            for (int mt = 0; mt < 4; mt++)
#pragma unroll
                for (int nt = 0; nt < 4; nt++)
                    MMA_BF16(acc[mt][nt], al[mt], bh[nt]);
#pragma unroll
            for (int mt = 0; mt < 4; mt++)
#pragma unroll
                for (int nt = 0; nt < 4; nt++)
                    MMA_BF16(acc[mt][nt], ah[mt], bl[nt]);
#pragma unroll
            for (int mt = 0; mt < 4; mt++)
#pragma unroll
                for (int nt = 0; nt < 4; nt++)
                    MMA_BF16(acc[mt][nt], ah[mt], bh[nt]);
        }
    };

    load_stage(0, 0);
    constexpr int NS = D_ / 32;
    for (int s = 0; s < NS; s++) {
        const int b = s & 1;
        if (s + 1 < NS) {
            load_stage(s + 1, b ^ 1);
            cp_wait<1>();
        } else {
            cp_wait<0>();
        }
        __syncthreads();
        compute_stage(b);
        __syncthreads();
    }

    // epilogue
#pragma unroll
    for (int mt = 0; mt < 4; mt++) {
#pragma unroll
        for (int half = 0; half < 2; half++) {
            const int m = m0 + wm0 + mt * 16 + g + half * 8;
            int bb = 0, l = 0;
            if (QKV) { bb = m >> 11; l = m & (L_ - 1); }
#pragma unroll
            for (int nt = 0; nt < 4; nt++) {
                const int n = n0 + wn0 + nt * 8 + t * 2;
                float2 v;
                v.x = acc[mt][nt][half * 2 + 0] + bias[n];
                v.y = acc[mt][nt][half * 2 + 1] + bias[n + 1];
                if (QKV) {
                    const int sidx = n0 >> 10;
                    const int h = (n >> 6) & (H_ - 1), dd = n & (HD_ - 1);
                    const size_t row = (size_t)(bb * H_ + h) * L_ + l;
                    const size_t woff = row * 32 + (dd >> 1);
                    if (sidx == 0) {
                        uint32_t hw, lw;
                        bf16x2_split(v.x, v.y, hw, lw);
                        qh[woff] = hw; ql[woff] = lw;
                    } else if (sidx == 1) {
                        uint32_t hw, lw;
                        bf16x2_split(v.x, v.y, hw, lw);
                        kh[woff] = hw; kl[woff] = lw;
                        *reinterpret_cast<float2*>(kraw + row * HD_ + dd) = v;
                    } else {
                        *reinterpret_cast<float2*>(vraw + row * HD_ + dd) = v;
                        const float vxn = __shfl_down_sync(0xffffffffu, v.x, 4);
                        const float vyn = __shfl_down_sync(0xffffffffu, v.y, 4);
                        if ((g & 1) == 0) {
                            const size_t vb = (size_t)(bb * H_ + h) * HD_ * (L_ / 2);
                            const size_t l2 = (size_t)(l >> 1);
                            uint32_t hw, lw;
                            bf16x2_split(v.x, vxn, hw, lw);
                            vth[vb + (size_t)dd * (L_ / 2) + l2] = hw;
                            vtl[vb + (size_t)dd * (L_ / 2) + l2] = lw;
                            bf16x2_split(v.y, vyn, hw, lw);
                            vth[vb + (size_t)(dd + 1) * (L_ / 2) + l2] = hw;
                            vtl[vb + (size_t)(dd + 1) * (L_ / 2) + l2] = lw;
                        }
                    }
                } else {
                    *reinterpret_cast<float2*>(outF + (size_t)m * NCOLS + n) = v;
                }
            }
        }
    }
}

// ===========================================================================
// Flash attention (causal), bf16x3 m16n8k16, ldmatrix loads, 2 CTAs/SM.
// ===========================================================================
#define ATST 36
#define AQ_WORDS (128 * ATST)
#define ABUF0 (2 * AQ_WORDS)
#define AKV_TILE (64 * ATST)
#define ABUFW (4 * AKV_TILE)
#define ATTN_WORDS (ABUF0 + 2 * ABUFW)
#define ATTN_SMEM (ATTN_WORDS * 4)               // 110592 B (2/SM = 216 KB)

__global__ __launch_bounds__(256, 2)
void attn_bf16(const uint32_t* __restrict__ qh_g, const uint32_t* __restrict__ ql_g,
               const uint32_t* __restrict__ kh_g, const uint32_t* __restrict__ kl_g,
               const uint32_t* __restrict__ vth_g, const uint32_t* __restrict__ vtl_g,
               uint32_t* __restrict__ ah_g, uint32_t* __restrict__ al_g)
{
    extern __shared__ uint32_t smu[];
    const uint32_t sb = smem_u32(smu);

    const int tidx = (int)gridDim.x - 1 - (int)blockIdx.x;
    const int bh   = blockIdx.y;
    const int row0 = tidx * 128;
    const uint32_t* qhp = qh_g + (size_t)bh * L_ * 32;
    const uint32_t* qlp = ql_g + (size_t)bh * L_ * 32;
    const uint32_t* khp = kh_g + (size_t)bh * L_ * 32;
    const uint32_t* klp = kl_g + (size_t)bh * L_ * 32;
    const uint32_t* vhp = vth_g + (size_t)bh * HD_ * (L_ / 2);
    const uint32_t* vlp = vtl_g + (size_t)bh * HD_ * (L_ / 2);

    const int tid = threadIdx.x;
    const int wid = tid >> 5;
    const int lane = tid & 31;
    const int g = lane >> 2;
    const int t = lane & 3;
    const int wrow = wid * 16;

    const uint32_t laneA = (uint32_t)(((lane & 15) * ATST + (lane >> 4) * 4) * 4);
    const uint32_t laneB = (uint32_t)((((lane & 7) + (lane >> 4) * 8) * ATST
                                      + ((lane >> 3) & 1) * 4) * 4);

    auto load_kv = [&](int c0, int b) {
        const uint32_t kH = sb + (uint32_t)(ABUF0 + b * ABUFW) * 4;
        const uint32_t kL = kH + AKV_TILE * 4;
        const uint32_t vH = kL + AKV_TILE * 4;
        const uint32_t vL = vH + AKV_TILE * 4;
#pragma unroll
        for (int i = 0; i < 2; i++) {
            const int idx = tid + i * 256;
            const int r = idx >> 3, c4 = (idx & 7) * 4;
            const uint32_t so = (uint32_t)(r * ATST + c4) * 4;
            cp_async16(kH + so, khp + (size_t)(c0 + r) * 32 + c4);
            cp_async16(kL + so, klp + (size_t)(c0 + r) * 32 + c4);
        }
#pragma unroll
        for (int i = 0; i < 2; i++) {
            const int idx = tid + i * 256;
            const int r = idx >> 3, c4 = (idx & 7) * 4;
            const uint32_t so = (uint32_t)(r * ATST + c4) * 4;
            cp_async16(vH + so, vhp + (size_t)r * (L_ / 2) + c0 / 2 + c4);
            cp_async16(vL + so, vlp + (size_t)r * (L_ / 2) + c0 / 2 + c4);
        }
        cp_commit();
    };
    load_kv(0, 0);

    uint32_t* Qh = smu;
    uint32_t* Ql = smu + AQ_WORDS;
#pragma unroll
    for (int i = 0; i < 2; i++) {
        const int idx = tid + i * 256;
        const int r = idx >> 2, c4 = (idx & 3) * 8;
        *reinterpret_cast<uint4*>(&Qh[r * ATST + c4]) =
            *reinterpret_cast<const uint4*>(qhp + (size_t)(row0 + r) * 32 + c4);
        *reinterpret_cast<uint4*>(&Qh[r * ATST + c4 + 4]) =
            *reinterpret_cast<const uint4*>(qhp + (size_t)(row0 + r) * 32 + c4 + 4);
        *reinterpret_cast<uint4*>(&Ql[r * ATST + c4]) =
            *reinterpret_cast<const uint4*>(qlp + (size_t)(row0 + r) * 32 + c4);
        *reinterpret_cast<uint4*>(&Ql[r * ATST + c4 + 4]) =
            *reinterpret_cast<const uint4*>(qlp + (size_t)(row0 + r) * 32 + c4 + 4);
    }
    const uint32_t QhA = sb;
    const uint32_t QlA = sb + AQ_WORDS * 4;

    float accO[8][4];
    float m_i[2] = { -1e30f, -1e30f };
    float l_i[2] = { 0.f, 0.f };
#pragma unroll
    for (int nt = 0; nt < 8; nt++)
#pragma unroll
        for (int e = 0; e < 4; e++) accO[nt][e] = 0.f;

    const int jmax = 2 * tidx + 1;
    for (int j0 = 0; j0 <= jmax; j0++) {
        const int c0 = j0 * 64;
        const int b = j0 & 1;

        cp_wait<0>();
        __syncthreads();

        if (j0 < jmax) load_kv(c0 + 64, b ^ 1);

        const uint32_t KH = sb + (uint32_t)(ABUF0 + b * ABUFW) * 4;
        const uint32_t KL = KH + AKV_TILE * 4;
        const uint32_t VH = KL + AKV_TILE * 4;
        const uint32_t VL = VH + AKV_TILE * 4;

        // ---- S = Q @ K^T ----
        float s[8][4];
#pragma unroll
        for (int nt = 0; nt < 8; nt++)
#pragma unroll
            for (int e = 0; e < 4; e++) s[nt][e] = 0.f;

#pragma unroll
        for (int k16 = 0; k16 < 4; k16++) {
            const uint32_t kboff = (uint32_t)(k16 * 32);
            uint32_t ah[4], al[4], bh2[8][2], bl2[8][2];
            const uint32_t qbase = (uint32_t)(wrow * ATST * 4) + kboff + laneA;
            LDSM_X4(ah[0], ah[1], ah[2], ah[3], QhA + qbase);
            LDSM_X4(al[0], al[1], al[2], al[3], QlA + qbase);
#pragma unroll
            for (int nt2 = 0; nt2 < 4; nt2++) {
                const uint32_t base = (uint32_t)(nt2 * 16 * ATST * 4) + kboff + laneB;
                LDSM_X4(bh2[2 * nt2][0], bh2[2 * nt2][1],
                        bh2[2 * nt2 + 1][0], bh2[2 * nt2 + 1][1], KH + base);
                LDSM_X4(bl2[2 * nt2][0], bl2[2 * nt2][1],
                        bl2[2 * nt2 + 1][0], bl2[2 * nt2 + 1][1], KL + base);
            }
#pragma unroll
            for (int nt = 0; nt < 8; nt++) MMA_BF16(s[nt], al, bh2[nt]);
#pragma unroll
            for (int nt = 0; nt < 8; nt++) MMA_BF16(s[nt], ah, bl2[nt]);
#pragma unroll
            for (int nt = 0; nt < 8; nt++) MMA_BF16(s[nt], ah, bh2[nt]);
        }

        // ---- scale + causal mask ----
        const bool dm = (c0 + 63 > row0);
        const int r0 = row0 + wrow + g;
        const int r1 = r0 + 8;
#pragma unroll
        for (int nt = 0; nt < 8; nt++) {
#pragma unroll
            for (int e = 0; e < 4; e++) {
                const int col = c0 + nt * 8 + 2 * t + (e & 1);
                const int row = (e < 2) ? r0 : r1;
                s[nt][e] *= SCALE_;
                if (dm && col > row) s[nt][e] = -1e30f;
            }
        }

        // ---- online softmax ----
        float mx0 = -1e30f, mx1 = -1e30f;
#pragma unroll
        for (int nt = 0; nt < 8; nt++) {
            mx0 = fmaxf(mx0, fmaxf(s[nt][0], s[nt][1]));
            mx1 = fmaxf(mx1, fmaxf(s[nt][2], s[nt][3]));
        }
#pragma unroll
        for (int off = 1; off <= 2; off <<= 1) {
            mx0 = fmaxf(mx0, __shfl_xor_sync(0xffffffffu, mx0, off));
            mx1 = fmaxf(mx1, __shfl_xor_sync(0xffffffffu, mx1, off));
        }
        const float mn0 = fmaxf(m_i[0], mx0);
        const float mn1 = fmaxf(m_i[1], mx1);
        const float corr0 = __expf(m_i[0] - mn0);
        const float corr1 = __expf(m_i[1] - mn1);
        m_i[0] = mn0; m_i[1] = mn1;

        float ls0 = 0.f, ls1 = 0.f;
#pragma unroll
        for (int nt = 0; nt < 8; nt++) {
            s[nt][0] = __expf(s[nt][0] - mn0);
            s[nt][1] = __expf(s[nt][1] - mn0);
            s[nt][2] = __expf(s[nt][2] - mn1);
            s[nt][3] = __expf(s[nt][3] - mn1);
            ls0 += s[nt][0] + s[nt][1];
            ls1 += s[nt][2] + s[nt][3];
        }
#pragma unroll
        for (int off = 1; off <= 2; off <<= 1) {
            ls0 += __shfl_xor_sync(0xffffffffu, ls0, off);
            ls1 += __shfl_xor_sync(0xffffffffu, ls1, off);
        }
        l_i[0] = l_i[0] * corr0 + ls0;
        l_i[1] = l_i[1] * corr1 + ls1;
#pragma unroll
        for (int nt = 0; nt < 8; nt++) {
            accO[nt][0] *= corr0; accO[nt][1] *= corr0;
            accO[nt][2] *= corr1; accO[nt][3] *= corr1;
        }

        // ---- pack P from registers ----
        uint32_t phw[8][2], plw[8][2];
#pragma unroll
        for (int nt = 0; nt < 8; nt++) {
            bf16x2_split(s[nt][0], s[nt][1], phw[nt][0], plw[nt][0]);
            bf16x2_split(s[nt][2], s[nt][3], phw[nt][1], plw[nt][1]);
        }

        // ---- O += P @ V ----
#pragma unroll
        for (int ks = 0; ks < 4; ks++) {
            const uint32_t kboff = (uint32_t)(ks * 32);
            uint32_t pah[4] = { phw[2 * ks][0], phw[2 * ks][1],
                                phw[2 * ks + 1][0], phw[2 * ks + 1][1] };
            uint32_t pal[4] = { plw[2 * ks][0], plw[2 * ks][1],
                                plw[2 * ks + 1][0], plw[2 * ks + 1][1] };
            uint32_t vh[8][2], vl[8][2];
#pragma unroll
            for (int nt2 = 0; nt2 < 4; nt2++) {
                const uint32_t base = (uint32_t)(nt2 * 16 * ATST * 4) + kboff + laneB;
                LDSM_X4(vh[2 * nt2][0], vh[2 * nt2][1],
                        vh[2 * nt2 + 1][0], vh[2 * nt2 + 1][1], VH + base);
                LDSM_X4(vl[2 * nt2][0], vl[2 * nt2][1],
                        vl[2 * nt2 + 1][0], vl[2 * nt2 + 1][1], VL + base);
            }
#pragma unroll
            for (int nt = 0; nt < 8; nt++) MMA_BF16(accO[nt], pal, vh[nt]);
#pragma unroll
            for (int nt = 0; nt < 8; nt++) MMA_BF16(accO[nt], pah, vl[nt]);
#pragma unroll
            for (int nt = 0; nt < 8; nt++) MMA_BF16(accO[nt], pah, vh[nt]);
        }
    }

    // ---- finalize ----
    const int bb = bh >> 4;
    const int h  = bh & (H_ - 1);
    const float inv0 = 1.0f / l_i[0];
    const float inv1 = 1.0f / l_i[1];
    const int r0 = row0 + wrow + g;
#pragma unroll
    for (int nt = 0; nt < 8; nt++) {
        const int widx = h * 32 + nt * 4 + t;
        uint32_t hw, lw;
        bf16x2_split(accO[nt][0] * inv0, accO[nt][1] * inv0, hw, lw);
        ah_g[((size_t)(bb * L_ + r0)) * 512 + widx] = hw;
        al_g[((size_t)(bb * L_ + r0)) * 512 + widx] = lw;
        bf16x2_split(accO[nt][2] * inv1, accO[nt][3] * inv1, hw, lw);
        ah_g[((size_t)(bb * L_ + r0 + 8)) * 512 + widx] = hw;
        al_g[((size_t)(bb * L_ + r0 + 8)) * 512 + widx] = lw;
    }
}

// ---------------------------------------------------------------------------
extern "C" void kernel_launch(void* const* d_in, const int* in_sizes, int n_in,
                              void* d_out, int out_size)
{
    const float* x     = (const float*)d_in[0];
    const float* w_qkv = (const float*)d_in[1];
    const float* b_qkv = (const float*)d_in[2];
    const float* w_out = (const float*)d_in[3];
    const float* b_out = (const float*)d_in[4];

    float* out  = (float*)d_out;
    float* kout = out  + (size_t)B_ * L_ * D_;
    float* vout = kout + NQKV;

    uint32_t *xh, *xl, *wqh, *wql, *woh, *wol;
    uint32_t *qh, *ql, *kh, *kl, *vth, *vtl, *ah, *al;
    cudaGetSymbolAddress((void**)&xh, g_xh);
    cudaGetSymbolAddress((void**)&xl, g_xl);
    cudaGetSymbolAddress((void**)&wqh, g_wqh);
    cudaGetSymbolAddress((void**)&wql, g_wql);
    cudaGetSymbolAddress((void**)&woh, g_woh);
    cudaGetSymbolAddress((void**)&wol, g_wol);
    cudaGetSymbolAddress((void**)&qh, g_qh);
    cudaGetSymbolAddress((void**)&ql, g_ql);
    cudaGetSymbolAddress((void**)&kh, g_kh);
    cudaGetSymbolAddress((void**)&kl, g_kl);
    cudaGetSymbolAddress((void**)&vth, g_vth);
    cudaGetSymbolAddress((void**)&vtl, g_vtl);
    cudaGetSymbolAddress((void**)&ah, g_ah);
    cudaGetSymbolAddress((void**)&al, g_al);

    cudaFuncSetAttribute(gemm_bf16<3 * D_, 1>,
                         cudaFuncAttributeMaxDynamicSharedMemorySize, GEMM_SMEM);
    cudaFuncSetAttribute(gemm_bf16<D_, 0>,
                         cudaFuncAttributeMaxDynamicSharedMemorySize, GEMM_SMEM);
    cudaFuncSetAttribute(attn_bf16,
                         cudaFuncAttributeMaxDynamicSharedMemorySize, ATTN_SMEM);

    // 0) Prep (single launch: x-pack + both weight transposes)
    prep_all<<<XB + WQB + WOB, 256>>>(x, w_qkv, w_out,
                                      xh, xl, wqh, wql, woh, wol);

    // 1) QKV projection (V^T pack fused into epilogue)
    gemm_bf16<3 * D_, 1><<<dim3(24, 32), 256, GEMM_SMEM>>>(
        xh, xl, wqh, wql, b_qkv, nullptr, qh, ql, kh, kl, vth, vtl, kout, vout);

    // 2) Causal flash attention (2 CTAs/SM)
    attn_bf16<<<dim3(L_ / 128, B_ * H_), 256, ATTN_SMEM>>>(
        qh, ql, kh, kl, vth, vtl, ah, al);

    // 3) Output projection
    gemm_bf16<D_, 0><<<dim3(8, 32), 256, GEMM_SMEM>>>(
        ah, al, woh, wol, b_out, out,
        nullptr, nullptr, nullptr, nullptr, nullptr, nullptr, nullptr, nullptr);
}

// round 14
// speedup vs baseline: 2.0223x; 1.0180x over previous
#include <cuda_runtime.h>
#include <cstdint>
#include <math.h>

#define B_  2
#define L_  2048
#define D_  1024
#define H_  16
#define HD_ 64
#define SCALE_ 0.125f

#define NQKV ((size_t)B_ * H_ * L_ * HD_)
#define NX   ((size_t)B_ * L_ * D_)
#define NWQ  ((size_t)D_ * 3 * D_)
#define NWO  ((size_t)D_ * D_)
#define PKW  (D_ / 2)
#define XW   (D_ / 4)          // 256 u32 words per row of int8 plane

// int8 limb planes + scales for QKV
__device__ uint32_t g_xq1[NX / 4], g_xq0[NX / 4];     // x limbs [4096][256]
__device__ uint32_t g_wq1[NWQ / 4], g_wq0[NWQ / 4];   // Wqkv^T limbs [3072][256]
__device__ float    g_sxa[B_ * L_];                   // per-row x scale
__device__ float    g_swq[3 * D_];                    // per-col W scale
// bf16x2 hi/lo planes (attention + out-proj)
__device__ uint32_t g_woh[NWO / 2], g_wol[NWO / 2];
__device__ uint32_t g_qh[NQKV / 2], g_ql[NQKV / 2];
__device__ uint32_t g_kh[NQKV / 2], g_kl[NQKV / 2];
__device__ uint32_t g_vth[NQKV / 2], g_vtl[NQKV / 2];
__device__ uint32_t g_ah[NX / 2],   g_al[NX / 2];

// ===========================================================================
// Helpers
// ===========================================================================
__device__ __forceinline__ void cp_async16(uint32_t dst, const void* src) {
    asm volatile("cp.async.cg.shared.global [%0], [%1], 16;"
                 :: "r"(dst), "l"(src) : "memory");
}
__device__ __forceinline__ void cp_commit() {
    asm volatile("cp.async.commit_group;" ::: "memory");
}
template<int N>
__device__ __forceinline__ void cp_wait() {
    asm volatile("cp.async.wait_group %0;" :: "n"(N) : "memory");
}
__device__ __forceinline__ uint32_t smem_u32(const void* p) {
    uint32_t a;
    asm("{ .reg .u64 t; cvta.to.shared.u64 t, %1; cvt.u32.u64 %0, t; }"
        : "=r"(a) : "l"(p));
    return a;
}
__device__ __forceinline__ uint32_t pack_bf16(float e0, float e1) {
    uint32_t d;
    asm("cvt.rn.bf16x2.f32 %0, %1, %2;" : "=r"(d) : "f"(e1), "f"(e0));
    return d;
}
__device__ __forceinline__ void bf16x2_split(float x0, float x1,
                                             uint32_t& hw, uint32_t& lw) {
    hw = pack_bf16(x0, x1);
    const float h0 = __uint_as_float(hw << 16);
    const float h1 = __uint_as_float(hw & 0xffff0000u);
    lw = pack_bf16(x0 - h0, x1 - h1);
}
__device__ __forceinline__ void quant_limbs(float x, float inv, int& a1, int& a0) {
    const float af = x * inv;                  // |af| <= 8128
    const float a1f = rintf(af * 0.015625f);   // /64, |a1| <= 127
    a1 = (int)a1f;
    a0 = (int)rintf(af - 64.f * a1f);          // |a0| <= 32
}
__device__ __forceinline__ uint32_t pack_s8x4(int a, int b, int c, int d) {
    return (uint32_t)(a & 0xff) | ((uint32_t)(b & 0xff) << 8) |
           ((uint32_t)(c & 0xff) << 16) | ((uint32_t)(d & 0xff) << 24);
}
#define MMA_BF16(c, a, b)                                                      \
    asm("mma.sync.aligned.m16n8k16.row.col.f32.bf16.bf16.f32 "                 \
        "{%0,%1,%2,%3}, {%4,%5,%6,%7}, {%8,%9}, {%0,%1,%2,%3};"                \
        : "+f"((c)[0]), "+f"((c)[1]), "+f"((c)[2]), "+f"((c)[3])               \
        : "r"((a)[0]), "r"((a)[1]), "r"((a)[2]), "r"((a)[3]),                  \
          "r"((b)[0]), "r"((b)[1]))
#define MMA_S8(c, a, b)                                                        \
    asm("mma.sync.aligned.m16n8k32.row.col.s32.s8.s8.s32 "                     \
        "{%0,%1,%2,%3}, {%4,%5,%6,%7}, {%8,%9}, {%0,%1,%2,%3};"                \
        : "+r"((c)[0]), "+r"((c)[1]), "+r"((c)[2]), "+r"((c)[3])               \
        : "r"((a)[0]), "r"((a)[1]), "r"((a)[2]), "r"((a)[3]),                  \
          "r"((b)[0]), "r"((b)[1]))
#define LDSM_X4(r0, r1, r2, r3, addr)                                          \
    asm volatile("ldmatrix.sync.aligned.m8n8.x4.shared.b16 {%0,%1,%2,%3}, [%4];" \
        : "=r"(r0), "=r"(r1), "=r"(r2), "=r"(r3) : "r"(addr))

// ===========================================================================
// Prep kernels
// ===========================================================================
// Per-row quantize x -> 14-bit, split to s8 limbs. 1 block per row.
__global__ __launch_bounds__(256)
void xquant(const float* __restrict__ x, uint32_t* __restrict__ xq1,
            uint32_t* __restrict__ xq0, float* __restrict__ sxa)
{
    __shared__ float red[8];
    const int row = blockIdx.x;
    const int tid = threadIdx.x;
    const float4 v = reinterpret_cast<const float4*>(x + (size_t)row * D_)[tid];
    float mx = fmaxf(fmaxf(fabsf(v.x), fabsf(v.y)), fmaxf(fabsf(v.z), fabsf(v.w)));
#pragma unroll
    for (int off = 16; off > 0; off >>= 1)
        mx = fmaxf(mx, __shfl_xor_sync(0xffffffffu, mx, off));
    if ((tid & 31) == 0) red[tid >> 5] = mx;
    __syncthreads();
    float m8 = red[0];
#pragma unroll
    for (int i = 1; i < 8; i++) m8 = fmaxf(m8, red[i]);
    const float s = (m8 > 0.f) ? m8 * (1.f / 8128.f) : 1.f;
    const float inv = (m8 > 0.f) ? 8128.f / m8 : 0.f;
    int a1[4], a0[4];
    quant_limbs(v.x, inv, a1[0], a0[0]);
    quant_limbs(v.y, inv, a1[1], a0[1]);
    quant_limbs(v.z, inv, a1[2], a0[2]);
    quant_limbs(v.w, inv, a1[3], a0[3]);
    xq1[(size_t)row * XW + tid] = pack_s8x4(a1[0], a1[1], a1[2], a1[3]);
    xq0[(size_t)row * XW + tid] = pack_s8x4(a0[0], a0[1], a0[2], a0[3]);
    if (tid == 0) sxa[row] = s;
}

// Per-column |max| of W [K][N]
__global__ __launch_bounds__(256)
void wcolmax(const float* __restrict__ w, float* __restrict__ sw, int K, int N)
{
    const int j = blockIdx.x * 256 + threadIdx.x;
    if (j >= N) return;
    float mx = 0.f;
    for (int k = 0; k < K; k += 4) {
        mx = fmaxf(mx, fabsf(w[(size_t)k * N + j]));
        mx = fmaxf(mx, fabsf(w[(size_t)(k + 1) * N + j]));
        mx = fmaxf(mx, fabsf(w[(size_t)(k + 2) * N + j]));
        mx = fmaxf(mx, fabsf(w[(size_t)(k + 3) * N + j]));
    }
    sw[j] = (mx > 0.f) ? mx * (1.f / 8128.f) : 1.f;
}

// W [K][N] fp32 -> limbs W1,W0 [N][K] s8 (u32-packed), tile transpose
__global__ __launch_bounds__(256)
void wpack_int(const float* __restrict__ src, const float* __restrict__ sw,
               uint32_t* __restrict__ d1, uint32_t* __restrict__ d0, int N)
{
    __shared__ float tsm[64][65];
    const int tid = threadIdx.x;
    const int n0 = blockIdx.x * 64;
    const int k0 = blockIdx.y * 64;
#pragma unroll
    for (int i = 0; i < 4; i++) {
        const int idx = tid + i * 256;
        const int kk = idx >> 4, n4 = (idx & 15) * 4;
        const float4 v = *reinterpret_cast<const float4*>(
            src + (size_t)(k0 + kk) * N + n0 + n4);
        tsm[kk][n4] = v.x; tsm[kk][n4 + 1] = v.y;
        tsm[kk][n4 + 2] = v.z; tsm[kk][n4 + 3] = v.w;
    }
    __syncthreads();
#pragma unroll
    for (int i = 0; i < 4; i++) {
        const int idx = tid + i * 256;
        const int nn = idx >> 4, k4 = idx & 15;
        const float inv = 1.f / sw[n0 + nn];
        int a1[4], a0[4];
#pragma unroll
        for (int e = 0; e < 4; e++)
            quant_limbs(tsm[k4 * 4 + e][nn], inv, a1[e], a0[e]);
        const size_t off = (size_t)(n0 + nn) * XW + k0 / 4 + k4;
        d1[off] = pack_s8x4(a1[0], a1[1], a1[2], a1[3]);
        d0[off] = pack_s8x4(a0[0], a0[1], a0[2], a0[3]);
    }
}

// W [K][N] fp32 -> bf16 hi/lo [N][K/2] (for out-proj, unchanged scheme)
__global__ __launch_bounds__(256)
void transpose_pack(const float* __restrict__ src, uint32_t* __restrict__ dhi,
                    uint32_t* __restrict__ dlo, int K, int N)
{
    __shared__ float tsm[64][65];
    const int tid = threadIdx.x;
    const int n0 = blockIdx.x * 64;
    const int k0 = blockIdx.y * 64;
#pragma unroll
    for (int i = 0; i < 4; i++) {
        const int idx = tid + i * 256;
        const int kk = idx >> 4, n4 = (idx & 15) * 4;
        const float4 v = *reinterpret_cast<const float4*>(
            src + (size_t)(k0 + kk) * N + n0 + n4);
        tsm[kk][n4] = v.x; tsm[kk][n4 + 1] = v.y;
        tsm[kk][n4 + 2] = v.z; tsm[kk][n4 + 3] = v.w;
    }
    __syncthreads();
    const int kw = K / 2;
#pragma unroll
    for (int i = 0; i < 8; i++) {
        const int idx = tid + i * 256;
        const int nn = idx >> 5, k2 = idx & 31;
        uint32_t hw, lw;
        bf16x2_split(tsm[2 * k2][nn], tsm[2 * k2 + 1][nn], hw, lw);
        const size_t off = (size_t)(n0 + nn) * kw + k0 / 2 + k2;
        dhi[off] = hw;
        dlo[off] = lw;
    }
}

// ===========================================================================
// int8 limb IMMA QKV GEMM: CTA 128x128, K-slab 64 (16 words), double-buffered.
// 256 thr / 8 warps (2m x 4n), warp 64x32. acc_hi = A1B1; acc_mid = A1B0+A0B1.
// out = (4096*hi + 64*mid) * sx[m] * sw[n] + bias. Epilogue scatter as before.
// ===========================================================================
#define IST 20
#define I_TF (128 * IST)
#define I_BUFW (4 * I_TF)
#define IGEMM_SMEM (2 * I_BUFW * 4)              // 81920 B

__global__ __launch_bounds__(256, 1)
void gemm_i8_qkv(const uint32_t* __restrict__ Xq1, const uint32_t* __restrict__ Xq0,
                 const uint32_t* __restrict__ Wq1, const uint32_t* __restrict__ Wq0,
                 const float* __restrict__ sxa, const float* __restrict__ swq,
                 const float* __restrict__ bias,
                 uint32_t* __restrict__ qh, uint32_t* __restrict__ ql,
                 uint32_t* __restrict__ kh, uint32_t* __restrict__ kl,
                 uint32_t* __restrict__ vth, uint32_t* __restrict__ vtl,
                 float* __restrict__ kraw, float* __restrict__ vraw)
{
    extern __shared__ uint32_t smu[];
    const uint32_t sb = smem_u32(smu);

    const int tid  = threadIdx.x;
    const int wid  = tid >> 5;
    const int lane = tid & 31;
    const int g = lane >> 2;
    const int t = lane & 3;
    const int wm0 = (wid >> 2) * 64;
    const int wn0 = (wid & 3) * 32;
    const int m0 = blockIdx.y * 128;
    const int n0 = blockIdx.x * 128;

    int acc_hi[4][4][4], acc_mid[4][4][4];
#pragma unroll
    for (int mt = 0; mt < 4; mt++)
#pragma unroll
        for (int nt = 0; nt < 4; nt++)
#pragma unroll
            for (int r = 0; r < 4; r++) { acc_hi[mt][nt][r] = 0; acc_mid[mt][nt][r] = 0; }

    auto load_stage = [&](int s, int b) {
        const int kw0 = s * 16;
        const uint32_t a1 = sb + (uint32_t)(b * I_BUFW) * 4;
        const uint32_t a0 = a1 + I_TF * 4;
        const uint32_t b1 = a0 + I_TF * 4;
        const uint32_t b0 = b1 + I_TF * 4;
#pragma unroll
        for (int i = 0; i < 2; i++) {
            const int idx = tid + i * 256;
            const int r = idx >> 2, c4 = (idx & 3) * 4;
            const size_t go = (size_t)(m0 + r) * XW + kw0 + c4;
            const uint32_t so = (uint32_t)(r * IST + c4) * 4;
            cp_async16(a1 + so, Xq1 + go);
            cp_async16(a0 + so, Xq0 + go);
        }
#pragma unroll
        for (int i = 0; i < 2; i++) {
            const int idx = tid + i * 256;
            const int r = idx >> 2, c4 = (idx & 3) * 4;
            const size_t go = (size_t)(n0 + r) * XW + kw0 + c4;
            const uint32_t so = (uint32_t)(r * IST + c4) * 4;
            cp_async16(b1 + so, Wq1 + go);
            cp_async16(b0 + so, Wq0 + go);
        }
        cp_commit();
    };

    auto compute_stage = [&](int b) {
        const uint32_t* A1 = smu + b * I_BUFW;
        const uint32_t* A0 = A1 + I_TF;
        const uint32_t* B1 = A0 + I_TF;
        const uint32_t* B0 = B1 + I_TF;
#pragma unroll
        for (int k32 = 0; k32 < 2; k32++) {
            const int kb = k32 * 8;
            uint32_t a1[4][4], a0[4][4], b1[4][2], b0[4][2];
#pragma unroll
            for (int mt = 0; mt < 4; mt++) {
                const int ro = (wm0 + mt * 16 + g) * IST + kb;
                a1[mt][0] = A1[ro + t];
                a1[mt][1] = A1[ro + 8 * IST + t];
                a1[mt][2] = A1[ro + t + 4];
                a1[mt][3] = A1[ro + 8 * IST + t + 4];
                a0[mt][0] = A0[ro + t];
                a0[mt][1] = A0[ro + 8 * IST + t];
                a0[mt][2] = A0[ro + t + 4];
                a0[mt][3] = A0[ro + 8 * IST + t + 4];
            }
#pragma unroll
            for (int nt = 0; nt < 4; nt++) {
                const int no = (wn0 + nt * 8 + g) * IST + kb;
                b1[nt][0] = B1[no + t]; b1[nt][1] = B1[no + t + 4];
                b0[nt][0] = B0[no + t]; b0[nt][1] = B0[no + t + 4];
            }
#pragma unroll
            for (int mt = 0; mt < 4; mt++)
#pragma unroll
                for (int nt = 0; nt < 4; nt++)
                    MMA_S8(acc_hi[mt][nt], a1[mt], b1[nt]);
#pragma unroll
            for (int mt = 0; mt < 4; mt++)
#pragma unroll
                for (int nt = 0; nt < 4; nt++)
                    MMA_S8(acc_mid[mt][nt], a1[mt], b0[nt]);
#pragma unroll
            for (int mt = 0; mt < 4; mt++)
#pragma unroll
                for (int nt = 0; nt < 4; nt++)
                    MMA_S8(acc_mid[mt][nt], a0[mt], b1[nt]);
        }
    };

    load_stage(0, 0);
    constexpr int NS = D_ / 64;          // 16 stages
    for (int s = 0; s < NS; s++) {
        const int b = s & 1;
        if (s + 1 < NS) {
            load_stage(s + 1, b ^ 1);
            cp_wait<1>();
        } else {
            cp_wait<0>();
        }
        __syncthreads();
        compute_stage(b);
        __syncthreads();
    }

    // epilogue: dequant + qkv scatter
#pragma unroll
    for (int mt = 0; mt < 4; mt++) {
#pragma unroll
        for (int half = 0; half < 2; half++) {
            const int m = m0 + wm0 + mt * 16 + g + half * 8;
            const int bb = m >> 11, l = m & (L_ - 1);
            const float sx = sxa[m];
#pragma unroll
            for (int nt = 0; nt < 4; nt++) {
                const int n = n0 + wn0 + nt * 8 + t * 2;
                const int e = half * 2;
                float2 v;
                v.x = ((float)acc_hi[mt][nt][e] * 4096.f
                     + (float)acc_mid[mt][nt][e] * 64.f) * (sx * swq[n]) + bias[n];
                v.y = ((float)acc_hi[mt][nt][e + 1] * 4096.f
                     + (float)acc_mid[mt][nt][e + 1] * 64.f) * (sx * swq[n + 1]) + bias[n + 1];

                const int sidx = n0 >> 10;   // block-uniform q/k/v select
                const int h = (n >> 6) & (H_ - 1), dd = n & (HD_ - 1);
                const size_t row = (size_t)(bb * H_ + h) * L_ + l;
                const size_t woff = row * 32 + (dd >> 1);
                if (sidx == 0) {
                    uint32_t hw, lw;
                    bf16x2_split(v.x, v.y, hw, lw);
                    qh[woff] = hw; ql[woff] = lw;
                } else if (sidx == 1) {
                    uint32_t hw, lw;
                    bf16x2_split(v.x, v.y, hw, lw);
                    kh[woff] = hw; kl[woff] = lw;
                    *reinterpret_cast<float2*>(kraw + row * HD_ + dd) = v;
                } else {
                    *reinterpret_cast<float2*>(vraw + row * HD_ + dd) = v;
                    const float vxn = __shfl_down_sync(0xffffffffu, v.x, 4);
                    const float vyn = __shfl_down_sync(0xffffffffu, v.y, 4);
                    if ((g & 1) == 0) {
                        const size_t vb = (size_t)(bb * H_ + h) * HD_ * (L_ / 2);
                        const size_t l2 = (size_t)(l >> 1);
                        uint32_t hw, lw;
                        bf16x2_split(v.x, vxn, hw, lw);
                        vth[vb + (size_t)dd * (L_ / 2) + l2] = hw;
                        vtl[vb + (size_t)dd * (L_ / 2) + l2] = lw;
                        bf16x2_split(v.y, vyn, hw, lw);
                        vth[vb + (size_t)(dd + 1) * (L_ / 2) + l2] = hw;
                        vtl[vb + (size_t)(dd + 1) * (L_ / 2) + l2] = lw;
                    }
                }
            }
        }
    }
}

// ===========================================================================
// bf16x3 out-proj GEMM (R13, validated): CTA 128x128, ldmatrix, 2 CTAs/SM.
// ===========================================================================
#define GST 20
#define G_TF (128 * GST)
#define G_BUFW (4 * G_TF)
#define GEMM_SMEM (2 * G_BUFW * 4)

__global__ __launch_bounds__(256, 2)
void gemm_out(const uint32_t* __restrict__ Ahi, const uint32_t* __restrict__ Alo,
              const uint32_t* __restrict__ Whi, const uint32_t* __restrict__ Wlo,
              const float* __restrict__ bias, float* __restrict__ outF)
{
    extern __shared__ uint32_t smu[];
    const uint32_t sb = smem_u32(smu);

    const int tid  = threadIdx.x;
    const int lane = tid & 31;
    const int wid  = tid >> 5;
    const int g = lane >> 2;
    const int t = lane & 3;
    const int wm0 = (wid >> 2) * 64;
    const int wn0 = (wid & 3) * 32;
    const int m0 = blockIdx.y * 128;
    const int n0 = blockIdx.x * 128;

    const uint32_t laneA = (uint32_t)(((lane & 15) * GST + (lane >> 4) * 4) * 4);
    const uint32_t laneB = (uint32_t)((((lane & 7) + (lane >> 4) * 8) * GST
                                      + ((lane >> 3) & 1) * 4) * 4);

    float acc[4][4][4];
#pragma unroll
    for (int mt = 0; mt < 4; mt++)
#pragma unroll
        for (int nt = 0; nt < 4; nt++)
#pragma unroll
            for (int r = 0; r < 4; r++) acc[mt][nt][r] = 0.f;

    auto load_stage = [&](int s, int b) {
        const int kw0 = s * 16;
        const uint32_t aH = sb + (uint32_t)(b * G_BUFW) * 4;
        const uint32_t aL = aH + G_TF * 4;
        const uint32_t bH = aL + G_TF * 4;
        const uint32_t bL = bH + G_TF * 4;
#pragma unroll
        for (int i = 0; i < 2; i++) {
            const int idx = tid + i * 256;
            const int r = idx >> 2, c4 = (idx & 3) * 4;
            const size_t go = (size_t)(m0 + r) * PKW + kw0 + c4;
            const uint32_t so = (uint32_t)(r * GST + c4) * 4;
            cp_async16(aH + so, Ahi + go);
            cp_async16(aL + so, Alo + go);
        }
#pragma unroll
        for (int i = 0; i < 2; i++) {
            const int idx = tid + i * 256;
            const int r = idx >> 2, c4 = (idx & 3) * 4;
            const size_t go = (size_t)(n0 + r) * PKW + kw0 + c4;
            const uint32_t so = (uint32_t)(r * GST + c4) * 4;
            cp_async16(bH + so, Whi + go);
            cp_async16(bL + so, Wlo + go);
        }
        cp_commit();
    };

    auto compute_stage = [&](int b) {
        const uint32_t aH = sb + (uint32_t)(b * G_BUFW) * 4;
        const uint32_t aL = aH + G_TF * 4;
        const uint32_t bHa = aL + G_TF * 4;
        const uint32_t bLa = bHa + G_TF * 4;
#pragma unroll
        for (int k16 = 0; k16 < 2; k16++) {
            const uint32_t kboff = (uint32_t)(k16 * 32);
            uint32_t ah[4][4], al[4][4], bh[4][2], bl[4][2];
#pragma unroll
            for (int mt = 0; mt < 4; mt++) {
                const uint32_t base = (uint32_t)((wm0 + mt * 16) * GST * 4) + kboff + laneA;
                LDSM_X4(ah[mt][0], ah[mt][1], ah[mt][2], ah[mt][3], aH + base);
                LDSM_X4(al[mt][0], al[mt][1], al[mt][2], al[mt][3], aL + base);
            }
#pragma unroll
            for (int nt2 = 0; nt2 < 2; nt2++) {
                const uint32_t base = (uint32_t)((wn0 + nt2 * 16) * GST * 4) + kboff + laneB;
                LDSM_X4(bh[2 * nt2][0], bh[2 * nt2][1],
                        bh[2 * nt2 + 1][0], bh[2 * nt2 + 1][1], bHa + base);
                LDSM_X4(bl[2 * nt2][0], bl[2 * nt2][1],
                        bl[2 * nt2 + 1][0], bl[2 * nt2 + 1][1], bLa + base);
            }
#pragma unroll
            for (int mt = 0; mt < 4; mt++)
#pragma unroll
                for (int nt = 0; nt < 4; nt++)
                    MMA_BF16(acc[mt][nt], al[mt], bh[nt]);
#pragma unroll
            for (int mt = 0; mt < 4; mt++)
#pragma unroll
                for (int nt = 0; nt < 4; nt++)
                    MMA_BF16(acc[mt][nt], ah[mt], bl[nt]);
#pragma unroll
            for (int mt = 0; mt < 4; mt++)
#pragma unroll
                for (int nt = 0; nt < 4; nt++)
                    MMA_BF16(acc[mt][nt], ah[mt], bh[nt]);
        }
    };

    load_stage(0, 0);
    constexpr int NS = D_ / 32;
    for (int s = 0; s < NS; s++) {
        const int b = s & 1;
        if (s + 1 < NS) {
            load_stage(s + 1, b ^ 1);
            cp_wait<1>();
        } else {
            cp_wait<0>();
        }
        __syncthreads();
        compute_stage(b);
        __syncthreads();
    }

#pragma unroll
    for (int mt = 0; mt < 4; mt++) {
#pragma unroll
        for (int half = 0; half < 2; half++) {
            const int m = m0 + wm0 + mt * 16 + g + half * 8;
#pragma unroll
            for (int nt = 0; nt < 4; nt++) {
                const int n = n0 + wn0 + nt * 8 + t * 2;
                float2 v;
                v.x = acc[mt][nt][half * 2 + 0] + bias[n];
                v.y = acc[mt][nt][half * 2 + 1] + bias[n + 1];
                *reinterpret_cast<float2*>(outF + (size_t)m * D_ + n) = v;
            }
        }
    }
}

// ===========================================================================
// Flash attention (causal), bf16x3 m16n8k16, ldmatrix loads (R13, validated).
// ===========================================================================
#define ATST 36
#define AQ_WORDS (128 * ATST)
#define ABUF0 (2 * AQ_WORDS)
#define AKV_TILE (64 * ATST)
#define ABUFW (4 * AKV_TILE)
#define ATTN_WORDS (ABUF0 + 2 * ABUFW)
#define ATTN_SMEM (ATTN_WORDS * 4)

__global__ __launch_bounds__(256, 2)
void attn_bf16(const uint32_t* __restrict__ qh_g, const uint32_t* __restrict__ ql_g,
               const uint32_t* __restrict__ kh_g, const uint32_t* __restrict__ kl_g,
               const uint32_t* __restrict__ vth_g, const uint32_t* __restrict__ vtl_g,
               uint32_t* __restrict__ ah_g, uint32_t* __restrict__ al_g)
{
    extern __shared__ uint32_t smu[];
    const uint32_t sb = smem_u32(smu);

    const int tidx = (int)gridDim.x - 1 - (int)blockIdx.x;
    const int bh   = blockIdx.y;
    const int row0 = tidx * 128;
    const uint32_t* qhp = qh_g + (size_t)bh * L_ * 32;
    const uint32_t* qlp = ql_g + (size_t)bh * L_ * 32;
    const uint32_t* khp = kh_g + (size_t)bh * L_ * 32;
    const uint32_t* klp = kl_g + (size_t)bh * L_ * 32;
    const uint32_t* vhp = vth_g + (size_t)bh * HD_ * (L_ / 2);
    const uint32_t* vlp = vtl_g + (size_t)bh * HD_ * (L_ / 2);

    const int tid = threadIdx.x;
    const int wid = tid >> 5;
    const int lane = tid & 31;
    const int g = lane >> 2;
    const int t = lane & 3;
    const int wrow = wid * 16;

    const uint32_t laneA = (uint32_t)(((lane & 15) * ATST + (lane >> 4) * 4) * 4);
    const uint32_t laneB = (uint32_t)((((lane & 7) + (lane >> 4) * 8) * ATST
                                      + ((lane >> 3) & 1) * 4) * 4);

    auto load_kv = [&](int c0, int b) {
        const uint32_t kH = sb + (uint32_t)(ABUF0 + b * ABUFW) * 4;
        const uint32_t kL = kH + AKV_TILE * 4;
        const uint32_t vH = kL + AKV_TILE * 4;
        const uint32_t vL = vH + AKV_TILE * 4;
#pragma unroll
        for (int i = 0; i < 2; i++) {
            const int idx = tid + i * 256;
            const int r = idx >> 3, c4 = (idx & 7) * 4;
            const uint32_t so = (uint32_t)(r * ATST + c4) * 4;
            cp_async16(kH + so, khp + (size_t)(c0 + r) * 32 + c4);
            cp_async16(kL + so, klp + (size_t)(c0 + r) * 32 + c4);
        }
#pragma unroll
        for (int i = 0; i < 2; i++) {
            const int idx = tid + i * 256;
            const int r = idx >> 3, c4 = (idx & 7) * 4;
            const uint32_t so = (uint32_t)(r * ATST + c4) * 4;
            cp_async16(vH + so, vhp + (size_t)r * (L_ / 2) + c0 / 2 + c4);
            cp_async16(vL + so, vlp + (size_t)r * (L_ / 2) + c0 / 2 + c4);
        }
        cp_commit();
    };
    load_kv(0, 0);

    uint32_t* Qh = smu;
    uint32_t* Ql = smu + AQ_WORDS;
#pragma unroll
    for (int i = 0; i < 2; i++) {
        const int idx = tid + i * 256;
        const int r = idx >> 2, c4 = (idx & 3) * 8;
        *reinterpret_cast<uint4*>(&Qh[r * ATST + c4]) =
            *reinterpret_cast<const uint4*>(qhp + (size_t)(row0 + r) * 32 + c4);
        *reinterpret_cast<uint4*>(&Qh[r * ATST + c4 + 4]) =
            *reinterpret_cast<const uint4*>(qhp + (size_t)(row0 + r) * 32 + c4 + 4);
        *reinterpret_cast<uint4*>(&Ql[r * ATST + c4]) =
            *reinterpret_cast<const uint4*>(qlp + (size_t)(row0 + r) * 32 + c4);
        *reinterpret_cast<uint4*>(&Ql[r * ATST + c4 + 4]) =
            *reinterpret_cast<const uint4*>(qlp + (size_t)(row0 + r) * 32 + c4 + 4);
    }
    const uint32_t QhA = sb;
    const uint32_t QlA = sb + AQ_WORDS * 4;

    float accO[8][4];
    float m_i[2] = { -1e30f, -1e30f };
    float l_i[2] = { 0.f, 0.f };
#pragma unroll
    for (int nt = 0; nt < 8; nt++)
#pragma unroll
        for (int e = 0; e < 4; e++) accO[nt][e] = 0.f;

    const int jmax = 2 * tidx + 1;
    for (int j0 = 0; j0 <= jmax; j0++) {
        const int c0 = j0 * 64;
        const int b = j0 & 1;

        cp_wait<0>();
        __syncthreads();

        if (j0 < jmax) load_kv(c0 + 64, b ^ 1);

        const uint32_t KH = sb + (uint32_t)(ABUF0 + b * ABUFW) * 4;
        const uint32_t KL = KH + AKV_TILE * 4;
        const uint32_t VH = KL + AKV_TILE * 4;
        const uint32_t VL = VH + AKV_TILE * 4;

        float s[8][4];
#pragma unroll
        for (int nt = 0; nt < 8; nt++)
#pragma unroll
            for (int e = 0; e < 4; e++) s[nt][e] = 0.f;

#pragma unroll
        for (int k16 = 0; k16 < 4; k16++) {
            const uint32_t kboff = (uint32_t)(k16 * 32);
            uint32_t ah[4], al[4], bh2[8][2], bl2[8][2];
            const uint32_t qbase = (uint32_t)(wrow * ATST * 4) + kboff + laneA;
            LDSM_X4(ah[0], ah[1], ah[2], ah[3], QhA + qbase);
            LDSM_X4(al[0], al[1], al[2], al[3], QlA + qbase);
#pragma unroll
            for (int nt2 = 0; nt2 < 4; nt2++) {
                const uint32_t base = (uint32_t)(nt2 * 16 * ATST * 4) + kboff + laneB;
                LDSM_X4(bh2[2 * nt2][0], bh2[2 * nt2][1],
                        bh2[2 * nt2 + 1][0], bh2[2 * nt2 + 1][1], KH + base);
                LDSM_X4(bl2[2 * nt2][0], bl2[2 * nt2][1],
                        bl2[2 * nt2 + 1][0], bl2[2 * nt2 + 1][1], KL + base);
            }
#pragma unroll
            for (int nt = 0; nt < 8; nt++) MMA_BF16(s[nt], al, bh2[nt]);
#pragma unroll
            for (int nt = 0; nt < 8; nt++) MMA_BF16(s[nt], ah, bl2[nt]);
#pragma unroll
            for (int nt = 0; nt < 8; nt++) MMA_BF16(s[nt], ah, bh2[nt]);
        }

        const bool dm = (c0 + 63 > row0);
        const int r0 = row0 + wrow + g;
        const int r1 = r0 + 8;
#pragma unroll
        for (int nt = 0; nt < 8; nt++) {
#pragma unroll
            for (int e = 0; e < 4; e++) {
                const int col = c0 + nt * 8 + 2 * t + (e & 1);
                const int row = (e < 2) ? r0 : r1;
                s[nt][e] *= SCALE_;
                if (dm && col > row) s[nt][e] = -1e30f;
            }
        }

        float mx0 = -1e30f, mx1 = -1e30f;
#pragma unroll
        for (int nt = 0; nt < 8; nt++) {
            mx0 = fmaxf(mx0, fmaxf(s[nt][0], s[nt][1]));
            mx1 = fmaxf(mx1, fmaxf(s[nt][2], s[nt][3]));
        }
#pragma unroll
        for (int off = 1; off <= 2; off <<= 1) {
            mx0 = fmaxf(mx0, __shfl_xor_sync(0xffffffffu, mx0, off));
            mx1 = fmaxf(mx1, __shfl_xor_sync(0xffffffffu, mx1, off));
        }
        const float mn0 = fmaxf(m_i[0], mx0);
        const float mn1 = fmaxf(m_i[1], mx1);
        const float corr0 = __expf(m_i[0] - mn0);
        const float corr1 = __expf(m_i[1] - mn1);
        m_i[0] = mn0; m_i[1] = mn1;

        float ls0 = 0.f, ls1 = 0.f;
#pragma unroll
        for (int nt = 0; nt < 8; nt++) {
            s[nt][0] = __expf(s[nt][0] - mn0);
            s[nt][1] = __expf(s[nt][1] - mn0);
            s[nt][2] = __expf(s[nt][2] - mn1);
            s[nt][3] = __expf(s[nt][3] - mn1);
            ls0 += s[nt][0] + s[nt][1];
            ls1 += s[nt][2] + s[nt][3];
        }
#pragma unroll
        for (int off = 1; off <= 2; off <<= 1) {
            ls0 += __shfl_xor_sync(0xffffffffu, ls0, off);
            ls1 += __shfl_xor_sync(0xffffffffu, ls1, off);
        }
        l_i[0] = l_i[0] * corr0 + ls0;
        l_i[1] = l_i[1] * corr1 + ls1;
#pragma unroll
        for (int nt = 0; nt < 8; nt++) {
            accO[nt][0] *= corr0; accO[nt][1] *= corr0;
            accO[nt][2] *= corr1; accO[nt][3] *= corr1;
        }

        uint32_t phw[8][2], plw[8][2];
#pragma unroll
        for (int nt = 0; nt < 8; nt++) {
            bf16x2_split(s[nt][0], s[nt][1], phw[nt][0], plw[nt][0]);
            bf16x2_split(s[nt][2], s[nt][3], phw[nt][1], plw[nt][1]);
        }

#pragma unroll
        for (int ks = 0; ks < 4; ks++) {
            const uint32_t kboff = (uint32_t)(ks * 32);
            uint32_t pah[4] = { phw[2 * ks][0], phw[2 * ks][1],
                                phw[2 * ks + 1][0], phw[2 * ks + 1][1] };
            uint32_t pal[4] = { plw[2 * ks][0], plw[2 * ks][1],
                                plw[2 * ks + 1][0], plw[2 * ks + 1][1] };
            uint32_t vh[8][2], vl[8][2];
#pragma unroll
            for (int nt2 = 0; nt2 < 4; nt2++) {
                const uint32_t base = (uint32_t)(nt2 * 16 * ATST * 4) + kboff + laneB;
                LDSM_X4(vh[2 * nt2][0], vh[2 * nt2][1],
                        vh[2 * nt2 + 1][0], vh[2 * nt2 + 1][1], VH + base);
                LDSM_X4(vl[2 * nt2][0], vl[2 * nt2][1],
                        vl[2 * nt2 + 1][0], vl[2 * nt2 + 1][1], VL + base);
            }
#pragma unroll
            for (int nt = 0; nt < 8; nt++) MMA_BF16(accO[nt], pal, vh[nt]);
#pragma unroll
            for (int nt = 0; nt < 8; nt++) MMA_BF16(accO[nt], pah, vl[nt]);
#pragma unroll
            for (int nt = 0; nt < 8; nt++) MMA_BF16(accO[nt], pah, vh[nt]);
        }
    }

    const int bb = bh >> 4;
    const int h  = bh & (H_ - 1);
    const float inv0 = 1.0f / l_i[0];
    const float inv1 = 1.0f / l_i[1];
    const int r0 = row0 + wrow + g;
#pragma unroll
    for (int nt = 0; nt < 8; nt++) {
        const int widx = h * 32 + nt * 4 + t;
        uint32_t hw, lw;
        bf16x2_split(accO[nt][0] * inv0, accO[nt][1] * inv0, hw, lw);
        ah_g[((size_t)(bb * L_ + r0)) * 512 + widx] = hw;
        al_g[((size_t)(bb * L_ + r0)) * 512 + widx] = lw;
        bf16x2_split(accO[nt][2] * inv1, accO[nt][3] * inv1, hw, lw);
        ah_g[((size_t)(bb * L_ + r0 + 8)) * 512 + widx] = hw;
        al_g[((size_t)(bb * L_ + r0 + 8)) * 512 + widx] = lw;
    }
}

// ---------------------------------------------------------------------------
extern "C" void kernel_launch(void* const* d_in, const int* in_sizes, int n_in,
                              void* d_out, int out_size)
{
    const float* x     = (const float*)d_in[0];
    const float* w_qkv = (const float*)d_in[1];
    const float* b_qkv = (const float*)d_in[2];
    const float* w_out = (const float*)d_in[3];
    const float* b_out = (const float*)d_in[4];

    float* out  = (float*)d_out;
    float* kout = out  + (size_t)B_ * L_ * D_;
    float* vout = kout + NQKV;

    uint32_t *xq1, *xq0, *wq1, *wq0, *woh, *wol;
    uint32_t *qh, *ql, *kh, *kl, *vth, *vtl, *ah, *al;
    float *sxa, *swq;
    cudaGetSymbolAddress((void**)&xq1, g_xq1);
    cudaGetSymbolAddress((void**)&xq0, g_xq0);
    cudaGetSymbolAddress((void**)&wq1, g_wq1);
    cudaGetSymbolAddress((void**)&wq0, g_wq0);
    cudaGetSymbolAddress((void**)&sxa, g_sxa);
    cudaGetSymbolAddress((void**)&swq, g_swq);
    cudaGetSymbolAddress((void**)&woh, g_woh);
    cudaGetSymbolAddress((void**)&wol, g_wol);
    cudaGetSymbolAddress((void**)&qh, g_qh);
    cudaGetSymbolAddress((void**)&ql, g_ql);
    cudaGetSymbolAddress((void**)&kh, g_kh);
    cudaGetSymbolAddress((void**)&kl, g_kl);
    cudaGetSymbolAddress((void**)&vth, g_vth);
    cudaGetSymbolAddress((void**)&vtl, g_vtl);
    cudaGetSymbolAddress((void**)&ah, g_ah);
    cudaGetSymbolAddress((void**)&al, g_al);

    cudaFuncSetAttribute(gemm_i8_qkv,
                         cudaFuncAttributeMaxDynamicSharedMemorySize, IGEMM_SMEM);
    cudaFuncSetAttribute(gemm_out,
                         cudaFuncAttributeMaxDynamicSharedMemorySize, GEMM_SMEM);
    cudaFuncSetAttribute(attn_bf16,
                         cudaFuncAttributeMaxDynamicSharedMemorySize, ATTN_SMEM);

    // 0) Prep
    xquant<<<B_ * L_, 256>>>(x, xq1, xq0, sxa);
    wcolmax<<<(3 * D_) / 256, 256>>>(w_qkv, swq, D_, 3 * D_);
    transpose_pack<<<dim3(D_ / 64, D_ / 64), 256>>>(w_out, woh, wol, D_, D_);
    wpack_int<<<dim3(3 * D_ / 64, D_ / 64), 256>>>(w_qkv, swq, wq1, wq0, 3 * D_);

    // 1) QKV projection (int8 limb IMMA)
    gemm_i8_qkv<<<dim3(24, 32), 256, IGEMM_SMEM>>>(
        xq1, xq0, wq1, wq0, sxa, swq, b_qkv,
        qh, ql, kh, kl, vth, vtl, kout, vout);

    // 2) Causal flash attention (bf16x3)
    attn_bf16<<<dim3(L_ / 128, B_ * H_), 256, ATTN_SMEM>>>(
        qh, ql, kh, kl, vth, vtl, ah, al);

    // 3) Output projection (bf16x3)
    gemm_out<<<dim3(8, 32), 256, GEMM_SMEM>>>(ah, al, woh, wol, b_out, out);
}

// round 16
// speedup vs baseline: 2.1224x; 1.0495x over previous
#include <cuda_runtime.h>
#include <cstdint>
#include <math.h>

#define B_  2
#define L_  2048
#define D_  1024
#define H_  16
#define HD_ 64
#define SCALE_ 0.125f

#define NQKV ((size_t)B_ * H_ * L_ * HD_)
#define NX   ((size_t)B_ * L_ * D_)
#define NWQ  ((size_t)D_ * 3 * D_)
#define NWO  ((size_t)D_ * D_)
#define PKW  (D_ / 2)
#define XW   (D_ / 4)

// int8 limb planes + scales for QKV
__device__ uint32_t g_xq1[NX / 4], g_xq0[NX / 4];
__device__ uint32_t g_wq1[NWQ / 4], g_wq0[NWQ / 4];
__device__ float    g_sxa[B_ * L_];
__device__ float    g_swq[3 * D_];
// bf16x2 hi/lo planes (attention + out-proj)
__device__ uint32_t g_woh[NWO / 2], g_wol[NWO / 2];
__device__ uint32_t g_qh[NQKV / 2], g_ql[NQKV / 2];
__device__ uint32_t g_kh[NQKV / 2], g_kl[NQKV / 2];
__device__ uint32_t g_vth[NQKV / 2], g_vtl[NQKV / 2];
__device__ uint32_t g_ah[NX / 2],   g_al[NX / 2];

// ===========================================================================
// Helpers
// ===========================================================================
__device__ __forceinline__ void cp_async16(uint32_t dst, const void* src) {
    asm volatile("cp.async.cg.shared.global [%0], [%1], 16;"
                 :: "r"(dst), "l"(src) : "memory");
}
__device__ __forceinline__ void cp_commit() {
    asm volatile("cp.async.commit_group;" ::: "memory");
}
template<int N>
__device__ __forceinline__ void cp_wait() {
    asm volatile("cp.async.wait_group %0;" :: "n"(N) : "memory");
}
__device__ __forceinline__ uint32_t smem_u32(const void* p) {
    uint32_t a;
    asm("{ .reg .u64 t; cvta.to.shared.u64 t, %1; cvt.u32.u64 %0, t; }"
        : "=r"(a) : "l"(p));
    return a;
}
__device__ __forceinline__ uint32_t pack_bf16(float e0, float e1) {
    uint32_t d;
    asm("cvt.rn.bf16x2.f32 %0, %1, %2;" : "=r"(d) : "f"(e1), "f"(e0));
    return d;
}
__device__ __forceinline__ void bf16x2_split(float x0, float x1,
                                             uint32_t& hw, uint32_t& lw) {
    hw = pack_bf16(x0, x1);
    const float h0 = __uint_as_float(hw << 16);
    const float h1 = __uint_as_float(hw & 0xffff0000u);
    lw = pack_bf16(x0 - h0, x1 - h1);
}
__device__ __forceinline__ void quant_limbs(float x, float inv, int& a1, int& a0) {
    const float af = x * inv;
    const float a1f = rintf(af * 0.015625f);
    a1 = (int)a1f;
    a0 = (int)rintf(af - 64.f * a1f);
}
__device__ __forceinline__ uint32_t pack_s8x4(int a, int b, int c, int d) {
    return (uint32_t)(a & 0xff) | ((uint32_t)(b & 0xff) << 8) |
           ((uint32_t)(c & 0xff) << 16) | ((uint32_t)(d & 0xff) << 24);
}
#define MMA_BF16(c, a, b)                                                      \
    asm("mma.sync.aligned.m16n8k16.row.col.f32.bf16.bf16.f32 "                 \
        "{%0,%1,%2,%3}, {%4,%5,%6,%7}, {%8,%9}, {%0,%1,%2,%3};"                \
        : "+f"((c)[0]), "+f"((c)[1]), "+f"((c)[2]), "+f"((c)[3])               \
        : "r"((a)[0]), "r"((a)[1]), "r"((a)[2]), "r"((a)[3]),                  \
          "r"((b)[0]), "r"((b)[1]))
#define MMA_S8(c, a, b)                                                        \
    asm("mma.sync.aligned.m16n8k32.row.col.s32.s8.s8.s32 "                     \
        "{%0,%1,%2,%3}, {%4,%5,%6,%7}, {%8,%9}, {%0,%1,%2,%3};"                \
        : "+r"((c)[0]), "+r"((c)[1]), "+r"((c)[2]), "+r"((c)[3])               \
        : "r"((a)[0]), "r"((a)[1]), "r"((a)[2]), "r"((a)[3]),                  \
          "r"((b)[0]), "r"((b)[1]))
#define LDSM_X4(r0, r1, r2, r3, addr)                                          \
    asm volatile("ldmatrix.sync.aligned.m8n8.x4.shared.b16 {%0,%1,%2,%3}, [%4];" \
        : "=r"(r0), "=r"(r1), "=r"(r2), "=r"(r3) : "r"(addr))

// ===========================================================================
// Prep: 2 launches.
// prep1: blocks [0,12) col-max of w_qkv; [12, 12+256) transpose-pack w_out.
// prep2: blocks [0,4096) x row-quant; [4096, 4096+768) w_qkv limb pack.
// ===========================================================================
#define CMB 12
#define WOB ((D_ / 64) * (D_ / 64))      // 256
#define XQB (B_ * L_)                    // 4096
#define WQB ((3 * D_ / 64) * (D_ / 64))  // 768

__global__ __launch_bounds__(256)
void prep1(const float* __restrict__ w_qkv, const float* __restrict__ w_out,
           float* __restrict__ swq,
           uint32_t* __restrict__ woh, uint32_t* __restrict__ wol)
{
    __shared__ float tsm[64][65];
    const int bid = blockIdx.x;
    const int tid = threadIdx.x;
    if (bid < CMB) {
        const int j = bid * 256 + tid;           // column of w_qkv (N=3072)
        float mx = 0.f;
        for (int k = 0; k < D_; k += 4) {
            mx = fmaxf(mx, fabsf(w_qkv[(size_t)k * (3 * D_) + j]));
            mx = fmaxf(mx, fabsf(w_qkv[(size_t)(k + 1) * (3 * D_) + j]));
            mx = fmaxf(mx, fabsf(w_qkv[(size_t)(k + 2) * (3 * D_) + j]));
            mx = fmaxf(mx, fabsf(w_qkv[(size_t)(k + 3) * (3 * D_) + j]));
        }
        swq[j] = (mx > 0.f) ? mx * (1.f / 8128.f) : 1.f;
    } else {
        const int b = bid - CMB;
        const int n0 = (b % (D_ / 64)) * 64;
        const int k0 = (b / (D_ / 64)) * 64;
#pragma unroll
        for (int i = 0; i < 4; i++) {
            const int idx = tid + i * 256;
            const int kk = idx >> 4, n4 = (idx & 15) * 4;
            const float4 v = *reinterpret_cast<const float4*>(
                w_out + (size_t)(k0 + kk) * D_ + n0 + n4);
            tsm[kk][n4] = v.x; tsm[kk][n4 + 1] = v.y;
            tsm[kk][n4 + 2] = v.z; tsm[kk][n4 + 3] = v.w;
        }
        __syncthreads();
#pragma unroll
        for (int i = 0; i < 8; i++) {
            const int idx = tid + i * 256;
            const int nn = idx >> 5, k2 = idx & 31;
            uint32_t hw, lw;
            bf16x2_split(tsm[2 * k2][nn], tsm[2 * k2 + 1][nn], hw, lw);
            woh[(size_t)(n0 + nn) * PKW + k0 / 2 + k2] = hw;
            wol[(size_t)(n0 + nn) * PKW + k0 / 2 + k2] = lw;
        }
    }
}

__global__ __launch_bounds__(256)
void prep2(const float* __restrict__ x, const float* __restrict__ w_qkv,
           const float* __restrict__ swq,
           uint32_t* __restrict__ xq1, uint32_t* __restrict__ xq0,
           float* __restrict__ sxa,
           uint32_t* __restrict__ wq1, uint32_t* __restrict__ wq0)
{
    __shared__ float tsm[64][65];
    const int bid = blockIdx.x;
    const int tid = threadIdx.x;
    if (bid < XQB) {
        // per-row quantize x -> 14-bit limbs
        const int row = bid;
        const float4 v = reinterpret_cast<const float4*>(x + (size_t)row * D_)[tid];
        float mx = fmaxf(fmaxf(fabsf(v.x), fabsf(v.y)),
                         fmaxf(fabsf(v.z), fabsf(v.w)));
#pragma unroll
        for (int off = 16; off > 0; off >>= 1)
            mx = fmaxf(mx, __shfl_xor_sync(0xffffffffu, mx, off));
        if ((tid & 31) == 0) tsm[0][tid >> 5] = mx;
        __syncthreads();
        float m8 = tsm[0][0];
#pragma unroll
        for (int i = 1; i < 8; i++) m8 = fmaxf(m8, tsm[0][i]);
        const float s = (m8 > 0.f) ? m8 * (1.f / 8128.f) : 1.f;
        const float inv = (m8 > 0.f) ? 8128.f / m8 : 0.f;
        int a1[4], a0[4];
        quant_limbs(v.x, inv, a1[0], a0[0]);
        quant_limbs(v.y, inv, a1[1], a0[1]);
        quant_limbs(v.z, inv, a1[2], a0[2]);
        quant_limbs(v.w, inv, a1[3], a0[3]);
        xq1[(size_t)row * XW + tid] = pack_s8x4(a1[0], a1[1], a1[2], a1[3]);
        xq0[(size_t)row * XW + tid] = pack_s8x4(a0[0], a0[1], a0[2], a0[3]);
        if (tid == 0) sxa[row] = s;
    } else {
        // transpose + limb-pack w_qkv tile
        const int b = bid - XQB;
        const int n0 = (b % (3 * D_ / 64)) * 64;
        const int k0 = (b / (3 * D_ / 64)) * 64;
#pragma unroll
        for (int i = 0; i < 4; i++) {
            const int idx = tid + i * 256;
            const int kk = idx >> 4, n4 = (idx & 15) * 4;
            const float4 v = *reinterpret_cast<const float4*>(
                w_qkv + (size_t)(k0 + kk) * (3 * D_) + n0 + n4);
            tsm[kk][n4] = v.x; tsm[kk][n4 + 1] = v.y;
            tsm[kk][n4 + 2] = v.z; tsm[kk][n4 + 3] = v.w;
        }
        __syncthreads();
#pragma unroll
        for (int i = 0; i < 4; i++) {
            const int idx = tid + i * 256;
            const int nn = idx >> 4, k4 = idx & 15;
            const float inv = 1.f / swq[n0 + nn];
            int a1[4], a0[4];
#pragma unroll
            for (int e = 0; e < 4; e++)
                quant_limbs(tsm[k4 * 4 + e][nn], inv, a1[e], a0[e]);
            const size_t off = (size_t)(n0 + nn) * XW + k0 / 4 + k4;
            wq1[off] = pack_s8x4(a1[0], a1[1], a1[2], a1[3]);
            wq0[off] = pack_s8x4(a0[0], a0[1], a0[2], a0[3]);
        }
    }
}

// ===========================================================================
// int8 limb IMMA QKV GEMM (R14, validated)
// ===========================================================================
#define IST 20
#define I_TF (128 * IST)
#define I_BUFW (4 * I_TF)
#define IGEMM_SMEM (2 * I_BUFW * 4)

__global__ __launch_bounds__(256, 1)
void gemm_i8_qkv(const uint32_t* __restrict__ Xq1, const uint32_t* __restrict__ Xq0,
                 const uint32_t* __restrict__ Wq1, const uint32_t* __restrict__ Wq0,
                 const float* __restrict__ sxa, const float* __restrict__ swq,
                 const float* __restrict__ bias,
                 uint32_t* __restrict__ qh, uint32_t* __restrict__ ql,
                 uint32_t* __restrict__ kh, uint32_t* __restrict__ kl,
                 uint32_t* __restrict__ vth, uint32_t* __restrict__ vtl,
                 float* __restrict__ kraw, float* __restrict__ vraw)
{
    extern __shared__ uint32_t smu[];
    const uint32_t sb = smem_u32(smu);

    const int tid  = threadIdx.x;
    const int wid  = tid >> 5;
    const int lane = tid & 31;
    const int g = lane >> 2;
    const int t = lane & 3;
    const int wm0 = (wid >> 2) * 64;
    const int wn0 = (wid & 3) * 32;
    const int m0 = blockIdx.y * 128;
    const int n0 = blockIdx.x * 128;

    int acc_hi[4][4][4], acc_mid[4][4][4];
#pragma unroll
    for (int mt = 0; mt < 4; mt++)
#pragma unroll
        for (int nt = 0; nt < 4; nt++)
#pragma unroll
            for (int r = 0; r < 4; r++) { acc_hi[mt][nt][r] = 0; acc_mid[mt][nt][r] = 0; }

    auto load_stage = [&](int s, int b) {
        const int kw0 = s * 16;
        const uint32_t a1 = sb + (uint32_t)(b * I_BUFW) * 4;
        const uint32_t a0 = a1 + I_TF * 4;
        const uint32_t b1 = a0 + I_TF * 4;
        const uint32_t b0 = b1 + I_TF * 4;
#pragma unroll
        for (int i = 0; i < 2; i++) {
            const int idx = tid + i * 256;
            const int r = idx >> 2, c4 = (idx & 3) * 4;
            const size_t go = (size_t)(m0 + r) * XW + kw0 + c4;
            const uint32_t so = (uint32_t)(r * IST + c4) * 4;
            cp_async16(a1 + so, Xq1 + go);
            cp_async16(a0 + so, Xq0 + go);
        }
#pragma unroll
        for (int i = 0; i < 2; i++) {
            const int idx = tid + i * 256;
            const int r = idx >> 2, c4 = (idx & 3) * 4;
            const size_t go = (size_t)(n0 + r) * XW + kw0 + c4;
            const uint32_t so = (uint32_t)(r * IST + c4) * 4;
            cp_async16(b1 + so, Wq1 + go);
            cp_async16(b0 + so, Wq0 + go);
        }
        cp_commit();
    };

    auto compute_stage = [&](int b) {
        const uint32_t* A1 = smu + b * I_BUFW;
        const uint32_t* A0 = A1 + I_TF;
        const uint32_t* B1 = A0 + I_TF;
        const uint32_t* B0 = B1 + I_TF;
#pragma unroll
        for (int k32 = 0; k32 < 2; k32++) {
            const int kb = k32 * 8;
            uint32_t a1[4][4], a0[4][4], b1[4][2], b0[4][2];
#pragma unroll
            for (int mt = 0; mt < 4; mt++) {
                const int ro = (wm0 + mt * 16 + g) * IST + kb;
                a1[mt][0] = A1[ro + t];
                a1[mt][1] = A1[ro + 8 * IST + t];
                a1[mt][2] = A1[ro + t + 4];
                a1[mt][3] = A1[ro + 8 * IST + t + 4];
                a0[mt][0] = A0[ro + t];
                a0[mt][1] = A0[ro + 8 * IST + t];
                a0[mt][2] = A0[ro + t + 4];
                a0[mt][3] = A0[ro + 8 * IST + t + 4];
            }
#pragma unroll
            for (int nt = 0; nt < 4; nt++) {
                const int no = (wn0 + nt * 8 + g) * IST + kb;
                b1[nt][0] = B1[no + t]; b1[nt][1] = B1[no + t + 4];
                b0[nt][0] = B0[no + t]; b0[nt][1] = B0[no + t + 4];
            }
#pragma unroll
            for (int mt = 0; mt < 4; mt++)
#pragma unroll
                for (int nt = 0; nt < 4; nt++)
                    MMA_S8(acc_hi[mt][nt], a1[mt], b1[nt]);
#pragma unroll
            for (int mt = 0; mt < 4; mt++)
#pragma unroll
                for (int nt = 0; nt < 4; nt++)
                    MMA_S8(acc_mid[mt][nt], a1[mt], b0[nt]);
#pragma unroll
            for (int mt = 0; mt < 4; mt++)
#pragma unroll
                for (int nt = 0; nt < 4; nt++)
                    MMA_S8(acc_mid[mt][nt], a0[mt], b1[nt]);
        }
    };

    load_stage(0, 0);
    constexpr int NS = D_ / 64;
    for (int s = 0; s < NS; s++) {
        const int b = s & 1;
        if (s + 1 < NS) {
            load_stage(s + 1, b ^ 1);
            cp_wait<1>();
        } else {
            cp_wait<0>();
        }
        __syncthreads();
        compute_stage(b);
        __syncthreads();
    }

#pragma unroll
    for (int mt = 0; mt < 4; mt++) {
#pragma unroll
        for (int half = 0; half < 2; half++) {
            const int m = m0 + wm0 + mt * 16 + g + half * 8;
            const int bb = m >> 11, l = m & (L_ - 1);
            const float sx = sxa[m];
#pragma unroll
            for (int nt = 0; nt < 4; nt++) {
                const int n = n0 + wn0 + nt * 8 + t * 2;
                const int e = half * 2;
                float2 v;
                v.x = ((float)acc_hi[mt][nt][e] * 4096.f
                     + (float)acc_mid[mt][nt][e] * 64.f) * (sx * swq[n]) + bias[n];
                v.y = ((float)acc_hi[mt][nt][e + 1] * 4096.f
                     + (float)acc_mid[mt][nt][e + 1] * 64.f) * (sx * swq[n + 1]) + bias[n + 1];

                const int sidx = n0 >> 10;
                const int h = (n >> 6) & (H_ - 1), dd = n & (HD_ - 1);
                const size_t row = (size_t)(bb * H_ + h) * L_ + l;
                const size_t woff = row * 32 + (dd >> 1);
                if (sidx == 0) {
                    uint32_t hw, lw;
                    bf16x2_split(v.x, v.y, hw, lw);
                    qh[woff] = hw; ql[woff] = lw;
                } else if (sidx == 1) {
                    uint32_t hw, lw;
                    bf16x2_split(v.x, v.y, hw, lw);
                    kh[woff] = hw; kl[woff] = lw;
                    *reinterpret_cast<float2*>(kraw + row * HD_ + dd) = v;
                } else {
                    *reinterpret_cast<float2*>(vraw + row * HD_ + dd) = v;
                    const float vxn = __shfl_down_sync(0xffffffffu, v.x, 4);
                    const float vyn = __shfl_down_sync(0xffffffffu, v.y, 4);
                    if ((g & 1) == 0) {
                        const size_t vb = (size_t)(bb * H_ + h) * HD_ * (L_ / 2);
                        const size_t l2 = (size_t)(l >> 1);
                        uint32_t hw, lw;
                        bf16x2_split(v.x, vxn, hw, lw);
                        vth[vb + (size_t)dd * (L_ / 2) + l2] = hw;
                        vtl[vb + (size_t)dd * (L_ / 2) + l2] = lw;
                        bf16x2_split(v.y, vyn, hw, lw);
                        vth[vb + (size_t)(dd + 1) * (L_ / 2) + l2] = hw;
                        vtl[vb + (size_t)(dd + 1) * (L_ / 2) + l2] = lw;
                    }
                }
            }
        }
    }
}

// ===========================================================================
// bf16x3 out-proj GEMM (R13, validated)
// ===========================================================================
#define GST 20
#define G_TF (128 * GST)
#define G_BUFW (4 * G_TF)
#define GEMM_SMEM (2 * G_BUFW * 4)

__global__ __launch_bounds__(256, 2)
void gemm_out(const uint32_t* __restrict__ Ahi, const uint32_t* __restrict__ Alo,
              const uint32_t* __restrict__ Whi, const uint32_t* __restrict__ Wlo,
              const float* __restrict__ bias, float* __restrict__ outF)
{
    extern __shared__ uint32_t smu[];
    const uint32_t sb = smem_u32(smu);

    const int tid  = threadIdx.x;
    const int lane = tid & 31;
    const int wid  = tid >> 5;
    const int g = lane >> 2;
    const int t = lane & 3;
    const int wm0 = (wid >> 2) * 64;
    const int wn0 = (wid & 3) * 32;
    const int m0 = blockIdx.y * 128;
    const int n0 = blockIdx.x * 128;

    const uint32_t laneA = (uint32_t)(((lane & 15) * GST + (lane >> 4) * 4) * 4);
    const uint32_t laneB = (uint32_t)((((lane & 7) + (lane >> 4) * 8) * GST
                                      + ((lane >> 3) & 1) * 4) * 4);

    float acc[4][4][4];
#pragma unroll
    for (int mt = 0; mt < 4; mt++)
#pragma unroll
        for (int nt = 0; nt < 4; nt++)
#pragma unroll
            for (int r = 0; r < 4; r++) acc[mt][nt][r] = 0.f;

    auto load_stage = [&](int s, int b) {
        const int kw0 = s * 16;
        const uint32_t aH = sb + (uint32_t)(b * G_BUFW) * 4;
        const uint32_t aL = aH + G_TF * 4;
        const uint32_t bH = aL + G_TF * 4;
        const uint32_t bL = bH + G_TF * 4;
#pragma unroll
        for (int i = 0; i < 2; i++) {
            const int idx = tid + i * 256;
            const int r = idx >> 2, c4 = (idx & 3) * 4;
            const size_t go = (size_t)(m0 + r) * PKW + kw0 + c4;
            const uint32_t so = (uint32_t)(r * GST + c4) * 4;
            cp_async16(aH + so, Ahi + go);
            cp_async16(aL + so, Alo + go);
        }
#pragma unroll
        for (int i = 0; i < 2; i++) {
            const int idx = tid + i * 256;
            const int r = idx >> 2, c4 = (idx & 3) * 4;
            const size_t go = (size_t)(n0 + r) * PKW + kw0 + c4;
            const uint32_t so = (uint32_t)(r * GST + c4) * 4;
            cp_async16(bH + so, Whi + go);
            cp_async16(bL + so, Wlo + go);
        }
        cp_commit();
    };

    auto compute_stage = [&](int b) {
        const uint32_t aH = sb + (uint32_t)(b * G_BUFW) * 4;
        const uint32_t aL = aH + G_TF * 4;
        const uint32_t bHa = aL + G_TF * 4;
        const uint32_t bLa = bHa + G_TF * 4;
#pragma unroll
        for (int k16 = 0; k16 < 2; k16++) {
            const uint32_t kboff = (uint32_t)(k16 * 32);
            uint32_t ah[4][4], al[4][4], bh[4][2], bl[4][2];
#pragma unroll
            for (int mt = 0; mt < 4; mt++) {
                const uint32_t base = (uint32_t)((wm0 + mt * 16) * GST * 4) + kboff + laneA;
                LDSM_X4(ah[mt][0], ah[mt][1], ah[mt][2], ah[mt][3], aH + base);
                LDSM_X4(al[mt][0], al[mt][1], al[mt][2], al[mt][3], aL + base);
            }
#pragma unroll
            for (int nt2 = 0; nt2 < 2; nt2++) {
                const uint32_t base = (uint32_t)((wn0 + nt2 * 16) * GST * 4) + kboff + laneB;
                LDSM_X4(bh[2 * nt2][0], bh[2 * nt2][1],
                        bh[2 * nt2 + 1][0], bh[2 * nt2 + 1][1], bHa + base);
                LDSM_X4(bl[2 * nt2][0], bl[2 * nt2][1],
                        bl[2 * nt2 + 1][0], bl[2 * nt2 + 1][1], bLa + base);
            }
#pragma unroll
            for (int mt = 0; mt < 4; mt++)
#pragma unroll
                for (int nt = 0; nt < 4; nt++)
                    MMA_BF16(acc[mt][nt], al[mt], bh[nt]);
#pragma unroll
            for (int mt = 0; mt < 4; mt++)
#pragma unroll
                for (int nt = 0; nt < 4; nt++)
                    MMA_BF16(acc[mt][nt], ah[mt], bl[nt]);
#pragma unroll
            for (int mt = 0; mt < 4; mt++)
#pragma unroll
                for (int nt = 0; nt < 4; nt++)
                    MMA_BF16(acc[mt][nt], ah[mt], bh[nt]);
        }
    };

    load_stage(0, 0);
    constexpr int NS = D_ / 32;
    for (int s = 0; s < NS; s++) {
        const int b = s & 1;
        if (s + 1 < NS) {
            load_stage(s + 1, b ^ 1);
            cp_wait<1>();
        } else {
            cp_wait<0>();
        }
        __syncthreads();
        compute_stage(b);
        __syncthreads();
    }

#pragma unroll
    for (int mt = 0; mt < 4; mt++) {
#pragma unroll
        for (int half = 0; half < 2; half++) {
            const int m = m0 + wm0 + mt * 16 + g + half * 8;
#pragma unroll
            for (int nt = 0; nt < 4; nt++) {
                const int n = n0 + wn0 + nt * 8 + t * 2;
                float2 v;
                v.x = acc[mt][nt][half * 2 + 0] + bias[n];
                v.y = acc[mt][nt][half * 2 + 1] + bias[n + 1];
                *reinterpret_cast<float2*>(outF + (size_t)m * D_ + n) = v;
            }
        }
    }
}

// ===========================================================================
// Flash attention (causal), bf16x3 m16n8k16, ldmatrix (R13, validated)
// ===========================================================================
#define ATST 36
#define AQ_WORDS (128 * ATST)
#define ABUF0 (2 * AQ_WORDS)
#define AKV_TILE (64 * ATST)
#define ABUFW (4 * AKV_TILE)
#define ATTN_WORDS (ABUF0 + 2 * ABUFW)
#define ATTN_SMEM (ATTN_WORDS * 4)

__global__ __launch_bounds__(256, 2)
void attn_bf16(const uint32_t* __restrict__ qh_g, const uint32_t* __restrict__ ql_g,
               const uint32_t* __restrict__ kh_g, const uint32_t* __restrict__ kl_g,
               const uint32_t* __restrict__ vth_g, const uint32_t* __restrict__ vtl_g,
               uint32_t* __restrict__ ah_g, uint32_t* __restrict__ al_g)
{
    extern __shared__ uint32_t smu[];
    const uint32_t sb = smem_u32(smu);

    const int tidx = (int)gridDim.x - 1 - (int)blockIdx.x;
    const int bh   = blockIdx.y;
    const int row0 = tidx * 128;
    const uint32_t* qhp = qh_g + (size_t)bh * L_ * 32;
    const uint32_t* qlp = ql_g + (size_t)bh * L_ * 32;
    const uint32_t* khp = kh_g + (size_t)bh * L_ * 32;
    const uint32_t* klp = kl_g + (size_t)bh * L_ * 32;
    const uint32_t* vhp = vth_g + (size_t)bh * HD_ * (L_ / 2);
    const uint32_t* vlp = vtl_g + (size_t)bh * HD_ * (L_ / 2);

    const int tid = threadIdx.x;
    const int wid = tid >> 5;
    const int lane = tid & 31;
    const int g = lane >> 2;
    const int t = lane & 3;
    const int wrow = wid * 16;

    const uint32_t laneA = (uint32_t)(((lane & 15) * ATST + (lane >> 4) * 4) * 4);
    const uint32_t laneB = (uint32_t)((((lane & 7) + (lane >> 4) * 8) * ATST
                                      + ((lane >> 3) & 1) * 4) * 4);

    auto load_kv = [&](int c0, int b) {
        const uint32_t kH = sb + (uint32_t)(ABUF0 + b * ABUFW) * 4;
        const uint32_t kL = kH + AKV_TILE * 4;
        const uint32_t vH = kL + AKV_TILE * 4;
        const uint32_t vL = vH + AKV_TILE * 4;
#pragma unroll
        for (int i = 0; i < 2; i++) {
            const int idx = tid + i * 256;
            const int r = idx >> 3, c4 = (idx & 7) * 4;
            const uint32_t so = (uint32_t)(r * ATST + c4) * 4;
            cp_async16(kH + so, khp + (size_t)(c0 + r) * 32 + c4);
            cp_async16(kL + so, klp + (size_t)(c0 + r) * 32 + c4);
        }
#pragma unroll
        for (int i = 0; i < 2; i++) {
            const int idx = tid + i * 256;
            const int r = idx >> 3, c4 = (idx & 7) * 4;
            const uint32_t so = (uint32_t)(r * ATST + c4) * 4;
            cp_async16(vH + so, vhp + (size_t)r * (L_ / 2) + c0 / 2 + c4);
            cp_async16(vL + so, vlp + (size_t)r * (L_ / 2) + c0 / 2 + c4);
        }
        cp_commit();
    };
    load_kv(0, 0);

    uint32_t* Qh = smu;
    uint32_t* Ql = smu + AQ_WORDS;
#pragma unroll
    for (int i = 0; i < 2; i++) {
        const int idx = tid + i * 256;
        const int r = idx >> 2, c4 = (idx & 3) * 8;
        *reinterpret_cast<uint4*>(&Qh[r * ATST + c4]) =
            *reinterpret_cast<const uint4*>(qhp + (size_t)(row0 + r) * 32 + c4);
        *reinterpret_cast<uint4*>(&Qh[r * ATST + c4 + 4]) =
            *reinterpret_cast<const uint4*>(qhp + (size_t)(row0 + r) * 32 + c4 + 4);
        *reinterpret_cast<uint4*>(&Ql[r * ATST + c4]) =
            *reinterpret_cast<const uint4*>(qlp + (size_t)(row0 + r) * 32 + c4);
        *reinterpret_cast<uint4*>(&Ql[r * ATST + c4 + 4]) =
            *reinterpret_cast<const uint4*>(qlp + (size_t)(row0 + r) * 32 + c4 + 4);
    }
    const uint32_t QhA = sb;
    const uint32_t QlA = sb + AQ_WORDS * 4;

    float accO[8][4];
    float m_i[2] = { -1e30f, -1e30f };
    float l_i[2] = { 0.f, 0.f };
#pragma unroll
    for (int nt = 0; nt < 8; nt++)
#pragma unroll
        for (int e = 0; e < 4; e++) accO[nt][e] = 0.f;

    const int jmax = 2 * tidx + 1;
    for (int j0 = 0; j0 <= jmax; j0++) {
        const int c0 = j0 * 64;
        const int b = j0 & 1;

        cp_wait<0>();
        __syncthreads();

        if (j0 < jmax) load_kv(c0 + 64, b ^ 1);

        const uint32_t KH = sb + (uint32_t)(ABUF0 + b * ABUFW) * 4;
        const uint32_t KL = KH + AKV_TILE * 4;
        const uint32_t VH = KL + AKV_TILE * 4;
        const uint32_t VL = VH + AKV_TILE * 4;

        float s[8][4];
#pragma unroll
        for (int nt = 0; nt < 8; nt++)
#pragma unroll
            for (int e = 0; e < 4; e++) s[nt][e] = 0.f;

#pragma unroll
        for (int k16 = 0; k16 < 4; k16++) {
            const uint32_t kboff = (uint32_t)(k16 * 32);
            uint32_t ah[4], al[4], bh2[8][2], bl2[8][2];
            const uint32_t qbase = (uint32_t)(wrow * ATST * 4) + kboff + laneA;
            LDSM_X4(ah[0], ah[1], ah[2], ah[3], QhA + qbase);
            LDSM_X4(al[0], al[1], al[2], al[3], QlA + qbase);
#pragma unroll
            for (int nt2 = 0; nt2 < 4; nt2++) {
                const uint32_t base = (uint32_t)(nt2 * 16 * ATST * 4) + kboff + laneB;
                LDSM_X4(bh2[2 * nt2][0], bh2[2 * nt2][1],
                        bh2[2 * nt2 + 1][0], bh2[2 * nt2 + 1][1], KH + base);
                LDSM_X4(bl2[2 * nt2][0], bl2[2 * nt2][1],
                        bl2[2 * nt2 + 1][0], bl2[2 * nt2 + 1][1], KL + base);
            }
#pragma unroll
            for (int nt = 0; nt < 8; nt++) MMA_BF16(s[nt], al, bh2[nt]);
#pragma unroll
            for (int nt = 0; nt < 8; nt++) MMA_BF16(s[nt], ah, bl2[nt]);
#pragma unroll
            for (int nt = 0; nt < 8; nt++) MMA_BF16(s[nt], ah, bh2[nt]);
        }

        const bool dm = (c0 + 63 > row0);
        const int r0 = row0 + wrow + g;
        const int r1 = r0 + 8;
#pragma unroll
        for (int nt = 0; nt < 8; nt++) {
#pragma unroll
            for (int e = 0; e < 4; e++) {
                const int col = c0 + nt * 8 + 2 * t + (e & 1);
                const int row = (e < 2) ? r0 : r1;
                s[nt][e] *= SCALE_;
                if (dm && col > row) s[nt][e] = -1e30f;
            }
        }

        float mx0 = -1e30f, mx1 = -1e30f;
#pragma unroll
        for (int nt = 0; nt < 8; nt++) {
            mx0 = fmaxf(mx0, fmaxf(s[nt][0], s[nt][1]));
            mx1 = fmaxf(mx1, fmaxf(s[nt][2], s[nt][3]));
        }
#pragma unroll
        for (int off = 1; off <= 2; off <<= 1) {
            mx0 = fmaxf(mx0, __shfl_xor_sync(0xffffffffu, mx0, off));
            mx1 = fmaxf(mx1, __shfl_xor_sync(0xffffffffu, mx1, off));
        }
        const float mn0 = fmaxf(m_i[0], mx0);
        const float mn1 = fmaxf(m_i[1], mx1);
        const float corr0 = __expf(m_i[0] - mn0);
        const float corr1 = __expf(m_i[1] - mn1);
        m_i[0] = mn0; m_i[1] = mn1;

        float ls0 = 0.f, ls1 = 0.f;
#pragma unroll
        for (int nt = 0; nt < 8; nt++) {
            s[nt][0] = __expf(s[nt][0] - mn0);
            s[nt][1] = __expf(s[nt][1] - mn0);
            s[nt][2] = __expf(s[nt][2] - mn1);
            s[nt][3] = __expf(s[nt][3] - mn1);
            ls0 += s[nt][0] + s[nt][1];
            ls1 += s[nt][2] + s[nt][3];
        }
#pragma unroll
        for (int off = 1; off <= 2; off <<= 1) {
            ls0 += __shfl_xor_sync(0xffffffffu, ls0, off);
            ls1 += __shfl_xor_sync(0xffffffffu, ls1, off);
        }
        l_i[0] = l_i[0] * corr0 + ls0;
        l_i[1] = l_i[1] * corr1 + ls1;
#pragma unroll
        for (int nt = 0; nt < 8; nt++) {
            accO[nt][0] *= corr0; accO[nt][1] *= corr0;
            accO[nt][2] *= corr1; accO[nt][3] *= corr1;
        }

        uint32_t phw[8][2], plw[8][2];
#pragma unroll
        for (int nt = 0; nt < 8; nt++) {
            bf16x2_split(s[nt][0], s[nt][1], phw[nt][0], plw[nt][0]);
            bf16x2_split(s[nt][2], s[nt][3], phw[nt][1], plw[nt][1]);
        }

#pragma unroll
        for (int ks = 0; ks < 4; ks++) {
            const uint32_t kboff = (uint32_t)(ks * 32);
            uint32_t pah[4] = { phw[2 * ks][0], phw[2 * ks][1],
                                phw[2 * ks + 1][0], phw[2 * ks + 1][1] };
            uint32_t pal[4] = { plw[2 * ks][0], plw[2 * ks][1],
                                plw[2 * ks + 1][0], plw[2 * ks + 1][1] };
            uint32_t vh[8][2], vl[8][2];
#pragma unroll
            for (int nt2 = 0; nt2 < 4; nt2++) {
                const uint32_t base = (uint32_t)(nt2 * 16 * ATST * 4) + kboff + laneB;
                LDSM_X4(vh[2 * nt2][0], vh[2 * nt2][1],
                        vh[2 * nt2 + 1][0], vh[2 * nt2 + 1][1], VH + base);
                LDSM_X4(vl[2 * nt2][0], vl[2 * nt2][1],
                        vl[2 * nt2 + 1][0], vl[2 * nt2 + 1][1], VL + base);
            }
#pragma unroll
            for (int nt = 0; nt < 8; nt++) MMA_BF16(accO[nt], pal, vh[nt]);
#pragma unroll
            for (int nt = 0; nt < 8; nt++) MMA_BF16(accO[nt], pah, vl[nt]);
#pragma unroll
            for (int nt = 0; nt < 8; nt++) MMA_BF16(accO[nt], pah, vh[nt]);
        }
    }

    const int bb = bh >> 4;
    const int h  = bh & (H_ - 1);
    const float inv0 = 1.0f / l_i[0];
    const float inv1 = 1.0f / l_i[1];
    const int r0 = row0 + wrow + g;
#pragma unroll
    for (int nt = 0; nt < 8; nt++) {
        const int widx = h * 32 + nt * 4 + t;
        uint32_t hw, lw;
        bf16x2_split(accO[nt][0] * inv0, accO[nt][1] * inv0, hw, lw);
        ah_g[((size_t)(bb * L_ + r0)) * 512 + widx] = hw;
        al_g[((size_t)(bb * L_ + r0)) * 512 + widx] = lw;
        bf16x2_split(accO[nt][2] * inv1, accO[nt][3] * inv1, hw, lw);
        ah_g[((size_t)(bb * L_ + r0 + 8)) * 512 + widx] = hw;
        al_g[((size_t)(bb * L_ + r0 + 8)) * 512 + widx] = lw;
    }
}

// ---------------------------------------------------------------------------
extern "C" void kernel_launch(void* const* d_in, const int* in_sizes, int n_in,
                              void* d_out, int out_size)
{
    const float* x     = (const float*)d_in[0];
    const float* w_qkv = (const float*)d_in[1];
    const float* b_qkv = (const float*)d_in[2];
    const float* w_out = (const float*)d_in[3];
    const float* b_out = (const float*)d_in[4];

    float* out  = (float*)d_out;
    float* kout = out  + (size_t)B_ * L_ * D_;
    float* vout = kout + NQKV;

    uint32_t *xq1, *xq0, *wq1, *wq0, *woh, *wol;
    uint32_t *qh, *ql, *kh, *kl, *vth, *vtl, *ah, *al;
    float *sxa, *swq;
    cudaGetSymbolAddress((void**)&xq1, g_xq1);
    cudaGetSymbolAddress((void**)&xq0, g_xq0);
    cudaGetSymbolAddress((void**)&wq1, g_wq1);
    cudaGetSymbolAddress((void**)&wq0, g_wq0);
    cudaGetSymbolAddress((void**)&sxa, g_sxa);
    cudaGetSymbolAddress((void**)&swq, g_swq);
    cudaGetSymbolAddress((void**)&woh, g_woh);
    cudaGetSymbolAddress((void**)&wol, g_wol);
    cudaGetSymbolAddress((void**)&qh, g_qh);
    cudaGetSymbolAddress((void**)&ql, g_ql);
    cudaGetSymbolAddress((void**)&kh, g_kh);
    cudaGetSymbolAddress((void**)&kl, g_kl);
    cudaGetSymbolAddress((void**)&vth, g_vth);
    cudaGetSymbolAddress((void**)&vtl, g_vtl);
    cudaGetSymbolAddress((void**)&ah, g_ah);
    cudaGetSymbolAddress((void**)&al, g_al);

    cudaFuncSetAttribute(gemm_i8_qkv,
                         cudaFuncAttributeMaxDynamicSharedMemorySize, IGEMM_SMEM);
    cudaFuncSetAttribute(gemm_out,
                         cudaFuncAttributeMaxDynamicSharedMemorySize, GEMM_SMEM);
    cudaFuncSetAttribute(attn_bf16,
                         cudaFuncAttributeMaxDynamicSharedMemorySize, ATTN_SMEM);

    // 0) Prep: 2 merged launches
    prep1<<<CMB + WOB, 256>>>(w_qkv, w_out, swq, woh, wol);
    prep2<<<XQB + WQB, 256>>>(x, w_qkv, swq, xq1, xq0, sxa, wq1, wq0);

    // 1) QKV projection (int8 limb IMMA)
    gemm_i8_qkv<<<dim3(24, 32), 256, IGEMM_SMEM>>>(
        xq1, xq0, wq1, wq0, sxa, swq, b_qkv,
        qh, ql, kh, kl, vth, vtl, kout, vout);

    // 2) Causal flash attention (bf16x3)
    attn_bf16<<<dim3(L_ / 128, B_ * H_), 256, ATTN_SMEM>>>(
        qh, ql, kh, kl, vth, vtl, ah, al);

    // 3) Output projection (bf16x3)
    gemm_out<<<dim3(8, 32), 256, GEMM_SMEM>>>(ah, al, woh, wol, b_out, out);
}